// round 7
// baseline (speedup 1.0000x reference)
#include <cuda_runtime.h>
#include <math.h>

#define B_  16
#define T_  32
#define S_  128
#define F_  3
#define H_  256
#define NH_ 8
#define DK_ 32
#define TP_ 4
#define R_  2048      // rows per model GEMM (B*S)
#define NB  256       // persistent blocks (must all be co-resident: 256 <= 148*2)

// ---------------- device scratch (no allocations allowed) ----------------
__device__ float g_eh[2][R_*H_];
__device__ float g_ec[R_*H_];
__device__ float g_dh[2][R_*H_];
__device__ float g_qkv[2*R_*768];       // enc rows [0,2048), dec rows [2048,4096)
__device__ float g_ctx_e[R_*H_];
__device__ float g_ctx_d[R_*H_];
__device__ float g_code[R_*H_];
__device__ float g_We[H_*768];
__device__ float g_Wd[H_*768];
__device__ float g_Wge[(F_+2*H_)*4*H_];
__device__ float g_Wgd[(3*H_)*4*H_];
__device__ float g_bge[4*H_];
__device__ float g_bgd[4*H_];

__device__ unsigned g_bar_count;
__device__ unsigned g_bar_epoch;

__device__ __forceinline__ float sigmoidf_(float x) { return 1.0f / (1.0f + __expf(-x)); }

__device__ __forceinline__ float warp_sum(float v) {
    v += __shfl_xor_sync(0xffffffffu, v, 16);
    v += __shfl_xor_sync(0xffffffffu, v, 8);
    v += __shfl_xor_sync(0xffffffffu, v, 4);
    v += __shfl_xor_sync(0xffffffffu, v, 2);
    v += __shfl_xor_sync(0xffffffffu, v, 1);
    return v;
}

// ---------------- grid barrier (sense-reversing, replay-safe) ----------------
__device__ __forceinline__ void gsync() {
    __syncthreads();
    if (threadIdx.x == 0) {
        unsigned e;
        asm volatile("ld.acquire.gpu.u32 %0, [%1];" : "=r"(e) : "l"(&g_bar_epoch) : "memory");
        __threadfence();
        unsigned old = atomicAdd(&g_bar_count, 1u);
        if (old == NB - 1) {
            atomicExch(&g_bar_count, 0u);
            __threadfence();
            atomicAdd(&g_bar_epoch, 1u);
        } else {
            unsigned cur;
            do {
                __nanosleep(32);
                asm volatile("ld.acquire.gpu.u32 %0, [%1];" : "=r"(cur) : "l"(&g_bar_epoch) : "memory");
            } while (cur == e);
        }
    }
    __syncthreads();
}

// ---------------- segmented A loader ----------------
// AMODE 0: plain A0, ld=K
// AMODE 1: enc gates [x(3)|eh|ctx_e], K=515
// AMODE 2: dec gates [code|dh|ctx_d], K=768
// AMODE 3: qkv both: rows<2048 -> A1 (eh), else A2 (dh); K=256
template<int AMODE>
__device__ __forceinline__ float loadA(const float* __restrict__ A0,
                                       const float* __restrict__ A1,
                                       const float* __restrict__ A2,
                                       int gm, int gk, int K, int t) {
    if (AMODE == 0) {
        return (gk < K) ? A0[(size_t)gm * K + gk] : 0.0f;
    } else if (AMODE == 1) {
        if (gk >= F_ + 2 * H_) return 0.0f;
        if (gk < F_) {
            int b = gm >> 7, s = gm & (S_ - 1);
            return A0[(((size_t)b * T_ + t) * S_ + s) * F_ + gk];
        }
        if (gk < F_ + H_) return A1[(size_t)gm * H_ + (gk - F_)];
        return A2[(size_t)gm * H_ + (gk - F_ - H_)];
    } else if (AMODE == 2) {
        if (gk < H_)     return A0[(size_t)gm * H_ + gk];
        if (gk < 2 * H_) return A1[(size_t)gm * H_ + (gk - H_)];
        return A2[(size_t)gm * H_ + (gk - 2 * H_)];
    } else {
        const float* p = (gm < R_) ? A1 : A2;
        return p[(size_t)(gm & (R_ - 1)) * H_ + gk];
    }
}

__device__ __forceinline__ void mma_tf32(float* d, const unsigned* a, const unsigned* b) {
    asm volatile(
        "mma.sync.aligned.m16n8k8.row.col.f32.tf32.tf32.f32 "
        "{%0,%1,%2,%3}, {%4,%5,%6,%7}, {%8,%9}, {%0,%1,%2,%3};\n"
        : "+f"(d[0]), "+f"(d[1]), "+f"(d[2]), "+f"(d[3])
        : "r"(a[0]), "r"(a[1]), "r"(a[2]), "r"(a[3]), "r"(b[0]), "r"(b[1]));
}

// ---------------- tile-looped TF32 GEMM phase ----------------
// BM=128 BN=64 BK=16, 8 warps (4x2), warp tile 32x32 via m16n8k8 (2x4).
// EPI 0: raw  EPI 1: sigmoid(+bias)  EPI 2: fused LSTM (permuted gates)
template<int AMODE, int EPI>
__device__ __forceinline__ void gemm_phase(
    float As[2][128][20], float Bs[2][16][72],
    const float* __restrict__ A0, const float* __restrict__ A1,
    const float* __restrict__ A2, const float* __restrict__ Bm,
    const float* __restrict__ Bm2,   // alt B for AMODE 3 (dec rows)
    const float* __restrict__ bias, float* __restrict__ C,
    const float* __restrict__ c_in, float* __restrict__ c_out,
    int Mtiles, int Ntiles, int N, int K, int t)
{
    const int tid = threadIdx.x, lane = tid & 31, warp = tid >> 5;
    const int wm = warp >> 1, wn = warp & 1;
    const int q = lane & 3, rsel = lane >> 2;
    const int tot = Mtiles * Ntiles;

    for (int tile = blockIdx.x; tile < tot; tile += NB) {
        const int bm = (tile % Mtiles) * 128;
        const int bn = (tile / Mtiles) * 64;
        const float* Bt = (AMODE == 3 && bm >= R_) ? Bm2 : Bm;

        float acc[2][4][4];
#pragma unroll
        for (int i = 0; i < 2; i++)
#pragma unroll
            for (int j = 0; j < 4; j++)
#pragma unroll
                for (int l = 0; l < 4; l++) acc[i][j][l] = 0.0f;

        const int ntiles = (K + 15) >> 4;
        float ra[8], rb[4];

#pragma unroll
        for (int i = 0; i < 8; i++) {
            int idx = tid + i * 256; int m = idx >> 4, k = idx & 15;
            ra[i] = loadA<AMODE>(A0, A1, A2, bm + m, k, K, t);
        }
#pragma unroll
        for (int i = 0; i < 4; i++) {
            int idx = tid + i * 256; int k = idx >> 6, n = idx & 63;
            rb[i] = (k < K) ? Bt[(size_t)k * N + bn + n] : 0.0f;
        }
#pragma unroll
        for (int i = 0; i < 8; i++) { int idx = tid + i * 256; As[0][idx >> 4][idx & 15] = ra[i]; }
#pragma unroll
        for (int i = 0; i < 4; i++) { int idx = tid + i * 256; Bs[0][idx >> 6][idx & 63] = rb[i]; }
        __syncthreads();

        int buf = 0;
        for (int kt = 0; kt < ntiles; kt++) {
            const int k0n = (kt + 1) << 4;
            const bool more = (kt + 1) < ntiles;
            if (more) {
#pragma unroll
                for (int i = 0; i < 8; i++) {
                    int idx = tid + i * 256; int m = idx >> 4, k = idx & 15;
                    ra[i] = loadA<AMODE>(A0, A1, A2, bm + m, k0n + k, K, t);
                }
#pragma unroll
                for (int i = 0; i < 4; i++) {
                    int idx = tid + i * 256; int k = idx >> 6, n = idx & 63;
                    rb[i] = (k0n + k < K) ? Bt[(size_t)(k0n + k) * N + bn + n] : 0.0f;
                }
            }
#pragma unroll
            for (int kk = 0; kk < 16; kk += 8) {
                unsigned a[2][4], b[4][2];
#pragma unroll
                for (int tm = 0; tm < 2; tm++) {
                    int row = wm * 32 + tm * 16 + rsel;
                    a[tm][0] = __float_as_uint(As[buf][row][kk + q]);
                    a[tm][1] = __float_as_uint(As[buf][row + 8][kk + q]);
                    a[tm][2] = __float_as_uint(As[buf][row][kk + q + 4]);
                    a[tm][3] = __float_as_uint(As[buf][row + 8][kk + q + 4]);
                }
#pragma unroll
                for (int tn = 0; tn < 4; tn++) {
                    int col = wn * 32 + tn * 8 + rsel;
                    b[tn][0] = __float_as_uint(Bs[buf][kk + q][col]);
                    b[tn][1] = __float_as_uint(Bs[buf][kk + q + 4][col]);
                }
#pragma unroll
                for (int tm = 0; tm < 2; tm++)
#pragma unroll
                    for (int tn = 0; tn < 4; tn++) mma_tf32(acc[tm][tn], a[tm], b[tn]);
            }
            if (more) {
#pragma unroll
                for (int i = 0; i < 8; i++) { int idx = tid + i * 256; As[buf ^ 1][idx >> 4][idx & 15] = ra[i]; }
#pragma unroll
                for (int i = 0; i < 4; i++) { int idx = tid + i * 256; Bs[buf ^ 1][idx >> 6][idx & 63] = rb[i]; }
            }
            __syncthreads();
            buf ^= 1;
        }

        if (EPI == 0) {
#pragma unroll
            for (int tm = 0; tm < 2; tm++)
#pragma unroll
                for (int tn = 0; tn < 4; tn++) {
                    int r0 = bm + wm * 32 + tm * 16 + rsel;
                    int col = bn + wn * 32 + tn * 8 + 2 * q;
                    C[(size_t)r0 * N + col]           = acc[tm][tn][0];
                    C[(size_t)r0 * N + col + 1]       = acc[tm][tn][1];
                    C[(size_t)(r0 + 8) * N + col]     = acc[tm][tn][2];
                    C[(size_t)(r0 + 8) * N + col + 1] = acc[tm][tn][3];
                }
        } else if (EPI == 1) {
#pragma unroll
            for (int tm = 0; tm < 2; tm++)
#pragma unroll
                for (int tn = 0; tn < 4; tn++) {
                    int r0 = bm + wm * 32 + tm * 16 + rsel;
                    int col = bn + wn * 32 + tn * 8 + 2 * q;
                    float b0 = bias[col], b1 = bias[col + 1];
                    C[(size_t)r0 * N + col]           = sigmoidf_(acc[tm][tn][0] + b0);
                    C[(size_t)r0 * N + col + 1]       = sigmoidf_(acc[tm][tn][1] + b1);
                    C[(size_t)(r0 + 8) * N + col]     = sigmoidf_(acc[tm][tn][2] + b0);
                    C[(size_t)(r0 + 8) * N + col + 1] = sigmoidf_(acc[tm][tn][3] + b1);
                }
        } else {
            // permuted gates: col = 4*h + gate, order [i,f,g,o]; even-q lanes (i,f),
            // odd-q partner lane^1 holds (g,o).
#pragma unroll
            for (int tm = 0; tm < 2; tm++)
#pragma unroll
                for (int tn = 0; tn < 4; tn++) {
                    int col = bn + wn * 32 + tn * 8 + 2 * q;
                    float b0 = bias[col], b1 = bias[col + 1];
#pragma unroll
                    for (int half = 0; half < 2; half++) {
                        int r = bm + wm * 32 + tm * 16 + rsel + half * 8;
                        float v0 = acc[tm][tn][half * 2 + 0] + b0;
                        float v1 = acc[tm][tn][half * 2 + 1] + b1;
                        float p0 = __shfl_xor_sync(0xffffffffu, v0, 1);
                        float p1 = __shfl_xor_sync(0xffffffffu, v1, 1);
                        if (!(q & 1)) {
                            int h = col >> 2;
                            float cn = sigmoidf_(v1) * c_in[(size_t)r * H_ + h]
                                     + sigmoidf_(v0) * tanhf(p0);
                            float hn = sigmoidf_(p1) * tanhf(cn);
                            C[(size_t)r * H_ + h] = hn;
                            if (c_out) c_out[(size_t)r * H_ + h] = cn;
                        }
                    }
                }
        }
    }
}

// ---------------- attention phase (enc + dec halves of g_qkv) ----------------
__device__ __forceinline__ void attn_phase() {
    const int w0 = blockIdx.x * 8 + (threadIdx.x >> 5);
    const int lane = threadIdx.x & 31;
    const float scale = 0.17677669529663687f;   // 1/sqrt(32)
    for (int p = w0; p < 2 * R_ * NH_; p += NB * 8) {
        int r = p >> 3;
        int head = p & (NH_ - 1);
        int s = r & (S_ - 1);
        const float* qkv = g_qkv;
        float qv = qkv[(size_t)r * 768 + head * DK_ + lane];
        const int offs[4] = {2, 1, -1, -2};
        float sc[4];
#pragma unroll
        for (int n = 0; n < 4; n++) {
            int sn = s + offs[n];
            float d = 0.0f;
            if (sn >= 0 && sn < S_) {
                int rn = r + offs[n];
                d = qv * qkv[(size_t)rn * 768 + 256 + head * DK_ + lane];
            }
            sc[n] = warp_sum(d) * scale;
        }
        float mx = fmaxf(fmaxf(sc[0], sc[1]), fmaxf(sc[2], sc[3]));
        float e[4], sum = 0.0f;
#pragma unroll
        for (int n = 0; n < 4; n++) { e[n] = __expf(sc[n] - mx); sum += e[n]; }
        float inv = 1.0f / sum;
        float accv = 0.0f;
#pragma unroll
        for (int n = 0; n < 4; n++) {
            int sn = s + offs[n];
            if (sn >= 0 && sn < S_) {
                int rn = r + offs[n];
                accv = fmaf(e[n] * inv, qkv[(size_t)rn * 768 + 512 + head * DK_ + lane], accv);
            }
        }
        float* ctx = (r < R_) ? g_ctx_e : g_ctx_d;
        ctx[(size_t)(r & (R_ - 1)) * H_ + head * DK_ + lane] = accv;
    }
}

// ---------------- output GEMV + assembly (one warp per row) ----------------
__device__ __forceinline__ void out_phase(const float* __restrict__ dh,
                                          const float* __restrict__ W,
                                          const float* __restrict__ bb,
                                          const float* __restrict__ input,
                                          float* __restrict__ dout, int t) {
    const int w = blockIdx.x * 8 + (threadIdx.x >> 5);   // 0..2047 exactly
    const int lane = threadIdx.x & 31;
    int r = w, b = r >> 7, s = r & (S_ - 1);
    float s0 = 0.0f, s1 = 0.0f;
#pragma unroll
    for (int j = 0; j < H_; j += 32) {
        float wv = W[j + lane];
        s0 = fmaf(dh[(size_t)r * H_ + j + lane], wv, s0);
        if (s > 0) s1 = fmaf(dh[(size_t)(r - 1) * H_ + j + lane], wv, s1);
    }
    s0 = warp_sum(s0);
    s1 = warp_sum(s1);
    if (lane == 0) {
        float o  = s0 + bb[0];
        float In = (s > 0) ? (s1 + bb[0])
                           : input[(((size_t)b * T_ + (t + 1)) * S_ + 0) * F_ + 1];
        float num = input[(((size_t)b * T_ + t) * S_ + s) * F_ + 2] + In - o;
        size_t base = (((size_t)b * (T_ - TP_ - 1) + (t - TP_)) * S_ + s) * 3;
        dout[base + 0] = o;
        dout[base + 1] = In;
        dout[base + 2] = num;
    }
}

// ---------------- the persistent kernel ----------------
__global__ __launch_bounds__(256, 2)
void persist_kernel(const float* __restrict__ input,
                    const float* __restrict__ embW, const float* __restrict__ embb,
                    const float* __restrict__ outW, const float* __restrict__ outb,
                    float* __restrict__ dout)
{
    __shared__ float As[2][128][20];
    __shared__ float Bs[2][16][72];

    int ce = 0, cd = 0;
    for (int t = 0; t < T_ - 1; t++) {
        // A: batched enc+dec QKV (M=4096, N=768, K=256)
        gemm_phase<3, 0>(As, Bs, nullptr, g_eh[ce], g_dh[cd], g_We, g_Wd,
                         nullptr, g_qkv, nullptr, nullptr, 32, 12, 768, H_, 0);
        gsync();
        // B: attention (both)
        attn_phase();
        gsync();
        // C: enc gates + LSTM -> eh[ce^1], ec
        gemm_phase<1, 2>(As, Bs, input, g_eh[ce], g_ctx_e, g_Wge, nullptr,
                         g_bge, g_eh[ce ^ 1], g_ec, g_ec, 16, 16, 4 * H_, F_ + 2 * H_, t);
        gsync();
        // D: emb -> code; also output GEMV for step t-1 (underloaded phase)
        gemm_phase<0, 1>(As, Bs, g_eh[ce ^ 1], nullptr, nullptr, embW, nullptr,
                         embb, g_code, nullptr, nullptr, 16, 4, H_, H_, 0);
        if (t - 1 >= TP_) out_phase(g_dh[cd], outW, outb, input, dout, t - 1);
        gsync();
        // E: dec gates + LSTM -> dh[cd^1] (c_in = old dh, c discarded)
        gemm_phase<2, 2>(As, Bs, g_code, g_dh[cd], g_ctx_d, g_Wgd, nullptr,
                         g_bgd, g_dh[cd ^ 1], g_dh[cd], nullptr, 16, 16, 4 * H_, 3 * H_, 0);
        gsync();
        ce ^= 1; cd ^= 1;
    }
    // final output for t = T-2 = 30 (dh already synced by last phase-E gsync)
    out_phase(g_dh[cd], outW, outb, input, dout, T_ - 2);
}

// ---------------- prep kernels ----------------
__global__ void zero_state_kernel() {
    int i = blockIdx.x * blockDim.x + threadIdx.x;
    if (i < R_ * H_) { g_eh[0][i] = 0.0f; g_ec[i] = 0.0f; g_dh[0][i] = 0.0f; }
}

__global__ void concat_w_kernel(const float* __restrict__ Wq, const float* __restrict__ Wk,
                                const float* __restrict__ Wv, float* __restrict__ Wc) {
    int idx = blockIdx.x * blockDim.x + threadIdx.x;
    if (idx >= H_ * 3 * H_) return;
    int k = idx / (3 * H_);
    int n = idx - k * (3 * H_);
    const float* src = (n < H_) ? Wq : ((n < 2 * H_) ? Wk : Wv);
    Wc[idx] = src[k * H_ + (n & (H_ - 1))];
}

__global__ void permute_wg_kernel(const float* __restrict__ W, const float* __restrict__ b,
                                  float* __restrict__ pW, float* __restrict__ pb, int K) {
    int idx = blockIdx.x * blockDim.x + threadIdx.x;
    if (idx >= K * 4 * H_) return;
    int k = idx >> 10;
    int n = idx & (4 * H_ - 1);
    int h = n >> 2, g = n & 3;
    pW[idx] = W[(size_t)k * 4 * H_ + g * H_ + h];
    if (idx < 4 * H_) pb[idx] = b[g * H_ + h];
}

// ---------------- host side ----------------
extern "C" void kernel_launch(void* const* d_in, const int* in_sizes, int n_in,
                              void* d_out, int out_size) {
    const float* input = (const float*)d_in[0];
    const float* eWq = (const float*)d_in[1];
    const float* eWk = (const float*)d_in[2];
    const float* eWv = (const float*)d_in[3];
    const float* eWg = (const float*)d_in[4];
    const float* ebg = (const float*)d_in[5];
    const float* dWq = (const float*)d_in[6];
    const float* dWk = (const float*)d_in[7];
    const float* dWv = (const float*)d_in[8];
    const float* dWg = (const float*)d_in[9];
    const float* dbg = (const float*)d_in[10];
    const float* embW = (const float*)d_in[11];
    const float* embb = (const float*)d_in[12];
    const float* outW = (const float*)d_in[13];
    const float* outb = (const float*)d_in[14];
    float* dout = (float*)d_out;

    float *p_We, *p_Wd, *p_Wge, *p_Wgd, *p_bge, *p_bgd;
    cudaGetSymbolAddress((void**)&p_We,  g_We);
    cudaGetSymbolAddress((void**)&p_Wd,  g_Wd);
    cudaGetSymbolAddress((void**)&p_Wge, g_Wge);
    cudaGetSymbolAddress((void**)&p_Wgd, g_Wgd);
    cudaGetSymbolAddress((void**)&p_bge, g_bge);
    cudaGetSymbolAddress((void**)&p_bgd, g_bgd);

    const int KE = F_ + 2 * H_;
    const int KD = 3 * H_;

    zero_state_kernel<<<(R_ * H_ + 255) / 256, 256>>>();
    concat_w_kernel<<<(H_ * 3 * H_ + 255) / 256, 256>>>(eWq, eWk, eWv, p_We);
    concat_w_kernel<<<(H_ * 3 * H_ + 255) / 256, 256>>>(dWq, dWk, dWv, p_Wd);
    permute_wg_kernel<<<(KE * 4 * H_ + 255) / 256, 256>>>(eWg, ebg, p_Wge, p_bge, KE);
    permute_wg_kernel<<<(KD * 4 * H_ + 255) / 256, 256>>>(dWg, dbg, p_Wgd, p_bgd, KD);

    persist_kernel<<<NB, 256>>>(input, embW, embb, outW, outb, dout);
}

// round 9
// speedup vs baseline: 1.4552x; 1.4552x over previous
#include <cuda_runtime.h>
#include <cuda_fp16.h>
#include <cstdint>
#include <math.h>

#define B_  16
#define T_  32
#define S_  128
#define F_  3
#define H_  256
#define NH_ 8
#define DK_ 32
#define TP_ 4
#define R_  2048
#define NB  192        // persistent blocks; 2 CTA/SM co-resident (192 <= 296)

// ---------------- device scratch ----------------
__device__ __half g_eh[2][R_*H_];
__device__ float  g_ec[R_*H_];
__device__ __half g_dh[2][R_*H_];
__device__ __half g_qkv[2*R_*768];     // enc rows [0,2048), dec [2048,4096)
__device__ __half g_ctx_e[R_*H_];
__device__ __half g_ctx_d[R_*H_];
__device__ __half g_code[R_*H_];
__device__ __half g_We_t[768*256];     // [n][k]
__device__ __half g_Wd_t[768*256];
__device__ __half g_Wge_t[1024*512];   // enc gates rows 3..514, cols permuted 4h+g
__device__ __half g_Wgd_t[1024*768];
__device__ __half g_embT[256*256];
__device__ float  g_Wx[3*1024];        // enc gate x-rows (fp32), permuted cols
__device__ float  g_bge[1024];
__device__ float  g_bgd[1024];
__device__ unsigned g_bar_count;
__device__ unsigned g_bar_epoch;

// ---------------- smem layout ----------------
// stage: As 128 rows x 20 half2 (80B) = 10240B, Bs same -> 20480B/stage, 4 stages
#define STAGE_B   20480
#define BIAS_OFF  (4*STAGE_B)              // 81920, 512B (128 floats)
#define WX_OFF    (BIAS_OFF + 512)         // 1536B (384 floats)
#define SMEM_SZ   (WX_OFF + 1536)          // 83968

__device__ __forceinline__ uint32_t s2u(const void* p) {
    uint32_t a;
    asm("{ .reg .u64 t; cvta.to.shared.u64 t, %1; cvt.u32.u64 %0, t; }" : "=r"(a) : "l"(p));
    return a;
}
__device__ __forceinline__ uint32_t lds32(uint32_t a) {
    uint32_t v;
    asm volatile("ld.shared.b32 %0, [%1];" : "=r"(v) : "r"(a));
    return v;
}
#define CPA(dst, src) asm volatile("cp.async.cg.shared.global [%0], [%1], 16;" :: "r"(dst), "l"(src) : "memory")
#define CP_COMMIT()   asm volatile("cp.async.commit_group;" ::: "memory")
#define CP_WAIT2()    asm volatile("cp.async.wait_group 2;" ::: "memory")

__device__ __forceinline__ float sigmoidf_(float x) { return 1.0f / (1.0f + __expf(-x)); }
__device__ __forceinline__ float warp_sum(float v) {
    v += __shfl_xor_sync(0xffffffffu, v, 16);
    v += __shfl_xor_sync(0xffffffffu, v, 8);
    v += __shfl_xor_sync(0xffffffffu, v, 4);
    v += __shfl_xor_sync(0xffffffffu, v, 2);
    v += __shfl_xor_sync(0xffffffffu, v, 1);
    return v;
}

__device__ __forceinline__ void mma_f16(float* d, const uint32_t* a, const uint32_t* b) {
    asm volatile(
        "mma.sync.aligned.m16n8k16.row.col.f32.f16.f16.f32 "
        "{%0,%1,%2,%3}, {%4,%5,%6,%7}, {%8,%9}, {%0,%1,%2,%3};\n"
        : "+f"(d[0]), "+f"(d[1]), "+f"(d[2]), "+f"(d[3])
        : "r"(a[0]), "r"(a[1]), "r"(a[2]), "r"(a[3]), "r"(b[0]), "r"(b[1]));
}

// ---------------- grid barrier ----------------
__device__ __forceinline__ void gsync() {
    __syncthreads();
    if (threadIdx.x == 0) {
        unsigned e;
        asm volatile("ld.acquire.gpu.u32 %0, [%1];" : "=r"(e) : "l"(&g_bar_epoch) : "memory");
        __threadfence();
        unsigned old = atomicAdd(&g_bar_count, 1u);
        if (old == NB - 1) {
            atomicExch(&g_bar_count, 0u);
            __threadfence();
            atomicAdd(&g_bar_epoch, 1u);
        } else {
            unsigned cur;
            do {
                __nanosleep(32);
                asm volatile("ld.acquire.gpu.u32 %0, [%1];" : "=r"(cur) : "l"(&g_bar_epoch) : "memory");
            } while (cur == e);
        }
    }
    __syncthreads();
}

// ---------------- stage loader (cp.async) ----------------
// AM 0: A0 plain [row][256]. AM 1: enc gates [eh|ctx] K=512.
// AM 2: dec gates [code|dh|ctx] K=768. AM 3: qkv dual (row<2048 -> A1 else A2) K=256.
template<int AM>
__device__ __forceinline__ void load_stage(uint32_t sb,
    const __half* __restrict__ A0, const __half* __restrict__ A1, const __half* __restrict__ A2,
    const __half* __restrict__ Bt, int bm, int bn, int KB, int kt, int slot)
{
    const int tid = threadIdx.x;
    uint32_t Ab = sb + (uint32_t)slot * STAGE_B;
    uint32_t Bb = Ab + 10240;
    const int gk0 = kt * 32;
#pragma unroll
    for (int i = 0; i < 2; i++) {
        int idx = tid + i * 256;
        int m = idx >> 2, c4 = idx & 3;
        int gk = gk0 + c4 * 8;
        int rowm = bm + m;
        const __half* ap;
        if (AM == 0)      ap = A0 + (size_t)rowm * 256 + gk;
        else if (AM == 1) ap = (gk < 256) ? (A1 + (size_t)rowm * 256 + gk)
                                          : (A2 + (size_t)rowm * 256 + gk - 256);
        else if (AM == 2) ap = (gk < 256) ? (A0 + (size_t)rowm * 256 + gk)
                        : ((gk < 512) ? (A1 + (size_t)rowm * 256 + gk - 256)
                                      : (A2 + (size_t)rowm * 256 + gk - 512));
        else { const __half* p = (rowm < R_) ? A1 : A2;
               ap = p + (size_t)(rowm & (R_ - 1)) * 256 + gk; }
        CPA(Ab + (uint32_t)(m * 80 + c4 * 16), ap);
        CPA(Bb + (uint32_t)(m * 80 + c4 * 16), Bt + (size_t)(bn + m) * KB + gk);
    }
}

// ---------------- fp16 tensor-core GEMM phase ----------------
// BM=128 BN=128 BK=32, 8 warps as 2(m)x4(n), warp tile 64x32 (4x4 m16n8k16).
// EPI 0: raw half  EPI 1: sigmoid(acc+bias) half  EPI 2: fused LSTM (h half, c float)
template<int AM, int EPI, bool XUPD, bool CIH>
__device__ void gemm_tc(char* smp, uint32_t sb,
    const __half* __restrict__ A0, const __half* __restrict__ A1, const __half* __restrict__ A2,
    const __half* __restrict__ B0, const __half* __restrict__ B1,
    const float* __restrict__ bias, __half* __restrict__ C,
    const void* __restrict__ c_in, float* __restrict__ c_out,
    int Mtiles, int Ntiles, int NOUT, int KB, int nkt, int t,
    const float* __restrict__ input)
{
    const int tid = threadIdx.x, lane = tid & 31, warp = tid >> 5;
    const int wm = warp >> 2, wn = warp & 3;          // 2 x 4
    const int q = lane & 3, rsel = lane >> 2;
    const int tot = Mtiles * Ntiles;
    float* bias_s = (float*)(smp + BIAS_OFF);
    float* wx_s   = (float*)(smp + WX_OFF);

    for (int tile = blockIdx.x; tile < tot; tile += NB) {
        const int bm = (tile % Mtiles) * 128;
        const int bn = (tile / Mtiles) * 128;
        const __half* Bt = (AM == 3 && bm >= R_) ? B1 : B0;

        __syncthreads();   // prior tile fully done before overwriting smem
        if (EPI >= 1) for (int i = tid; i < 128; i += 256) bias_s[i] = bias[bn + i];
        if (XUPD)     for (int i = tid; i < 384; i += 256) wx_s[i] = g_Wx[(i >> 7) * 1024 + bn + (i & 127)];

        float acc[4][4][4];
#pragma unroll
        for (int a = 0; a < 4; a++)
#pragma unroll
            for (int b = 0; b < 4; b++)
#pragma unroll
                for (int l = 0; l < 4; l++) acc[a][b][l] = 0.0f;

        // prologue: 3 stages
#pragma unroll
        for (int s = 0; s < 3; s++) {
            if (s < nkt) load_stage<AM>(sb, A0, A1, A2, Bt, bm, bn, KB, s, s);
            CP_COMMIT();
        }

        for (int kt = 0; kt < nkt; kt++) {
            CP_WAIT2();
            __syncthreads();
            if (kt + 3 < nkt) load_stage<AM>(sb, A0, A1, A2, Bt, bm, bn, KB, kt + 3, (kt + 3) & 3);
            CP_COMMIT();

            uint32_t Ab = sb + (uint32_t)(kt & 3) * STAGE_B;
            uint32_t Bb = Ab + 10240;
#pragma unroll
            for (int st = 0; st < 2; st++) {        // two k16 steps per BK=32
                const int kb = st * 8;
                uint32_t af[4][4], bf[4][2];
#pragma unroll
                for (int tm = 0; tm < 4; tm++) {
                    uint32_t r0 = Ab + (uint32_t)((wm * 64 + tm * 16 + rsel) * 80);
                    af[tm][0] = lds32(r0 + (kb + q) * 4);
                    af[tm][1] = lds32(r0 + 640 + (kb + q) * 4);          // +8 rows
                    af[tm][2] = lds32(r0 + (kb + q + 4) * 4);
                    af[tm][3] = lds32(r0 + 640 + (kb + q + 4) * 4);
                }
#pragma unroll
                for (int tn = 0; tn < 4; tn++) {
                    uint32_t c0 = Bb + (uint32_t)((wn * 32 + tn * 8 + rsel) * 80);
                    bf[tn][0] = lds32(c0 + (kb + q) * 4);
                    bf[tn][1] = lds32(c0 + (kb + q + 4) * 4);
                }
#pragma unroll
                for (int tm = 0; tm < 4; tm++)
#pragma unroll
                    for (int tn = 0; tn < 4; tn++) mma_f16(acc[tm][tn], af[tm], bf[tn]);
            }
        }
        asm volatile("cp.async.wait_group 0;" ::: "memory");

        // ---------------- epilogue ----------------
#pragma unroll
        for (int tm = 0; tm < 4; tm++)
#pragma unroll
            for (int tn = 0; tn < 4; tn++) {
                const int r0  = bm + wm * 64 + tm * 16 + rsel;
                const int cl  = wn * 32 + tn * 8 + 2 * q;     // local col (even)
                const int col = bn + cl;
                if (EPI == 0) {
                    __half2 h01, h23;
                    h01.x = __float2half(acc[tm][tn][0]); h01.y = __float2half(acc[tm][tn][1]);
                    h23.x = __float2half(acc[tm][tn][2]); h23.y = __float2half(acc[tm][tn][3]);
                    *(__half2*)(C + (size_t)r0 * NOUT + col)       = h01;
                    *(__half2*)(C + (size_t)(r0 + 8) * NOUT + col) = h23;
                } else if (EPI == 1) {
                    float b0 = bias_s[cl], b1 = bias_s[cl + 1];
                    __half2 h01, h23;
                    h01.x = __float2half(sigmoidf_(acc[tm][tn][0] + b0));
                    h01.y = __float2half(sigmoidf_(acc[tm][tn][1] + b1));
                    h23.x = __float2half(sigmoidf_(acc[tm][tn][2] + b0));
                    h23.y = __float2half(sigmoidf_(acc[tm][tn][3] + b1));
                    *(__half2*)(C + (size_t)r0 * NOUT + col)       = h01;
                    *(__half2*)(C + (size_t)(r0 + 8) * NOUT + col) = h23;
                } else {
                    // permuted gates: col = 4h+g, order [i,f,g,o]; even-q lane holds (i,f),
                    // partner lane^1 holds (g,o).
                    float b0 = bias_s[cl], b1 = bias_s[cl + 1];
#pragma unroll
                    for (int half = 0; half < 2; half++) {
                        const int r = r0 + half * 8;
                        float v0 = acc[tm][tn][half * 2 + 0] + b0;
                        float v1 = acc[tm][tn][half * 2 + 1] + b1;
                        if (XUPD) {
                            int bb = r >> 7, s = r & (S_ - 1);
                            const float* xp = input + (((size_t)bb * T_ + t) * S_ + s) * F_;
                            float x0 = xp[0], x1 = xp[1], x2 = xp[2];
                            v0 += x0 * wx_s[cl]     + x1 * wx_s[128 + cl]     + x2 * wx_s[256 + cl];
                            v1 += x0 * wx_s[cl + 1] + x1 * wx_s[128 + cl + 1] + x2 * wx_s[256 + cl + 1];
                        }
                        float p0 = __shfl_xor_sync(0xffffffffu, v0, 1);
                        float p1 = __shfl_xor_sync(0xffffffffu, v1, 1);
                        if (!(q & 1)) {
                            int h = (bn + cl) >> 2;
                            float cprev = CIH ? __half2float(((const __half*)c_in)[(size_t)r * H_ + h])
                                              : ((const float*)c_in)[(size_t)r * H_ + h];
                            float cn = sigmoidf_(v1) * cprev + sigmoidf_(v0) * tanhf(p0);
                            float hn = sigmoidf_(p1) * tanhf(cn);
                            C[(size_t)r * H_ + h] = __float2half(hn);
                            if (c_out) c_out[(size_t)r * H_ + h] = cn;
                        }
                    }
                }
            }
    }
}

// ---------------- attention (enc + dec halves) ----------------
__device__ __forceinline__ void attn_phase() {
    const int w0 = blockIdx.x * 8 + (threadIdx.x >> 5);
    const int lane = threadIdx.x & 31;
    const float scale = 0.17677669529663687f;   // 1/sqrt(32)
    for (int p = w0; p < 2 * R_ * NH_; p += NB * 8) {
        int r = p >> 3;
        int head = p & (NH_ - 1);
        int s = r & (S_ - 1);
        float qv = __half2float(g_qkv[(size_t)r * 768 + head * DK_ + lane]);
        const int offs[4] = {2, 1, -1, -2};
        float sc[4];
#pragma unroll
        for (int n = 0; n < 4; n++) {
            int sn = s + offs[n];
            float d = 0.0f;
            if (sn >= 0 && sn < S_) {
                int rn = r + offs[n];
                d = qv * __half2float(g_qkv[(size_t)rn * 768 + 256 + head * DK_ + lane]);
            }
            sc[n] = warp_sum(d) * scale;
        }
        float mx = fmaxf(fmaxf(sc[0], sc[1]), fmaxf(sc[2], sc[3]));
        float e[4], sum = 0.0f;
#pragma unroll
        for (int n = 0; n < 4; n++) { e[n] = __expf(sc[n] - mx); sum += e[n]; }
        float inv = 1.0f / sum;
        float accv = 0.0f;
#pragma unroll
        for (int n = 0; n < 4; n++) {
            int sn = s + offs[n];
            if (sn >= 0 && sn < S_) {
                int rn = r + offs[n];
                accv = fmaf(e[n] * inv,
                            __half2float(g_qkv[(size_t)rn * 768 + 512 + head * DK_ + lane]), accv);
            }
        }
        __half* ctx = (r < R_) ? g_ctx_e : g_ctx_d;
        ctx[(size_t)(r & (R_ - 1)) * H_ + head * DK_ + lane] = __float2half(accv);
    }
}

// ---------------- output GEMV + assembly ----------------
__device__ __forceinline__ void out_phase(const __half* __restrict__ dh,
                                          const float* __restrict__ W,
                                          const float* __restrict__ bb,
                                          const float* __restrict__ input,
                                          float* __restrict__ dout, int t) {
    const int w0 = blockIdx.x * 8 + (threadIdx.x >> 5);
    const int lane = threadIdx.x & 31;
    for (int r = w0; r < R_; r += NB * 8) {
        int b = r >> 7, s = r & (S_ - 1);
        float s0 = 0.0f, s1 = 0.0f;
#pragma unroll
        for (int j = 0; j < H_; j += 32) {
            float wv = W[j + lane];
            s0 = fmaf(__half2float(dh[(size_t)r * H_ + j + lane]), wv, s0);
            if (s > 0) s1 = fmaf(__half2float(dh[(size_t)(r - 1) * H_ + j + lane]), wv, s1);
        }
        s0 = warp_sum(s0);
        s1 = warp_sum(s1);
        if (lane == 0) {
            float o  = s0 + bb[0];
            float In = (s > 0) ? (s1 + bb[0])
                               : input[(((size_t)b * T_ + (t + 1)) * S_ + 0) * F_ + 1];
            float num = input[(((size_t)b * T_ + t) * S_ + s) * F_ + 2] + In - o;
            size_t base = (((size_t)b * (T_ - TP_ - 1) + (t - TP_)) * S_ + s) * 3;
            dout[base + 0] = o;
            dout[base + 1] = In;
            dout[base + 2] = num;
        }
    }
}

// ---------------- persistent kernel ----------------
__global__ __launch_bounds__(256, 2)
void persist_kernel(const float* __restrict__ input, const float* __restrict__ embb,
                    const float* __restrict__ outW, const float* __restrict__ outb,
                    float* __restrict__ dout)
{
    extern __shared__ char smp[];
    uint32_t sb = s2u(smp);

    int ce = 0, cd = 0;
    for (int t = 0; t < T_ - 1; t++) {
        // A: enc+dec QKV (M=4096, N=768, K=256) -> g_qkv
        gemm_tc<3, 0, false, false>(smp, sb, nullptr, g_eh[ce], g_dh[cd],
                                    g_We_t, g_Wd_t, nullptr, g_qkv, nullptr, nullptr,
                                    32, 6, 768, 256, 8, 0, nullptr);
        gsync();
        attn_phase();
        gsync();
        // C: enc gates (K=512 + rank-3 x) + LSTM -> eh[ce^1], ec
        gemm_tc<1, 2, true, false>(smp, sb, nullptr, g_eh[ce], g_ctx_e,
                                   g_Wge_t, nullptr, g_bge, g_eh[ce ^ 1], g_ec, g_ec,
                                   16, 8, 256, 512, 16, t, input);
        gsync();
        // D: emb -> code (sigmoid); + output for step t-1
        gemm_tc<0, 1, false, false>(smp, sb, g_eh[ce ^ 1], nullptr, nullptr,
                                    g_embT, nullptr, embb, g_code, nullptr, nullptr,
                                    16, 2, 256, 256, 8, 0, nullptr);
        if (t - 1 >= TP_) out_phase(g_dh[cd], outW, outb, input, dout, t - 1);
        gsync();
        // E: dec gates (K=768) + LSTM (c_in = old dh, half) -> dh[cd^1]
        gemm_tc<2, 2, false, true>(smp, sb, g_code, g_dh[cd], g_ctx_d,
                                   g_Wgd_t, nullptr, g_bgd, g_dh[cd ^ 1], g_dh[cd], nullptr,
                                   16, 8, 256, 768, 24, 0, nullptr);
        gsync();
        ce ^= 1; cd ^= 1;
    }
    out_phase(g_dh[cd], outW, outb, input, dout, T_ - 2);
}

// ---------------- prep kernels ----------------
__global__ void zero_state_kernel() {
    int i = blockIdx.x * blockDim.x + threadIdx.x;
    if (i < R_ * H_) {
        g_eh[0][i] = __float2half(0.0f);
        g_dh[0][i] = __float2half(0.0f);
        g_ec[i] = 0.0f;
    }
}
__global__ void prep_qkv_kernel(const float* __restrict__ Wq, const float* __restrict__ Wk,
                                const float* __restrict__ Wv, __half* __restrict__ Wt) {
    int idx = blockIdx.x * blockDim.x + threadIdx.x;   // 768*256
    if (idx >= 768 * 256) return;
    int n = idx >> 8, k = idx & 255;
    const float* src = (n < 256) ? Wq : ((n < 512) ? Wk : Wv);
    Wt[(size_t)n * 256 + k] = __float2half(src[(size_t)k * 256 + (n & 255)]);
}
__global__ void prep_genc_kernel(const float* __restrict__ Wg, const float* __restrict__ bg) {
    int idx = blockIdx.x * blockDim.x + threadIdx.x;   // 1024*512
    if (idx >= 1024 * 512) return;
    int n = idx >> 9, k2 = idx & 511;
    int gcol = (n & 3) * 256 + (n >> 2);
    g_Wge_t[(size_t)n * 512 + k2] = __float2half(Wg[(size_t)(3 + k2) * 1024 + gcol]);
    if (k2 < 3) g_Wx[k2 * 1024 + n] = Wg[(size_t)k2 * 1024 + gcol];
    if (k2 == 0) g_bge[n] = bg[gcol];
}
__global__ void prep_gdec_kernel(const float* __restrict__ Wg, const float* __restrict__ bg) {
    int idx = blockIdx.x * blockDim.x + threadIdx.x;   // 1024*768
    if (idx >= 1024 * 768) return;
    int n = idx / 768, k2 = idx - n * 768;
    int gcol = (n & 3) * 256 + (n >> 2);
    g_Wgd_t[(size_t)n * 768 + k2] = __float2half(Wg[(size_t)k2 * 1024 + gcol]);
    if (k2 == 0) g_bgd[n] = bg[gcol];
}
__global__ void prep_emb_kernel(const float* __restrict__ W) {
    int idx = blockIdx.x * blockDim.x + threadIdx.x;   // 256*256
    if (idx >= 256 * 256) return;
    int n = idx >> 8, k = idx & 255;
    g_embT[(size_t)n * 256 + k] = __float2half(W[(size_t)k * 256 + n]);
}

// ---------------- host ----------------
extern "C" void kernel_launch(void* const* d_in, const int* in_sizes, int n_in,
                              void* d_out, int out_size) {
    const float* input = (const float*)d_in[0];
    const float* eWq = (const float*)d_in[1];
    const float* eWk = (const float*)d_in[2];
    const float* eWv = (const float*)d_in[3];
    const float* eWg = (const float*)d_in[4];
    const float* ebg = (const float*)d_in[5];
    const float* dWq = (const float*)d_in[6];
    const float* dWk = (const float*)d_in[7];
    const float* dWv = (const float*)d_in[8];
    const float* dWg = (const float*)d_in[9];
    const float* dbg = (const float*)d_in[10];
    const float* embW = (const float*)d_in[11];
    const float* embb = (const float*)d_in[12];
    const float* outW = (const float*)d_in[13];
    const float* outb = (const float*)d_in[14];
    float* dout = (float*)d_out;

    __half *p_We, *p_Wd;
    cudaGetSymbolAddress((void**)&p_We, g_We_t);
    cudaGetSymbolAddress((void**)&p_Wd, g_Wd_t);

    static int s_init = 0;
    if (!s_init) {
        cudaFuncSetAttribute(persist_kernel, cudaFuncAttributeMaxDynamicSharedMemorySize, SMEM_SZ);
        s_init = 1;
    }

    zero_state_kernel<<<(R_ * H_ + 255) / 256, 256>>>();
    prep_qkv_kernel<<<(768 * 256 + 255) / 256, 256>>>(eWq, eWk, eWv, p_We);
    prep_qkv_kernel<<<(768 * 256 + 255) / 256, 256>>>(dWq, dWk, dWv, p_Wd);
    prep_genc_kernel<<<(1024 * 512 + 255) / 256, 256>>>(eWg, ebg);
    prep_gdec_kernel<<<(1024 * 768 + 255) / 256, 256>>>(dWg, dbg);
    prep_emb_kernel<<<(256 * 256 + 255) / 256, 256>>>(embW);

    persist_kernel<<<NB, 256, SMEM_SZ>>>(input, embb, outW, outb, dout);
}

// round 10
// speedup vs baseline: 1.5297x; 1.0512x over previous
#include <cuda_runtime.h>
#include <cuda_fp16.h>
#include <cstdint>
#include <math.h>

#define B_  16
#define T_  32
#define S_  128
#define F_  3
#define H_  256
#define NH_ 8
#define DK_ 32
#define TP_ 4
#define R_  2048
#define NB  148        // one persistent block per SM

// ---------------- device scratch ----------------
__device__ __half g_eh[2][R_*H_];
__device__ float  g_ec[R_*H_];
__device__ __half g_dh[2][R_*H_];
__device__ __half g_qkv[2*R_*768];     // enc rows [0,2048), dec [2048,4096)
__device__ __half g_ctx_e[R_*H_];
__device__ __half g_ctx_d[R_*H_];
__device__ __half g_code[R_*H_];
__device__ __half g_We_t[768*256];     // [n][k]
__device__ __half g_Wd_t[768*256];
__device__ __half g_Wge_t[1024*512];   // enc gates rows 3..514, cols permuted 4h+g
__device__ __half g_Wgd_t[1024*768];
__device__ __half g_embT[256*256];
__device__ float  g_Wx[3*1024];        // enc gate x-rows (fp32), permuted cols
__device__ float  g_bge[1024];
__device__ float  g_bgd[1024];
__device__ unsigned g_bar_count;
__device__ unsigned g_bar_epoch;

// ---------------- smem layout ----------------
#define STAGE_B   20480
#define BIAS_OFF  (4*STAGE_B)
#define WX_OFF    (BIAS_OFF + 512)
#define SMEM_SZ   (WX_OFF + 1536)          // 83968

__device__ __forceinline__ uint32_t s2u(const void* p) {
    uint32_t a;
    asm("{ .reg .u64 t; cvta.to.shared.u64 t, %1; cvt.u32.u64 %0, t; }" : "=r"(a) : "l"(p));
    return a;
}
__device__ __forceinline__ uint32_t lds32(uint32_t a) {
    uint32_t v;
    asm volatile("ld.shared.b32 %0, [%1];" : "=r"(v) : "r"(a));
    return v;
}
#define CPA(dst, src) asm volatile("cp.async.cg.shared.global [%0], [%1], 16;" :: "r"(dst), "l"(src) : "memory")
#define CP_COMMIT()   asm volatile("cp.async.commit_group;" ::: "memory")
#define CP_WAIT2()    asm volatile("cp.async.wait_group 2;" ::: "memory")

__device__ __forceinline__ float sigmoidf_(float x) { return 1.0f / (1.0f + __expf(-x)); }
__device__ __forceinline__ float warp_sum(float v) {
    v += __shfl_xor_sync(0xffffffffu, v, 16);
    v += __shfl_xor_sync(0xffffffffu, v, 8);
    v += __shfl_xor_sync(0xffffffffu, v, 4);
    v += __shfl_xor_sync(0xffffffffu, v, 2);
    v += __shfl_xor_sync(0xffffffffu, v, 1);
    return v;
}

__device__ __forceinline__ void mma_f16(float* d, const uint32_t* a, const uint32_t* b) {
    asm volatile(
        "mma.sync.aligned.m16n8k16.row.col.f32.f16.f16.f32 "
        "{%0,%1,%2,%3}, {%4,%5,%6,%7}, {%8,%9}, {%0,%1,%2,%3};\n"
        : "+f"(d[0]), "+f"(d[1]), "+f"(d[2]), "+f"(d[3])
        : "r"(a[0]), "r"(a[1]), "r"(a[2]), "r"(a[3]), "r"(b[0]), "r"(b[1]));
}

// ---------------- grid barrier ----------------
__device__ __forceinline__ void gsync() {
    __syncthreads();
    if (threadIdx.x == 0) {
        unsigned e;
        asm volatile("ld.acquire.gpu.u32 %0, [%1];" : "=r"(e) : "l"(&g_bar_epoch) : "memory");
        __threadfence();
        unsigned old = atomicAdd(&g_bar_count, 1u);
        if (old == NB - 1) {
            atomicExch(&g_bar_count, 0u);
            __threadfence();
            atomicAdd(&g_bar_epoch, 1u);
        } else {
            unsigned cur;
            do {
                __nanosleep(32);
                asm volatile("ld.acquire.gpu.u32 %0, [%1];" : "=r"(cur) : "l"(&g_bar_epoch) : "memory");
            } while (cur == e);
        }
    }
    __syncthreads();
}

// ---------------- stage loader (cp.async) ----------------
// AM 0: A0 plain [row][256]. AM 1: enc gates [eh|ctx] K=512.
// AM 2: dec gates [code|dh|ctx] K=768. AM 3: qkv dual (row<2048 -> A1 else A2) K=256.
template<int AM>
__device__ __forceinline__ void load_stage(uint32_t sb,
    const __half* __restrict__ A0, const __half* __restrict__ A1, const __half* __restrict__ A2,
    const __half* __restrict__ Bt, int bm, int bn, int KB, int kt, int slot)
{
    const int tid = threadIdx.x;
    uint32_t Ab = sb + (uint32_t)slot * STAGE_B;
    uint32_t Bb = Ab + 10240;
    const int gk0 = kt * 32;
#pragma unroll
    for (int i = 0; i < 2; i++) {
        int idx = tid + i * 256;
        int m = idx >> 2, c4 = idx & 3;
        int gk = gk0 + c4 * 8;
        int rowm = bm + m;
        const __half* ap;
        if (AM == 0)      ap = A0 + (size_t)rowm * 256 + gk;
        else if (AM == 1) ap = (gk < 256) ? (A1 + (size_t)rowm * 256 + gk)
                                          : (A2 + (size_t)rowm * 256 + gk - 256);
        else if (AM == 2) ap = (gk < 256) ? (A0 + (size_t)rowm * 256 + gk)
                        : ((gk < 512) ? (A1 + (size_t)rowm * 256 + gk - 256)
                                      : (A2 + (size_t)rowm * 256 + gk - 512));
        else { const __half* p = (rowm < R_) ? A1 : A2;
               ap = p + (size_t)(rowm & (R_ - 1)) * 256 + gk; }
        CPA(Ab + (uint32_t)(m * 80 + c4 * 16), ap);
        CPA(Bb + (uint32_t)(m * 80 + c4 * 16), Bt + (size_t)(bn + m) * KB + gk);
    }
}

// ---------------- fp16 tensor-core GEMM phase ----------------
// BM=128 BN=128 BK=32, 8 warps as 2(m)x4(n), warp tile 64x32 (4x4 m16n8k16).
// EPI 0: raw half  EPI 1: sigmoid(acc+bias) half  EPI 2: fused LSTM (h half, c per CIH)
template<int AM, int EPI, bool XUPD, bool CIH>
__device__ void gemm_tc(char* smp, uint32_t sb,
    const __half* __restrict__ A0, const __half* __restrict__ A1, const __half* __restrict__ A2,
    const __half* __restrict__ B0, const __half* __restrict__ B1,
    const float* __restrict__ bias, __half* __restrict__ C,
    const void* __restrict__ c_in, float* __restrict__ c_out,
    int Mtiles, int Ntiles, int NOUT, int KB, int nkt, int t,
    const float* __restrict__ input, int boff)
{
    const int tid = threadIdx.x, lane = tid & 31, warp = tid >> 5;
    const int wm = warp >> 2, wn = warp & 3;          // 2 x 4
    const int q = lane & 3, rsel = lane >> 2;
    const int tot = Mtiles * Ntiles;
    float* bias_s = (float*)(smp + BIAS_OFF);
    float* wx_s   = (float*)(smp + WX_OFF);

    for (int tile = (blockIdx.x + boff) % NB; tile < tot; tile += NB) {
        const int bm = (tile % Mtiles) * 128;
        const int bn = (tile / Mtiles) * 128;
        const __half* Bt = (AM == 3 && bm >= R_) ? B1 : B0;

        __syncthreads();   // prior tile fully done before overwriting smem
        if (EPI >= 1) for (int i = tid; i < 128; i += 256) bias_s[i] = bias[bn + i];
        if (XUPD)     for (int i = tid; i < 384; i += 256) wx_s[i] = g_Wx[(i >> 7) * 1024 + bn + (i & 127)];

        float acc[4][4][4];
#pragma unroll
        for (int a = 0; a < 4; a++)
#pragma unroll
            for (int b = 0; b < 4; b++)
#pragma unroll
                for (int l = 0; l < 4; l++) acc[a][b][l] = 0.0f;

        // prologue: 3 stages
#pragma unroll
        for (int s = 0; s < 3; s++) {
            if (s < nkt) load_stage<AM>(sb, A0, A1, A2, Bt, bm, bn, KB, s, s);
            CP_COMMIT();
        }

        for (int kt = 0; kt < nkt; kt++) {
            CP_WAIT2();
            __syncthreads();
            if (kt + 3 < nkt) load_stage<AM>(sb, A0, A1, A2, Bt, bm, bn, KB, kt + 3, (kt + 3) & 3);
            CP_COMMIT();

            uint32_t Ab = sb + (uint32_t)(kt & 3) * STAGE_B;
            uint32_t Bb = Ab + 10240;
#pragma unroll
            for (int st = 0; st < 2; st++) {        // two k16 steps per BK=32
                const int kb = st * 8;
                uint32_t af[4][4], bf[4][2];
#pragma unroll
                for (int tm = 0; tm < 4; tm++) {
                    uint32_t r0 = Ab + (uint32_t)((wm * 64 + tm * 16 + rsel) * 80);
                    af[tm][0] = lds32(r0 + (kb + q) * 4);
                    af[tm][1] = lds32(r0 + 640 + (kb + q) * 4);          // +8 rows
                    af[tm][2] = lds32(r0 + (kb + q + 4) * 4);
                    af[tm][3] = lds32(r0 + 640 + (kb + q + 4) * 4);
                }
#pragma unroll
                for (int tn = 0; tn < 4; tn++) {
                    uint32_t c0 = Bb + (uint32_t)((wn * 32 + tn * 8 + rsel) * 80);
                    bf[tn][0] = lds32(c0 + (kb + q) * 4);
                    bf[tn][1] = lds32(c0 + (kb + q + 4) * 4);
                }
#pragma unroll
                for (int tm = 0; tm < 4; tm++)
#pragma unroll
                    for (int tn = 0; tn < 4; tn++) mma_f16(acc[tm][tn], af[tm], bf[tn]);
            }
        }
        asm volatile("cp.async.wait_group 0;" ::: "memory");

        // ---------------- epilogue ----------------
#pragma unroll
        for (int tm = 0; tm < 4; tm++)
#pragma unroll
            for (int tn = 0; tn < 4; tn++) {
                const int r0  = bm + wm * 64 + tm * 16 + rsel;
                const int cl  = wn * 32 + tn * 8 + 2 * q;     // local col (even)
                const int col = bn + cl;
                if (EPI == 0) {
                    __half2 h01, h23;
                    h01.x = __float2half(acc[tm][tn][0]); h01.y = __float2half(acc[tm][tn][1]);
                    h23.x = __float2half(acc[tm][tn][2]); h23.y = __float2half(acc[tm][tn][3]);
                    *(__half2*)(C + (size_t)r0 * NOUT + col)       = h01;
                    *(__half2*)(C + (size_t)(r0 + 8) * NOUT + col) = h23;
                } else if (EPI == 1) {
                    float b0 = bias_s[cl], b1 = bias_s[cl + 1];
                    __half2 h01, h23;
                    h01.x = __float2half(sigmoidf_(acc[tm][tn][0] + b0));
                    h01.y = __float2half(sigmoidf_(acc[tm][tn][1] + b1));
                    h23.x = __float2half(sigmoidf_(acc[tm][tn][2] + b0));
                    h23.y = __float2half(sigmoidf_(acc[tm][tn][3] + b1));
                    *(__half2*)(C + (size_t)r0 * NOUT + col)       = h01;
                    *(__half2*)(C + (size_t)(r0 + 8) * NOUT + col) = h23;
                } else {
                    // permuted gates: col = 4h+g, order [i,f,g,o]; even-q lane holds (i,f),
                    // partner lane^1 holds (g,o).
                    float b0 = bias_s[cl], b1 = bias_s[cl + 1];
#pragma unroll
                    for (int half = 0; half < 2; half++) {
                        const int r = r0 + half * 8;
                        float v0 = acc[tm][tn][half * 2 + 0] + b0;
                        float v1 = acc[tm][tn][half * 2 + 1] + b1;
                        if (XUPD) {
                            int bb = r >> 7, s = r & (S_ - 1);
                            const float* xp = input + (((size_t)bb * T_ + t) * S_ + s) * F_;
                            float x0 = xp[0], x1 = xp[1], x2 = xp[2];
                            v0 += x0 * wx_s[cl]     + x1 * wx_s[128 + cl]     + x2 * wx_s[256 + cl];
                            v1 += x0 * wx_s[cl + 1] + x1 * wx_s[128 + cl + 1] + x2 * wx_s[256 + cl + 1];
                        }
                        float p0 = __shfl_xor_sync(0xffffffffu, v0, 1);
                        float p1 = __shfl_xor_sync(0xffffffffu, v1, 1);
                        if (!(q & 1)) {
                            int h = (bn + cl) >> 2;
                            float cprev = CIH ? __half2float(((const __half*)c_in)[(size_t)r * H_ + h])
                                              : ((const float*)c_in)[(size_t)r * H_ + h];
                            float cn = sigmoidf_(v1) * cprev + sigmoidf_(v0) * tanhf(p0);
                            float hn = sigmoidf_(p1) * tanhf(cn);
                            C[(size_t)r * H_ + h] = __float2half(hn);
                            if (c_out) c_out[(size_t)r * H_ + h] = cn;
                        }
                    }
                }
            }
    }
}

// ---------------- attention over [pbase, pbase+pcount) head-rows ----------------
__device__ __forceinline__ void attn_phase(int pbase, int pcount) {
    const int w0 = blockIdx.x * 8 + (threadIdx.x >> 5);
    const int lane = threadIdx.x & 31;
    const float scale = 0.17677669529663687f;   // 1/sqrt(32)
    for (int pi = w0; pi < pcount; pi += NB * 8) {
        int p = pbase + pi;
        int r = p >> 3;
        int head = p & (NH_ - 1);
        int s = r & (S_ - 1);
        float qv = __half2float(g_qkv[(size_t)r * 768 + head * DK_ + lane]);
        const int offs[4] = {2, 1, -1, -2};
        float sc[4];
#pragma unroll
        for (int n = 0; n < 4; n++) {
            int sn = s + offs[n];
            float d = 0.0f;
            if (sn >= 0 && sn < S_) {
                int rn = r + offs[n];
                d = qv * __half2float(g_qkv[(size_t)rn * 768 + 256 + head * DK_ + lane]);
            }
            sc[n] = warp_sum(d) * scale;
        }
        float mx = fmaxf(fmaxf(sc[0], sc[1]), fmaxf(sc[2], sc[3]));
        float e[4], sum = 0.0f;
#pragma unroll
        for (int n = 0; n < 4; n++) { e[n] = __expf(sc[n] - mx); sum += e[n]; }
        float inv = 1.0f / sum;
        float accv = 0.0f;
#pragma unroll
        for (int n = 0; n < 4; n++) {
            int sn = s + offs[n];
            if (sn >= 0 && sn < S_) {
                int rn = r + offs[n];
                accv = fmaf(e[n] * inv,
                            __half2float(g_qkv[(size_t)rn * 768 + 512 + head * DK_ + lane]), accv);
            }
        }
        __half* ctx = (r < R_) ? g_ctx_e : g_ctx_d;
        ctx[(size_t)(r & (R_ - 1)) * H_ + head * DK_ + lane] = __float2half(accv);
    }
}

// ---------------- output GEMV + assembly ----------------
__device__ __forceinline__ void out_phase(const __half* __restrict__ dh,
                                          const float* __restrict__ W,
                                          const float* __restrict__ bb,
                                          const float* __restrict__ input,
                                          float* __restrict__ dout, int t) {
    const int w0 = blockIdx.x * 8 + (threadIdx.x >> 5);
    const int lane = threadIdx.x & 31;
    for (int r = w0; r < R_; r += NB * 8) {
        int b = r >> 7, s = r & (S_ - 1);
        float s0 = 0.0f, s1 = 0.0f;
#pragma unroll
        for (int j = 0; j < H_; j += 32) {
            float wv = W[j + lane];
            s0 = fmaf(__half2float(dh[(size_t)r * H_ + j + lane]), wv, s0);
            if (s > 0) s1 = fmaf(__half2float(dh[(size_t)(r - 1) * H_ + j + lane]), wv, s1);
        }
        s0 = warp_sum(s0);
        s1 = warp_sum(s1);
        if (lane == 0) {
            float o  = s0 + bb[0];
            float In = (s > 0) ? (s1 + bb[0])
                               : input[(((size_t)b * T_ + (t + 1)) * S_ + 0) * F_ + 1];
            float num = input[(((size_t)b * T_ + t) * S_ + s) * F_ + 2] + In - o;
            size_t base = (((size_t)b * (T_ - TP_ - 1) + (t - TP_)) * S_ + s) * 3;
            dout[base + 0] = o;
            dout[base + 1] = In;
            dout[base + 2] = num;
        }
    }
}

// ---------------- persistent kernel ----------------
// Schedule per step t (4 barriers):
//  G1: C(t): enc gates+LSTM  -> eh(t), ec
//  G2: D(t): emb->code; QKV dual {enc from eh(t) [for t+1], dec from dh(t-1) [for t]}; out(t-1)
//  G3: attn: enc ctx(t+1) + dec ctx(t)
//  G4: E(t): dec gates+LSTM -> dh(t)
// Pre-loop: QKV enc(0) + attn enc(0).
__global__ __launch_bounds__(256, 1)
void persist_kernel(const float* __restrict__ input, const float* __restrict__ embb,
                    const float* __restrict__ outW, const float* __restrict__ outb,
                    float* __restrict__ dout)
{
    extern __shared__ char smp[];
    uint32_t sb = s2u(smp);

    int ce = 0, cd = 0;
    // pre-loop: enc QKV(0) from eh[0]=0, then enc attention(0)
    gemm_tc<0, 0, false, false>(smp, sb, g_eh[0], nullptr, nullptr,
                                g_We_t, nullptr, nullptr, g_qkv, nullptr, nullptr,
                                16, 6, 768, 256, 8, 0, nullptr, 0);
    gsync();
    attn_phase(0, R_ * NH_);
    gsync();

    for (int t = 0; t < T_ - 1; t++) {
        // G1: enc gates + LSTM (K=512 + rank-3 x) -> eh[ce^1], ec
        gemm_tc<1, 2, true, false>(smp, sb, nullptr, g_eh[ce], g_ctx_e,
                                   g_Wge_t, nullptr, g_bge, g_eh[ce ^ 1], g_ec, g_ec,
                                   16, 8, 256, 512, 16, t, input, 0);
        gsync();
        // G2: QKV dual (enc<-eh(t), dec<-dh(t-1)); emb->code; out(t-1)
        gemm_tc<3, 0, false, false>(smp, sb, nullptr, g_eh[ce ^ 1], g_dh[cd],
                                    g_We_t, g_Wd_t, nullptr, g_qkv, nullptr, nullptr,
                                    32, 6, 768, 256, 8, 0, nullptr, 0);
        gemm_tc<0, 1, false, false>(smp, sb, g_eh[ce ^ 1], nullptr, nullptr,
                                    g_embT, nullptr, embb, g_code, nullptr, nullptr,
                                    16, 2, 256, 256, 8, 0, nullptr, 44);
        if (t - 1 >= TP_) out_phase(g_dh[cd], outW, outb, input, dout, t - 1);
        gsync();
        // G3: attention (enc ctx for t+1, dec ctx for t)
        attn_phase(0, 2 * R_ * NH_);
        gsync();
        // G4: dec gates + LSTM (K=768, c_in = dh(t-1) half) -> dh[cd^1]
        gemm_tc<2, 2, false, true>(smp, sb, g_code, g_dh[cd], g_ctx_d,
                                   g_Wgd_t, nullptr, g_bgd, g_dh[cd ^ 1], g_dh[cd], nullptr,
                                   16, 8, 256, 768, 24, 0, nullptr, 0);
        gsync();
        ce ^= 1; cd ^= 1;
    }
    out_phase(g_dh[cd], outW, outb, input, dout, T_ - 2);
}

// ---------------- prep kernels ----------------
__global__ void zero_state_kernel() {
    int i = blockIdx.x * blockDim.x + threadIdx.x;
    if (i < R_ * H_) {
        g_eh[0][i] = __float2half(0.0f);
        g_dh[0][i] = __float2half(0.0f);
        g_ec[i] = 0.0f;
    }
}
__global__ void prep_qkv_kernel(const float* __restrict__ Wq, const float* __restrict__ Wk,
                                const float* __restrict__ Wv, __half* __restrict__ Wt) {
    int idx = blockIdx.x * blockDim.x + threadIdx.x;   // 768*256
    if (idx >= 768 * 256) return;
    int n = idx >> 8, k = idx & 255;
    const float* src = (n < 256) ? Wq : ((n < 512) ? Wk : Wv);
    Wt[(size_t)n * 256 + k] = __float2half(src[(size_t)k * 256 + (n & 255)]);
}
__global__ void prep_genc_kernel(const float* __restrict__ Wg, const float* __restrict__ bg) {
    int idx = blockIdx.x * blockDim.x + threadIdx.x;   // 1024*512
    if (idx >= 1024 * 512) return;
    int n = idx >> 9, k2 = idx & 511;
    int gcol = (n & 3) * 256 + (n >> 2);
    g_Wge_t[(size_t)n * 512 + k2] = __float2half(Wg[(size_t)(3 + k2) * 1024 + gcol]);
    if (k2 < 3) g_Wx[k2 * 1024 + n] = Wg[(size_t)k2 * 1024 + gcol];
    if (k2 == 0) g_bge[n] = bg[gcol];
}
__global__ void prep_gdec_kernel(const float* __restrict__ Wg, const float* __restrict__ bg) {
    int idx = blockIdx.x * blockDim.x + threadIdx.x;   // 1024*768
    if (idx >= 1024 * 768) return;
    int n = idx / 768, k2 = idx - n * 768;
    int gcol = (n & 3) * 256 + (n >> 2);
    g_Wgd_t[(size_t)n * 768 + k2] = __float2half(Wg[(size_t)k2 * 1024 + gcol]);
    if (k2 == 0) g_bgd[n] = bg[gcol];
}
__global__ void prep_emb_kernel(const float* __restrict__ W) {
    int idx = blockIdx.x * blockDim.x + threadIdx.x;   // 256*256
    if (idx >= 256 * 256) return;
    int n = idx >> 8, k = idx & 255;
    g_embT[(size_t)n * 256 + k] = __float2half(W[(size_t)k * 256 + n]);
}

// ---------------- host ----------------
extern "C" void kernel_launch(void* const* d_in, const int* in_sizes, int n_in,
                              void* d_out, int out_size) {
    const float* input = (const float*)d_in[0];
    const float* eWq = (const float*)d_in[1];
    const float* eWk = (const float*)d_in[2];
    const float* eWv = (const float*)d_in[3];
    const float* eWg = (const float*)d_in[4];
    const float* ebg = (const float*)d_in[5];
    const float* dWq = (const float*)d_in[6];
    const float* dWk = (const float*)d_in[7];
    const float* dWv = (const float*)d_in[8];
    const float* dWg = (const float*)d_in[9];
    const float* dbg = (const float*)d_in[10];
    const float* embW = (const float*)d_in[11];
    const float* embb = (const float*)d_in[12];
    const float* outW = (const float*)d_in[13];
    const float* outb = (const float*)d_in[14];
    float* dout = (float*)d_out;

    __half *p_We, *p_Wd;
    cudaGetSymbolAddress((void**)&p_We, g_We_t);
    cudaGetSymbolAddress((void**)&p_Wd, g_Wd_t);

    static int s_init = 0;
    if (!s_init) {
        cudaFuncSetAttribute(persist_kernel, cudaFuncAttributeMaxDynamicSharedMemorySize, SMEM_SZ);
        s_init = 1;
    }

    zero_state_kernel<<<(R_ * H_ + 255) / 256, 256>>>();
    prep_qkv_kernel<<<(768 * 256 + 255) / 256, 256>>>(eWq, eWk, eWv, p_We);
    prep_qkv_kernel<<<(768 * 256 + 255) / 256, 256>>>(dWq, dWk, dWv, p_Wd);
    prep_genc_kernel<<<(1024 * 512 + 255) / 256, 256>>>(eWg, ebg);
    prep_gdec_kernel<<<(1024 * 768 + 255) / 256, 256>>>(dWg, dbg);
    prep_emb_kernel<<<(256 * 256 + 255) / 256, 256>>>(embW);

    persist_kernel<<<NB, 256, SMEM_SZ>>>(input, embb, outW, outb, dout);
}

// round 11
// speedup vs baseline: 1.5349x; 1.0034x over previous
#include <cuda_runtime.h>
#include <cuda_fp16.h>
#include <cstdint>
#include <math.h>

#define B_  16
#define T_  32
#define S_  128
#define F_  3
#define H_  256
#define NH_ 8
#define DK_ 32
#define TP_ 4
#define R_  2048
#define NB  148        // one persistent block per SM

// ---------------- device scratch ----------------
__device__ __half g_eh[2][R_*H_];
__device__ float  g_ec[R_*H_];
__device__ __half g_dh[2][R_*H_];
__device__ __half g_qkv[2*R_*768];     // enc rows [0,2048), dec [2048,4096)
__device__ __half g_ctx_e[R_*H_];
__device__ __half g_ctx_d[R_*H_];
__device__ __half g_code[R_*H_];
__device__ __half g_We_t[768*256];     // [n][k]
__device__ __half g_Wd_t[768*256];
__device__ __half g_Wge_t[1024*512];   // enc gates rows 3..514, cols permuted 4h+g
__device__ __half g_Wgd_t[1024*768];
__device__ __half g_embT[256*256];
__device__ float  g_Wx[3*1024];        // enc gate x-rows (fp32), permuted cols
__device__ float  g_bge[1024];
__device__ float  g_bgd[1024];
__device__ unsigned g_bar_count;
__device__ unsigned g_bar_epoch;

// ---------------- smem layout ----------------
#define STAGE_B   20480
#define BIAS_OFF  (4*STAGE_B)
#define WX_OFF    (BIAS_OFF + 512)
#define SMEM_SZ   (WX_OFF + 1536)          // 83968

__device__ __forceinline__ uint32_t s2u(const void* p) {
    uint32_t a;
    asm("{ .reg .u64 t; cvta.to.shared.u64 t, %1; cvt.u32.u64 %0, t; }" : "=r"(a) : "l"(p));
    return a;
}
#define CPA(dst, src) asm volatile("cp.async.cg.shared.global [%0], [%1], 16;" :: "r"(dst), "l"(src) : "memory")
#define CP_COMMIT()   asm volatile("cp.async.commit_group;" ::: "memory")
#define CP_WAIT2()    asm volatile("cp.async.wait_group 2;" ::: "memory")
#define LDSM4(r0, r1, r2, r3, a) \
    asm volatile("ldmatrix.sync.aligned.m8n8.x4.shared.b16 {%0,%1,%2,%3}, [%4];" \
        : "=r"(r0), "=r"(r1), "=r"(r2), "=r"(r3) : "r"(a))

__device__ __forceinline__ float sigmoidf_(float x) { return 1.0f / (1.0f + __expf(-x)); }
__device__ __forceinline__ float warp_sum(float v) {
    v += __shfl_xor_sync(0xffffffffu, v, 16);
    v += __shfl_xor_sync(0xffffffffu, v, 8);
    v += __shfl_xor_sync(0xffffffffu, v, 4);
    v += __shfl_xor_sync(0xffffffffu, v, 2);
    v += __shfl_xor_sync(0xffffffffu, v, 1);
    return v;
}

__device__ __forceinline__ void mma_f16(float* d, const uint32_t* a, const uint32_t* b) {
    asm volatile(
        "mma.sync.aligned.m16n8k16.row.col.f32.f16.f16.f32 "
        "{%0,%1,%2,%3}, {%4,%5,%6,%7}, {%8,%9}, {%0,%1,%2,%3};\n"
        : "+f"(d[0]), "+f"(d[1]), "+f"(d[2]), "+f"(d[3])
        : "r"(a[0]), "r"(a[1]), "r"(a[2]), "r"(a[3]), "r"(b[0]), "r"(b[1]));
}

// ---------------- grid barrier (acq_rel arrivals, release publish) ----------------
__device__ __forceinline__ void gsync() {
    __syncthreads();
    if (threadIdx.x == 0) {
        unsigned e;
        asm volatile("ld.acquire.gpu.u32 %0, [%1];" : "=r"(e) : "l"(&g_bar_epoch) : "memory");
        unsigned old;
        asm volatile("atom.add.acq_rel.gpu.u32 %0, [%1], %2;"
                     : "=r"(old) : "l"(&g_bar_count), "r"(1u) : "memory");
        if (old == NB - 1) {
            g_bar_count = 0;   // ordered before the release-add below
            unsigned dummy;
            asm volatile("atom.add.release.gpu.u32 %0, [%1], %2;"
                         : "=r"(dummy) : "l"(&g_bar_epoch), "r"(1u) : "memory");
        } else {
            unsigned cur;
            do {
                __nanosleep(32);
                asm volatile("ld.acquire.gpu.u32 %0, [%1];" : "=r"(cur) : "l"(&g_bar_epoch) : "memory");
            } while (cur == e);
        }
    }
    __syncthreads();
}

// ---------------- stage loader (cp.async) ----------------
// AM 0: A0 plain [row][256]. AM 1: enc gates [eh|ctx] K=512.
// AM 2: dec gates [code|dh|ctx] K=768. AM 3: qkv dual (row<2048 -> A1 else A2) K=256.
template<int AM>
__device__ __forceinline__ void load_stage(uint32_t sb,
    const __half* __restrict__ A0, const __half* __restrict__ A1, const __half* __restrict__ A2,
    const __half* __restrict__ Bt, int bm, int bn, int KB, int kt, int slot)
{
    const int tid = threadIdx.x;
    uint32_t Ab = sb + (uint32_t)slot * STAGE_B;
    uint32_t Bb = Ab + 10240;
    const int gk0 = kt * 32;
#pragma unroll
    for (int i = 0; i < 2; i++) {
        int idx = tid + i * 256;
        int m = idx >> 2, c4 = idx & 3;
        int gk = gk0 + c4 * 8;
        int rowm = bm + m;
        const __half* ap;
        if (AM == 0)      ap = A0 + (size_t)rowm * 256 + gk;
        else if (AM == 1) ap = (gk < 256) ? (A1 + (size_t)rowm * 256 + gk)
                                          : (A2 + (size_t)rowm * 256 + gk - 256);
        else if (AM == 2) ap = (gk < 256) ? (A0 + (size_t)rowm * 256 + gk)
                        : ((gk < 512) ? (A1 + (size_t)rowm * 256 + gk - 256)
                                      : (A2 + (size_t)rowm * 256 + gk - 512));
        else { const __half* p = (rowm < R_) ? A1 : A2;
               ap = p + (size_t)(rowm & (R_ - 1)) * 256 + gk; }
        CPA(Ab + (uint32_t)(m * 80 + c4 * 16), ap);
        CPA(Bb + (uint32_t)(m * 80 + c4 * 16), Bt + (size_t)(bn + m) * KB + gk);
    }
}

// ---------------- fp16 tensor-core GEMM phase ----------------
// BM=128 BN=128 BK=32, 8 warps as 2(m)x4(n), warp tile 64x32 (4x4 m16n8k16).
// Fragments via ldmatrix.x4. EPI 0: raw  EPI 1: sigmoid(+bias)  EPI 2: fused LSTM.
template<int AM, int EPI, bool XUPD, bool CIH>
__device__ void gemm_tc(char* smp, uint32_t sb,
    const __half* __restrict__ A0, const __half* __restrict__ A1, const __half* __restrict__ A2,
    const __half* __restrict__ B0, const __half* __restrict__ B1,
    const float* __restrict__ bias, __half* __restrict__ C,
    const void* __restrict__ c_in, float* __restrict__ c_out,
    int Mtiles, int Ntiles, int NOUT, int KB, int nkt, int t,
    const float* __restrict__ input, int boff)
{
    const int tid = threadIdx.x, lane = tid & 31, warp = tid >> 5;
    const int wm = warp >> 2, wn = warp & 3;          // 2 x 4
    const int q = lane & 3, rsel = lane >> 2;
    const int tot = Mtiles * Ntiles;
    float* bias_s = (float*)(smp + BIAS_OFF);
    float* wx_s   = (float*)(smp + WX_OFF);
    // ldmatrix per-lane offset: rows (lane&15), k-chunk (lane>>4)
    const uint32_t offL = (uint32_t)((lane & 15) * 80 + (lane >> 4) * 16);

    for (int tile = (blockIdx.x + boff) % NB; tile < tot; tile += NB) {
        const int bm = (tile % Mtiles) * 128;
        const int bn = (tile / Mtiles) * 128;
        const __half* Bt = (AM == 3 && bm >= R_) ? B1 : B0;

        __syncthreads();   // prior tile fully done before overwriting smem
        if (EPI >= 1) for (int i = tid; i < 128; i += 256) bias_s[i] = bias[bn + i];
        if (XUPD)     for (int i = tid; i < 384; i += 256) wx_s[i] = g_Wx[(i >> 7) * 1024 + bn + (i & 127)];

        float acc[4][4][4];
#pragma unroll
        for (int a = 0; a < 4; a++)
#pragma unroll
            for (int b = 0; b < 4; b++)
#pragma unroll
                for (int l = 0; l < 4; l++) acc[a][b][l] = 0.0f;

        // prologue: 3 stages
#pragma unroll
        for (int s = 0; s < 3; s++) {
            if (s < nkt) load_stage<AM>(sb, A0, A1, A2, Bt, bm, bn, KB, s, s);
            CP_COMMIT();
        }

        for (int kt = 0; kt < nkt; kt++) {
            CP_WAIT2();
            __syncthreads();
            if (kt + 3 < nkt) load_stage<AM>(sb, A0, A1, A2, Bt, bm, bn, KB, kt + 3, (kt + 3) & 3);
            CP_COMMIT();

            uint32_t Ab = sb + (uint32_t)(kt & 3) * STAGE_B;
            uint32_t Bb = Ab + 10240;
#pragma unroll
            for (int st = 0; st < 2; st++) {        // two k16 steps per BK=32
                uint32_t a[4][4], b[2][4];
#pragma unroll
                for (int tm = 0; tm < 4; tm++)
                    LDSM4(a[tm][0], a[tm][1], a[tm][2], a[tm][3],
                          Ab + (uint32_t)((wm * 64 + tm * 16) * 80 + st * 32) + offL);
#pragma unroll
                for (int tp = 0; tp < 2; tp++)
                    LDSM4(b[tp][0], b[tp][1], b[tp][2], b[tp][3],
                          Bb + (uint32_t)((wn * 32 + tp * 16) * 80 + st * 32) + offL);
#pragma unroll
                for (int tm = 0; tm < 4; tm++)
#pragma unroll
                    for (int tn = 0; tn < 4; tn++) {
                        uint32_t bb[2] = { b[tn >> 1][tn & 1], b[tn >> 1][(tn & 1) + 2] };
                        mma_f16(acc[tm][tn], a[tm], bb);
                    }
            }
        }
        asm volatile("cp.async.wait_group 0;" ::: "memory");

        // ---------------- epilogue ----------------
#pragma unroll
        for (int tm = 0; tm < 4; tm++)
#pragma unroll
            for (int tn = 0; tn < 4; tn++) {
                const int r0  = bm + wm * 64 + tm * 16 + rsel;
                const int cl  = wn * 32 + tn * 8 + 2 * q;     // local col (even)
                const int col = bn + cl;
                if (EPI == 0) {
                    __half2 h01, h23;
                    h01.x = __float2half(acc[tm][tn][0]); h01.y = __float2half(acc[tm][tn][1]);
                    h23.x = __float2half(acc[tm][tn][2]); h23.y = __float2half(acc[tm][tn][3]);
                    *(__half2*)(C + (size_t)r0 * NOUT + col)       = h01;
                    *(__half2*)(C + (size_t)(r0 + 8) * NOUT + col) = h23;
                } else if (EPI == 1) {
                    float b0 = bias_s[cl], b1 = bias_s[cl + 1];
                    __half2 h01, h23;
                    h01.x = __float2half(sigmoidf_(acc[tm][tn][0] + b0));
                    h01.y = __float2half(sigmoidf_(acc[tm][tn][1] + b1));
                    h23.x = __float2half(sigmoidf_(acc[tm][tn][2] + b0));
                    h23.y = __float2half(sigmoidf_(acc[tm][tn][3] + b1));
                    *(__half2*)(C + (size_t)r0 * NOUT + col)       = h01;
                    *(__half2*)(C + (size_t)(r0 + 8) * NOUT + col) = h23;
                } else {
                    // permuted gates: col = 4h+g, order [i,f,g,o]; even-q lane holds (i,f),
                    // partner lane^1 holds (g,o).
                    float b0 = bias_s[cl], b1 = bias_s[cl + 1];
#pragma unroll
                    for (int half = 0; half < 2; half++) {
                        const int r = r0 + half * 8;
                        float v0 = acc[tm][tn][half * 2 + 0] + b0;
                        float v1 = acc[tm][tn][half * 2 + 1] + b1;
                        if (XUPD) {
                            int bb = r >> 7, s = r & (S_ - 1);
                            const float* xp = input + (((size_t)bb * T_ + t) * S_ + s) * F_;
                            float x0 = xp[0], x1 = xp[1], x2 = xp[2];
                            v0 += x0 * wx_s[cl]     + x1 * wx_s[128 + cl]     + x2 * wx_s[256 + cl];
                            v1 += x0 * wx_s[cl + 1] + x1 * wx_s[128 + cl + 1] + x2 * wx_s[256 + cl + 1];
                        }
                        float p0 = __shfl_xor_sync(0xffffffffu, v0, 1);
                        float p1 = __shfl_xor_sync(0xffffffffu, v1, 1);
                        if (!(q & 1)) {
                            int h = (bn + cl) >> 2;
                            float cprev = CIH ? __half2float(((const __half*)c_in)[(size_t)r * H_ + h])
                                              : ((const float*)c_in)[(size_t)r * H_ + h];
                            float cn = sigmoidf_(v1) * cprev + sigmoidf_(v0) * tanhf(p0);
                            float hn = sigmoidf_(p1) * tanhf(cn);
                            C[(size_t)r * H_ + h] = __float2half(hn);
                            if (c_out) c_out[(size_t)r * H_ + h] = cn;
                        }
                    }
                }
            }
    }
}

// ---------------- attention over [pbase, pbase+pcount) head-rows ----------------
__device__ __forceinline__ void attn_phase(int pbase, int pcount) {
    const int w0 = blockIdx.x * 8 + (threadIdx.x >> 5);
    const int lane = threadIdx.x & 31;
    const float scale = 0.17677669529663687f;   // 1/sqrt(32)
    for (int pi = w0; pi < pcount; pi += NB * 8) {
        int p = pbase + pi;
        int r = p >> 3;
        int head = p & (NH_ - 1);
        int s = r & (S_ - 1);
        float qv = __half2float(g_qkv[(size_t)r * 768 + head * DK_ + lane]);
        const int offs[4] = {2, 1, -1, -2};
        float sc[4];
#pragma unroll
        for (int n = 0; n < 4; n++) {
            int sn = s + offs[n];
            float d = 0.0f;
            if (sn >= 0 && sn < S_) {
                int rn = r + offs[n];
                d = qv * __half2float(g_qkv[(size_t)rn * 768 + 256 + head * DK_ + lane]);
            }
            sc[n] = warp_sum(d) * scale;
        }
        float mx = fmaxf(fmaxf(sc[0], sc[1]), fmaxf(sc[2], sc[3]));
        float e[4], sum = 0.0f;
#pragma unroll
        for (int n = 0; n < 4; n++) { e[n] = __expf(sc[n] - mx); sum += e[n]; }
        float inv = 1.0f / sum;
        float accv = 0.0f;
#pragma unroll
        for (int n = 0; n < 4; n++) {
            int sn = s + offs[n];
            if (sn >= 0 && sn < S_) {
                int rn = r + offs[n];
                accv = fmaf(e[n] * inv,
                            __half2float(g_qkv[(size_t)rn * 768 + 512 + head * DK_ + lane]), accv);
            }
        }
        __half* ctx = (r < R_) ? g_ctx_e : g_ctx_d;
        ctx[(size_t)(r & (R_ - 1)) * H_ + head * DK_ + lane] = __float2half(accv);
    }
}

// ---------------- output GEMV + assembly ----------------
__device__ __forceinline__ void out_phase(const __half* __restrict__ dh,
                                          const float* __restrict__ W,
                                          const float* __restrict__ bb,
                                          const float* __restrict__ input,
                                          float* __restrict__ dout, int t) {
    const int w0 = blockIdx.x * 8 + (threadIdx.x >> 5);
    const int lane = threadIdx.x & 31;
    for (int r = w0; r < R_; r += NB * 8) {
        int b = r >> 7, s = r & (S_ - 1);
        float s0 = 0.0f, s1 = 0.0f;
#pragma unroll
        for (int j = 0; j < H_; j += 32) {
            float wv = W[j + lane];
            s0 = fmaf(__half2float(dh[(size_t)r * H_ + j + lane]), wv, s0);
            if (s > 0) s1 = fmaf(__half2float(dh[(size_t)(r - 1) * H_ + j + lane]), wv, s1);
        }
        s0 = warp_sum(s0);
        s1 = warp_sum(s1);
        if (lane == 0) {
            float o  = s0 + bb[0];
            float In = (s > 0) ? (s1 + bb[0])
                               : input[(((size_t)b * T_ + (t + 1)) * S_ + 0) * F_ + 1];
            float num = input[(((size_t)b * T_ + t) * S_ + s) * F_ + 2] + In - o;
            size_t base = (((size_t)b * (T_ - TP_ - 1) + (t - TP_)) * S_ + s) * 3;
            dout[base + 0] = o;
            dout[base + 1] = In;
            dout[base + 2] = num;
        }
    }
}

// ---------------- persistent kernel ----------------
// Per step t (4 barriers):
//  G1: enc gates+LSTM -> eh(t), ec
//  G2: QKV dual {enc<-eh(t) [for t+1], dec<-dh(t-1) [for t]}; emb->code (blocks 104-135)
//  G3: attention (enc t+1 + dec t); out(t-1)
//  G4: dec gates+LSTM -> dh(t)
// Pre-loop: enc QKV(0) + enc attention(0).
__global__ __launch_bounds__(256, 1)
void persist_kernel(const float* __restrict__ input, const float* __restrict__ embb,
                    const float* __restrict__ outW, const float* __restrict__ outb,
                    float* __restrict__ dout)
{
    extern __shared__ char smp[];
    uint32_t sb = s2u(smp);

    int ce = 0, cd = 0;
    gemm_tc<0, 0, false, false>(smp, sb, g_eh[0], nullptr, nullptr,
                                g_We_t, nullptr, nullptr, g_qkv, nullptr, nullptr,
                                16, 6, 768, 256, 8, 0, nullptr, 0);
    gsync();
    attn_phase(0, R_ * NH_);
    gsync();

    for (int t = 0; t < T_ - 1; t++) {
        // G1: enc gates + LSTM (K=512 + rank-3 x) -> eh[ce^1], ec
        gemm_tc<1, 2, true, false>(smp, sb, nullptr, g_eh[ce], g_ctx_e,
                                   g_Wge_t, nullptr, g_bge, g_eh[ce ^ 1], g_ec, g_ec,
                                   16, 8, 256, 512, 16, t, input, 0);
        gsync();
        // G2: QKV dual; emb->code on blocks 104-135 (disjoint from QKV 2nd wave 0-43)
        gemm_tc<3, 0, false, false>(smp, sb, nullptr, g_eh[ce ^ 1], g_dh[cd],
                                    g_We_t, g_Wd_t, nullptr, g_qkv, nullptr, nullptr,
                                    32, 6, 768, 256, 8, 0, nullptr, 0);
        gemm_tc<0, 1, false, false>(smp, sb, g_eh[ce ^ 1], nullptr, nullptr,
                                    g_embT, nullptr, embb, g_code, nullptr, nullptr,
                                    16, 2, 256, 256, 8, 0, nullptr, 44);
        gsync();
        // G3: attention (enc ctx for t+1, dec ctx for t); out(t-1)
        attn_phase(0, 2 * R_ * NH_);
        if (t - 1 >= TP_) out_phase(g_dh[cd], outW, outb, input, dout, t - 1);
        gsync();
        // G4: dec gates + LSTM (K=768, c_in = dh(t-1) half) -> dh[cd^1]
        gemm_tc<2, 2, false, true>(smp, sb, g_code, g_dh[cd], g_ctx_d,
                                   g_Wgd_t, nullptr, g_bgd, g_dh[cd ^ 1], g_dh[cd], nullptr,
                                   16, 8, 256, 768, 24, 0, nullptr, 0);
        gsync();
        ce ^= 1; cd ^= 1;
    }
    out_phase(g_dh[cd], outW, outb, input, dout, T_ - 2);
}

// ---------------- single prep kernel (also: persist becomes launch parity-1 for ncu) ----------------
__global__ void prep_all_kernel(const float* __restrict__ eWq, const float* __restrict__ eWk,
                                const float* __restrict__ eWv, const float* __restrict__ eWg,
                                const float* __restrict__ ebg, const float* __restrict__ dWq,
                                const float* __restrict__ dWk, const float* __restrict__ dWv,
                                const float* __restrict__ dWg, const float* __restrict__ dbg,
                                const float* __restrict__ embW) {
    int idx = blockIdx.x * blockDim.x + threadIdx.x;   // grid covers 1024*768
    // zero state
    if (idx < R_ * H_) {
        g_eh[0][idx] = __float2half(0.0f);
        g_dh[0][idx] = __float2half(0.0f);
        g_ec[idx] = 0.0f;
    }
    // QKV weights (enc + dec), [n][k] transposed
    if (idx < 768 * 256) {
        int n = idx >> 8, k = idx & 255;
        const float* se = (n < 256) ? eWq : ((n < 512) ? eWk : eWv);
        const float* sd = (n < 256) ? dWq : ((n < 512) ? dWk : dWv);
        g_We_t[idx] = __float2half(se[(size_t)k * 256 + (n & 255)]);
        g_Wd_t[idx] = __float2half(sd[(size_t)k * 256 + (n & 255)]);
    }
    // enc gates (rows 3.., permuted cols) + x rows + bias
    if (idx < 1024 * 512) {
        int n = idx >> 9, k2 = idx & 511;
        int gcol = (n & 3) * 256 + (n >> 2);
        g_Wge_t[idx] = __float2half(eWg[(size_t)(3 + k2) * 1024 + gcol]);
        if (k2 < 3) g_Wx[k2 * 1024 + n] = eWg[(size_t)k2 * 1024 + gcol];
        if (k2 == 0) g_bge[n] = ebg[gcol];
    }
    // dec gates
    if (idx < 1024 * 768) {
        int n = idx / 768, k2 = idx - n * 768;
        int gcol = (n & 3) * 256 + (n >> 2);
        g_Wgd_t[idx] = __float2half(dWg[(size_t)k2 * 1024 + gcol]);
        if (k2 == 0) g_bgd[n] = dbg[gcol];
    }
    // emb transposed
    if (idx < 256 * 256) {
        int n = idx >> 8, k = idx & 255;
        g_embT[idx] = __float2half(embW[(size_t)k * 256 + n]);
    }
}

// ---------------- host ----------------
extern "C" void kernel_launch(void* const* d_in, const int* in_sizes, int n_in,
                              void* d_out, int out_size) {
    const float* input = (const float*)d_in[0];
    const float* eWq = (const float*)d_in[1];
    const float* eWk = (const float*)d_in[2];
    const float* eWv = (const float*)d_in[3];
    const float* eWg = (const float*)d_in[4];
    const float* ebg = (const float*)d_in[5];
    const float* dWq = (const float*)d_in[6];
    const float* dWk = (const float*)d_in[7];
    const float* dWv = (const float*)d_in[8];
    const float* dWg = (const float*)d_in[9];
    const float* dbg = (const float*)d_in[10];
    const float* embW = (const float*)d_in[11];
    const float* embb = (const float*)d_in[12];
    const float* outW = (const float*)d_in[13];
    const float* outb = (const float*)d_in[14];
    float* dout = (float*)d_out;

    static int s_init = 0;
    if (!s_init) {
        cudaFuncSetAttribute(persist_kernel, cudaFuncAttributeMaxDynamicSharedMemorySize, SMEM_SZ);
        s_init = 1;
    }

    prep_all_kernel<<<(1024 * 768 + 255) / 256, 256>>>(eWq, eWk, eWv, eWg, ebg,
                                                       dWq, dWk, dWv, dWg, dbg, embW);
    persist_kernel<<<NB, 256, SMEM_SZ>>>(input, embb, outW, outb, dout);
}

// round 12
// speedup vs baseline: 2.2277x; 1.4514x over previous
#include <cuda_runtime.h>
#include <cuda_fp16.h>
#include <cstdint>
#include <math.h>

#define B_  16
#define T_  32
#define S_  128
#define F_  3
#define H_  256
#define NH_ 8
#define DK_ 32
#define TP_ 4
#define R_  2048
#define NB  148        // one persistent block per SM
#define NT  512        // threads per block (16 warps)
#define WPB 16

// ---------------- device scratch ----------------
__device__ __half g_eh[2][R_*H_];
__device__ float  g_ec[R_*H_];
__device__ __half g_dh[2][R_*H_];
__device__ __half g_qkv[2*R_*768];     // enc rows [0,2048), dec [2048,4096)
__device__ __half g_ctx_e[R_*H_];
__device__ __half g_ctx_d[R_*H_];
__device__ __half g_code[R_*H_];
__device__ __half g_We_t[768*256];     // [n][k]
__device__ __half g_Wd_t[768*256];
__device__ __half g_Wge_t[1024*512];   // enc gates rows 3..514, cols permuted 4h+g
__device__ __half g_Wgd_t[1024*768];
__device__ __half g_embT[256*256];
__device__ float  g_Wx[3*1024];        // enc gate x-rows (fp32), permuted cols
__device__ float  g_bge[1024];
__device__ float  g_bgd[1024];
__device__ unsigned g_bar_count;
__device__ unsigned g_bar_epoch;

// ---------------- smem layout ----------------
#define STAGE_B   20480
#define BIAS_OFF  (4*STAGE_B)
#define WX_OFF    (BIAS_OFF + 512)
#define SMEM_SZ   (WX_OFF + 1536)          // 83968

__device__ __forceinline__ uint32_t s2u(const void* p) {
    uint32_t a;
    asm("{ .reg .u64 t; cvta.to.shared.u64 t, %1; cvt.u32.u64 %0, t; }" : "=r"(a) : "l"(p));
    return a;
}
#define CPA(dst, src) asm volatile("cp.async.cg.shared.global [%0], [%1], 16;" :: "r"(dst), "l"(src) : "memory")
#define CP_COMMIT()   asm volatile("cp.async.commit_group;" ::: "memory")
#define CP_WAIT2()    asm volatile("cp.async.wait_group 2;" ::: "memory")
#define LDSM4(r0, r1, r2, r3, a) \
    asm volatile("ldmatrix.sync.aligned.m8n8.x4.shared.b16 {%0,%1,%2,%3}, [%4];" \
        : "=r"(r0), "=r"(r1), "=r"(r2), "=r"(r3) : "r"(a))

__device__ __forceinline__ float sigmoidf_(float x) { return 1.0f / (1.0f + __expf(-x)); }
__device__ __forceinline__ float warp_sum(float v) {
    v += __shfl_xor_sync(0xffffffffu, v, 16);
    v += __shfl_xor_sync(0xffffffffu, v, 8);
    v += __shfl_xor_sync(0xffffffffu, v, 4);
    v += __shfl_xor_sync(0xffffffffu, v, 2);
    v += __shfl_xor_sync(0xffffffffu, v, 1);
    return v;
}

__device__ __forceinline__ void mma_f16(float* d, const uint32_t* a, const uint32_t* b) {
    asm volatile(
        "mma.sync.aligned.m16n8k16.row.col.f32.f16.f16.f32 "
        "{%0,%1,%2,%3}, {%4,%5,%6,%7}, {%8,%9}, {%0,%1,%2,%3};\n"
        : "+f"(d[0]), "+f"(d[1]), "+f"(d[2]), "+f"(d[3])
        : "r"(a[0]), "r"(a[1]), "r"(a[2]), "r"(a[3]), "r"(b[0]), "r"(b[1]));
}

// ---------------- grid barrier ----------------
__device__ __forceinline__ void gsync() {
    __syncthreads();
    if (threadIdx.x == 0) {
        unsigned e;
        asm volatile("ld.acquire.gpu.u32 %0, [%1];" : "=r"(e) : "l"(&g_bar_epoch) : "memory");
        unsigned old;
        asm volatile("atom.add.acq_rel.gpu.u32 %0, [%1], %2;"
                     : "=r"(old) : "l"(&g_bar_count), "r"(1u) : "memory");
        if (old == NB - 1) {
            g_bar_count = 0;
            unsigned dummy;
            asm volatile("atom.add.release.gpu.u32 %0, [%1], %2;"
                         : "=r"(dummy) : "l"(&g_bar_epoch), "r"(1u) : "memory");
        } else {
            unsigned cur;
            do {
                __nanosleep(32);
                asm volatile("ld.acquire.gpu.u32 %0, [%1];" : "=r"(cur) : "l"(&g_bar_epoch) : "memory");
            } while (cur == e);
        }
    }
    __syncthreads();
}

// ---------------- stage loader (cp.async): one A + one B 16B xfer per thread ----------------
// AM 0: A0 plain [row][256]. AM 1: enc gates [eh|ctx] K=512.
// AM 2: dec gates [code|dh|ctx] K=768. AM 3: qkv dual (row<2048 -> A1 else A2) K=256.
template<int AM>
__device__ __forceinline__ void load_stage(uint32_t sb,
    const __half* __restrict__ A0, const __half* __restrict__ A1, const __half* __restrict__ A2,
    const __half* __restrict__ Bt, int bm, int bn, int KB, int kt, int slot)
{
    const int tid = threadIdx.x;
    uint32_t Ab = sb + (uint32_t)slot * STAGE_B;
    uint32_t Bb = Ab + 10240;
    const int gk0 = kt * 32;
    int m = tid >> 2, c4 = tid & 3;
    int gk = gk0 + c4 * 8;
    int rowm = bm + m;
    const __half* ap;
    if (AM == 0)      ap = A0 + (size_t)rowm * 256 + gk;
    else if (AM == 1) ap = (gk < 256) ? (A1 + (size_t)rowm * 256 + gk)
                                      : (A2 + (size_t)rowm * 256 + gk - 256);
    else if (AM == 2) ap = (gk < 256) ? (A0 + (size_t)rowm * 256 + gk)
                    : ((gk < 512) ? (A1 + (size_t)rowm * 256 + gk - 256)
                                  : (A2 + (size_t)rowm * 256 + gk - 512));
    else { const __half* p = (rowm < R_) ? A1 : A2;
           ap = p + (size_t)(rowm & (R_ - 1)) * 256 + gk; }
    CPA(Ab + (uint32_t)(m * 80 + c4 * 16), ap);
    CPA(Bb + (uint32_t)(m * 80 + c4 * 16), Bt + (size_t)(bn + m) * KB + gk);
}

// ---------------- fp16 tensor-core GEMM phase ----------------
// BM=128 BN=128 BK=32, 16 warps as 4(m)x4(n), warp tile 32x32 (2x4 m16n8k16).
// Fragments via ldmatrix.x4. EPI 0: raw  EPI 1: sigmoid(+bias)  EPI 2: fused LSTM.
template<int AM, int EPI, bool XUPD, bool CIH>
__device__ void gemm_tc(char* smp, uint32_t sb,
    const __half* __restrict__ A0, const __half* __restrict__ A1, const __half* __restrict__ A2,
    const __half* __restrict__ B0, const __half* __restrict__ B1,
    const float* __restrict__ bias, __half* __restrict__ C,
    const void* __restrict__ c_in, float* __restrict__ c_out,
    int Mtiles, int Ntiles, int NOUT, int KB, int nkt, int t,
    const float* __restrict__ input, int boff)
{
    const int tid = threadIdx.x, lane = tid & 31, warp = tid >> 5;
    const int wm = warp >> 2, wn = warp & 3;          // 4 x 4
    const int q = lane & 3, rsel = lane >> 2;
    const int tot = Mtiles * Ntiles;
    float* bias_s = (float*)(smp + BIAS_OFF);
    float* wx_s   = (float*)(smp + WX_OFF);
    const uint32_t offL = (uint32_t)((lane & 15) * 80 + (lane >> 4) * 16);

    for (int tile = (blockIdx.x + boff) % NB; tile < tot; tile += NB) {
        const int bm = (tile % Mtiles) * 128;
        const int bn = (tile / Mtiles) * 128;
        const __half* Bt = (AM == 3 && bm >= R_) ? B1 : B0;

        __syncthreads();   // prior tile fully done before overwriting smem
        if (EPI >= 1) for (int i = tid; i < 128; i += NT) bias_s[i] = bias[bn + i];
        if (XUPD)     for (int i = tid; i < 384; i += NT) wx_s[i] = g_Wx[(i >> 7) * 1024 + bn + (i & 127)];

        float acc[2][4][4];
#pragma unroll
        for (int a = 0; a < 2; a++)
#pragma unroll
            for (int b = 0; b < 4; b++)
#pragma unroll
                for (int l = 0; l < 4; l++) acc[a][b][l] = 0.0f;

        // prologue: 3 stages
#pragma unroll
        for (int s = 0; s < 3; s++) {
            if (s < nkt) load_stage<AM>(sb, A0, A1, A2, Bt, bm, bn, KB, s, s);
            CP_COMMIT();
        }

        for (int kt = 0; kt < nkt; kt++) {
            CP_WAIT2();
            __syncthreads();
            if (kt + 3 < nkt) load_stage<AM>(sb, A0, A1, A2, Bt, bm, bn, KB, kt + 3, (kt + 3) & 3);
            CP_COMMIT();

            uint32_t Ab = sb + (uint32_t)(kt & 3) * STAGE_B;
            uint32_t Bb = Ab + 10240;
#pragma unroll
            for (int st = 0; st < 2; st++) {        // two k16 steps per BK=32
                uint32_t a[2][4], b[2][4];
#pragma unroll
                for (int tm = 0; tm < 2; tm++)
                    LDSM4(a[tm][0], a[tm][1], a[tm][2], a[tm][3],
                          Ab + (uint32_t)((wm * 32 + tm * 16) * 80 + st * 32) + offL);
#pragma unroll
                for (int tp = 0; tp < 2; tp++)
                    LDSM4(b[tp][0], b[tp][1], b[tp][2], b[tp][3],
                          Bb + (uint32_t)((wn * 32 + tp * 16) * 80 + st * 32) + offL);
#pragma unroll
                for (int tm = 0; tm < 2; tm++)
#pragma unroll
                    for (int tn = 0; tn < 4; tn++) {
                        uint32_t bb[2] = { b[tn >> 1][tn & 1], b[tn >> 1][(tn & 1) + 2] };
                        mma_f16(acc[tm][tn], a[tm], bb);
                    }
            }
        }
        asm volatile("cp.async.wait_group 0;" ::: "memory");

        // ---------------- epilogue ----------------
#pragma unroll
        for (int tm = 0; tm < 2; tm++)
#pragma unroll
            for (int tn = 0; tn < 4; tn++) {
                const int r0  = bm + wm * 32 + tm * 16 + rsel;
                const int cl  = wn * 32 + tn * 8 + 2 * q;     // local col (even)
                const int col = bn + cl;
                if (EPI == 0) {
                    __half2 h01, h23;
                    h01.x = __float2half(acc[tm][tn][0]); h01.y = __float2half(acc[tm][tn][1]);
                    h23.x = __float2half(acc[tm][tn][2]); h23.y = __float2half(acc[tm][tn][3]);
                    *(__half2*)(C + (size_t)r0 * NOUT + col)       = h01;
                    *(__half2*)(C + (size_t)(r0 + 8) * NOUT + col) = h23;
                } else if (EPI == 1) {
                    float b0 = bias_s[cl], b1 = bias_s[cl + 1];
                    __half2 h01, h23;
                    h01.x = __float2half(sigmoidf_(acc[tm][tn][0] + b0));
                    h01.y = __float2half(sigmoidf_(acc[tm][tn][1] + b1));
                    h23.x = __float2half(sigmoidf_(acc[tm][tn][2] + b0));
                    h23.y = __float2half(sigmoidf_(acc[tm][tn][3] + b1));
                    *(__half2*)(C + (size_t)r0 * NOUT + col)       = h01;
                    *(__half2*)(C + (size_t)(r0 + 8) * NOUT + col) = h23;
                } else {
                    // permuted gates: col = 4h+g, order [i,f,g,o]; even-q lane holds (i,f),
                    // partner lane^1 holds (g,o).
                    float b0 = bias_s[cl], b1 = bias_s[cl + 1];
#pragma unroll
                    for (int half = 0; half < 2; half++) {
                        const int r = r0 + half * 8;
                        float v0 = acc[tm][tn][half * 2 + 0] + b0;
                        float v1 = acc[tm][tn][half * 2 + 1] + b1;
                        if (XUPD) {
                            int bb = r >> 7, s = r & (S_ - 1);
                            const float* xp = input + (((size_t)bb * T_ + t) * S_ + s) * F_;
                            float x0 = xp[0], x1 = xp[1], x2 = xp[2];
                            v0 += x0 * wx_s[cl]     + x1 * wx_s[128 + cl]     + x2 * wx_s[256 + cl];
                            v1 += x0 * wx_s[cl + 1] + x1 * wx_s[128 + cl + 1] + x2 * wx_s[256 + cl + 1];
                        }
                        float p0 = __shfl_xor_sync(0xffffffffu, v0, 1);
                        float p1 = __shfl_xor_sync(0xffffffffu, v1, 1);
                        if (!(q & 1)) {
                            int h = (bn + cl) >> 2;
                            float cprev = CIH ? __half2float(((const __half*)c_in)[(size_t)r * H_ + h])
                                              : ((const float*)c_in)[(size_t)r * H_ + h];
                            float cn = sigmoidf_(v1) * cprev + sigmoidf_(v0) * tanhf(p0);
                            float hn = sigmoidf_(p1) * tanhf(cn);
                            C[(size_t)r * H_ + h] = __float2half(hn);
                            if (c_out) c_out[(size_t)r * H_ + h] = cn;
                        }
                    }
                }
            }
    }
}

// ---------------- attention over [pbase, pbase+pcount) head-rows ----------------
__device__ __forceinline__ void attn_phase(int pbase, int pcount) {
    const int w0 = blockIdx.x * WPB + (threadIdx.x >> 5);
    const int lane = threadIdx.x & 31;
    const float scale = 0.17677669529663687f;   // 1/sqrt(32)
    for (int pi = w0; pi < pcount; pi += NB * WPB) {
        int p = pbase + pi;
        int r = p >> 3;
        int head = p & (NH_ - 1);
        int s = r & (S_ - 1);
        float qv = __half2float(g_qkv[(size_t)r * 768 + head * DK_ + lane]);
        const int offs[4] = {2, 1, -1, -2};
        float sc[4];
#pragma unroll
        for (int n = 0; n < 4; n++) {
            int sn = s + offs[n];
            float d = 0.0f;
            if (sn >= 0 && sn < S_) {
                int rn = r + offs[n];
                d = qv * __half2float(g_qkv[(size_t)rn * 768 + 256 + head * DK_ + lane]);
            }
            sc[n] = warp_sum(d) * scale;
        }
        float mx = fmaxf(fmaxf(sc[0], sc[1]), fmaxf(sc[2], sc[3]));
        float e[4], sum = 0.0f;
#pragma unroll
        for (int n = 0; n < 4; n++) { e[n] = __expf(sc[n] - mx); sum += e[n]; }
        float inv = 1.0f / sum;
        float accv = 0.0f;
#pragma unroll
        for (int n = 0; n < 4; n++) {
            int sn = s + offs[n];
            if (sn >= 0 && sn < S_) {
                int rn = r + offs[n];
                accv = fmaf(e[n] * inv,
                            __half2float(g_qkv[(size_t)rn * 768 + 512 + head * DK_ + lane]), accv);
            }
        }
        __half* ctx = (r < R_) ? g_ctx_e : g_ctx_d;
        ctx[(size_t)(r & (R_ - 1)) * H_ + head * DK_ + lane] = __float2half(accv);
    }
}

// ---------------- output GEMV + assembly ----------------
__device__ __forceinline__ void out_phase(const __half* __restrict__ dh,
                                          const float* __restrict__ W,
                                          const float* __restrict__ bb,
                                          const float* __restrict__ input,
                                          float* __restrict__ dout, int t) {
    const int w0 = blockIdx.x * WPB + (threadIdx.x >> 5);
    const int lane = threadIdx.x & 31;
    for (int r = w0; r < R_; r += NB * WPB) {
        int b = r >> 7, s = r & (S_ - 1);
        float s0 = 0.0f, s1 = 0.0f;
#pragma unroll
        for (int j = 0; j < H_; j += 32) {
            float wv = W[j + lane];
            s0 = fmaf(__half2float(dh[(size_t)r * H_ + j + lane]), wv, s0);
            if (s > 0) s1 = fmaf(__half2float(dh[(size_t)(r - 1) * H_ + j + lane]), wv, s1);
        }
        s0 = warp_sum(s0);
        s1 = warp_sum(s1);
        if (lane == 0) {
            float o  = s0 + bb[0];
            float In = (s > 0) ? (s1 + bb[0])
                               : input[(((size_t)b * T_ + (t + 1)) * S_ + 0) * F_ + 1];
            float num = input[(((size_t)b * T_ + t) * S_ + s) * F_ + 2] + In - o;
            size_t base = (((size_t)b * (T_ - TP_ - 1) + (t - TP_)) * S_ + s) * 3;
            dout[base + 0] = o;
            dout[base + 1] = In;
            dout[base + 2] = num;
        }
    }
}

// ---------------- persistent kernel ----------------
// Per step t (4 barriers):
//  G1: enc gates+LSTM -> eh(t), ec
//  G2: QKV dual {enc<-eh(t) [for t+1], dec<-dh(t-1) [for t]}; emb->code (offset blocks)
//  G3: attention (enc t+1 + dec t); out(t-1)
//  G4: dec gates+LSTM -> dh(t)
__global__ __launch_bounds__(NT, 1)
void persist_kernel(const float* __restrict__ input, const float* __restrict__ embb,
                    const float* __restrict__ outW, const float* __restrict__ outb,
                    float* __restrict__ dout)
{
    extern __shared__ char smp[];
    uint32_t sb = s2u(smp);

    int ce = 0, cd = 0;
    gemm_tc<0, 0, false, false>(smp, sb, g_eh[0], nullptr, nullptr,
                                g_We_t, nullptr, nullptr, g_qkv, nullptr, nullptr,
                                16, 6, 768, 256, 8, 0, nullptr, 0);
    gsync();
    attn_phase(0, R_ * NH_);
    gsync();

    for (int t = 0; t < T_ - 1; t++) {
        // G1: enc gates + LSTM (K=512 + rank-3 x) -> eh[ce^1], ec
        gemm_tc<1, 2, true, false>(smp, sb, nullptr, g_eh[ce], g_ctx_e,
                                   g_Wge_t, nullptr, g_bge, g_eh[ce ^ 1], g_ec, g_ec,
                                   16, 8, 256, 512, 16, t, input, 0);
        gsync();
        // G2: QKV dual; emb->code on offset blocks (disjoint from QKV 2nd wave 0-43)
        gemm_tc<3, 0, false, false>(smp, sb, nullptr, g_eh[ce ^ 1], g_dh[cd],
                                    g_We_t, g_Wd_t, nullptr, g_qkv, nullptr, nullptr,
                                    32, 6, 768, 256, 8, 0, nullptr, 0);
        gemm_tc<0, 1, false, false>(smp, sb, g_eh[ce ^ 1], nullptr, nullptr,
                                    g_embT, nullptr, embb, g_code, nullptr, nullptr,
                                    16, 2, 256, 256, 8, 0, nullptr, 44);
        gsync();
        // G3: attention (enc ctx for t+1, dec ctx for t); out(t-1)
        attn_phase(0, 2 * R_ * NH_);
        if (t - 1 >= TP_) out_phase(g_dh[cd], outW, outb, input, dout, t - 1);
        gsync();
        // G4: dec gates + LSTM (K=768, c_in = dh(t-1) half) -> dh[cd^1]
        gemm_tc<2, 2, false, true>(smp, sb, g_code, g_dh[cd], g_ctx_d,
                                   g_Wgd_t, nullptr, g_bgd, g_dh[cd ^ 1], g_dh[cd], nullptr,
                                   16, 8, 256, 768, 24, 0, nullptr, 0);
        gsync();
        ce ^= 1; cd ^= 1;
    }
    out_phase(g_dh[cd], outW, outb, input, dout, T_ - 2);
}

// ---------------- single prep kernel ----------------
__global__ void prep_all_kernel(const float* __restrict__ eWq, const float* __restrict__ eWk,
                                const float* __restrict__ eWv, const float* __restrict__ eWg,
                                const float* __restrict__ ebg, const float* __restrict__ dWq,
                                const float* __restrict__ dWk, const float* __restrict__ dWv,
                                const float* __restrict__ dWg, const float* __restrict__ dbg,
                                const float* __restrict__ embW) {
    int idx = blockIdx.x * blockDim.x + threadIdx.x;   // grid covers 1024*768
    if (idx < R_ * H_) {
        g_eh[0][idx] = __float2half(0.0f);
        g_dh[0][idx] = __float2half(0.0f);
        g_ec[idx] = 0.0f;
    }
    if (idx < 768 * 256) {
        int n = idx >> 8, k = idx & 255;
        const float* se = (n < 256) ? eWq : ((n < 512) ? eWk : eWv);
        const float* sd = (n < 256) ? dWq : ((n < 512) ? dWk : dWv);
        g_We_t[idx] = __float2half(se[(size_t)k * 256 + (n & 255)]);
        g_Wd_t[idx] = __float2half(sd[(size_t)k * 256 + (n & 255)]);
    }
    if (idx < 1024 * 512) {
        int n = idx >> 9, k2 = idx & 511;
        int gcol = (n & 3) * 256 + (n >> 2);
        g_Wge_t[idx] = __float2half(eWg[(size_t)(3 + k2) * 1024 + gcol]);
        if (k2 < 3) g_Wx[k2 * 1024 + n] = eWg[(size_t)k2 * 1024 + gcol];
        if (k2 == 0) g_bge[n] = ebg[gcol];
    }
    if (idx < 1024 * 768) {
        int n = idx / 768, k2 = idx - n * 768;
        int gcol = (n & 3) * 256 + (n >> 2);
        g_Wgd_t[idx] = __float2half(dWg[(size_t)k2 * 1024 + gcol]);
        if (k2 == 0) g_bgd[n] = dbg[gcol];
    }
    if (idx < 256 * 256) {
        int n = idx >> 8, k = idx & 255;
        g_embT[idx] = __float2half(embW[(size_t)k * 256 + n]);
    }
}

// ---------------- host ----------------
extern "C" void kernel_launch(void* const* d_in, const int* in_sizes, int n_in,
                              void* d_out, int out_size) {
    const float* input = (const float*)d_in[0];
    const float* eWq = (const float*)d_in[1];
    const float* eWk = (const float*)d_in[2];
    const float* eWv = (const float*)d_in[3];
    const float* eWg = (const float*)d_in[4];
    const float* ebg = (const float*)d_in[5];
    const float* dWq = (const float*)d_in[6];
    const float* dWk = (const float*)d_in[7];
    const float* dWv = (const float*)d_in[8];
    const float* dWg = (const float*)d_in[9];
    const float* dbg = (const float*)d_in[10];
    const float* embW = (const float*)d_in[11];
    const float* embb = (const float*)d_in[12];
    const float* outW = (const float*)d_in[13];
    const float* outb = (const float*)d_in[14];
    float* dout = (float*)d_out;

    static int s_init = 0;
    if (!s_init) {
        cudaFuncSetAttribute(persist_kernel, cudaFuncAttributeMaxDynamicSharedMemorySize, SMEM_SZ);
        s_init = 1;
    }

    prep_all_kernel<<<(1024 * 768 + 255) / 256, 256>>>(eWq, eWk, eWv, eWg, ebg,
                                                       dWq, dWk, dWv, dWg, dbg, embW);
    persist_kernel<<<NB, NT, SMEM_SZ>>>(input, embb, outW, outb, dout);
}

// round 13
// speedup vs baseline: 2.8724x; 1.2894x over previous
#include <cuda_runtime.h>
#include <cuda_fp16.h>
#include <cstdint>
#include <math.h>

#define B_  16
#define T_  32
#define S_  128
#define F_  3
#define H_  256
#define NH_ 8
#define DK_ 32
#define TP_ 4
#define R_  2048
#define NB  148        // one persistent block per SM
#define NT  512        // threads per block (16 warps)
#define WPB 16

// ---------------- device scratch ----------------
__device__ __half g_eh[2][R_*H_];
__device__ float  g_ec[R_*H_];
__device__ __half g_dh[2][R_*H_];
__device__ __half g_qkv[2*R_*768];     // enc rows [0,2048), dec [2048,4096)
__device__ __half g_ctx_e[R_*H_];
__device__ __half g_ctx_d[R_*H_];
__device__ __half g_code[R_*H_];
__device__ __half g_We_t[768*256];     // [n][k]
__device__ __half g_Wd_t[768*256];
__device__ __half g_Wge_t[1024*512];   // enc gates rows 3..514, cols permuted 4h+g
__device__ __half g_Wgd_t[1024*768];
__device__ __half g_embT[256*256];
__device__ float  g_Wx[3*1024];        // enc gate x-rows (fp32), permuted cols
__device__ float  g_bge[1024];
__device__ float  g_bgd[1024];
__device__ unsigned g_bar_count;
__device__ unsigned g_bar_epoch;

// ---------------- smem layout: 8 cp.async stages + mbarriers + bias/wx ----------------
#define NSTAGE    8
#define STAGE_B   20480
#define MBAR_OFF  (NSTAGE*STAGE_B)         // 163840; full[8] @ +s*16, empty[8] @ +128+s*16
#define BIAS_OFF  (MBAR_OFF + 256)
#define WX_OFF    (BIAS_OFF + 512)
#define SMEM_SZ   (WX_OFF + 1536)          // 166144

__device__ __forceinline__ uint32_t s2u(const void* p) {
    uint32_t a;
    asm("{ .reg .u64 t; cvta.to.shared.u64 t, %1; cvt.u32.u64 %0, t; }" : "=r"(a) : "l"(p));
    return a;
}
#define CPA(dst, src) asm volatile("cp.async.cg.shared.global [%0], [%1], 16;" :: "r"(dst), "l"(src) : "memory")
#define CP_ARRIVE(a)  asm volatile("cp.async.mbarrier.arrive.noinc.shared.b64 [%0];" :: "r"(a) : "memory")
#define MBAR_INIT(a, c) asm volatile("mbarrier.init.shared.b64 [%0], %1;" :: "r"(a), "r"(c) : "memory")
#define MBAR_ARRIVE(a)  asm volatile("mbarrier.arrive.shared.b64 _, [%0];" :: "r"(a) : "memory")
#define MBAR_WAITP(a, par) do { \
    uint32_t _m = (a), _p = (par), _d; \
    asm volatile("{ .reg .pred p; mbarrier.try_wait.parity.acquire.cta.shared::cta.b64 p, [%1], %2; selp.b32 %0,1,0,p; }" \
        : "=r"(_d) : "r"(_m), "r"(_p) : "memory"); \
    if (!_d) { \
        asm volatile("{ .reg .pred P1; WL_%=: mbarrier.try_wait.parity.acquire.cta.shared::cta.b64 P1, [%0], %1, 0x989680;" \
            " @P1 bra.uni WD_%=; bra.uni WL_%=; WD_%=: }" :: "r"(_m), "r"(_p) : "memory"); \
    } } while (0)
#define LDSM4(r0, r1, r2, r3, a) \
    asm volatile("ldmatrix.sync.aligned.m8n8.x4.shared.b16 {%0,%1,%2,%3}, [%4];" \
        : "=r"(r0), "=r"(r1), "=r"(r2), "=r"(r3) : "r"(a))

__device__ __forceinline__ float sigmoidf_(float x) { return 1.0f / (1.0f + __expf(-x)); }
__device__ __forceinline__ float warp_sum(float v) {
    v += __shfl_xor_sync(0xffffffffu, v, 16);
    v += __shfl_xor_sync(0xffffffffu, v, 8);
    v += __shfl_xor_sync(0xffffffffu, v, 4);
    v += __shfl_xor_sync(0xffffffffu, v, 2);
    v += __shfl_xor_sync(0xffffffffu, v, 1);
    return v;
}

__device__ __forceinline__ void mma_f16(float* d, const uint32_t* a, const uint32_t* b) {
    asm volatile(
        "mma.sync.aligned.m16n8k16.row.col.f32.f16.f16.f32 "
        "{%0,%1,%2,%3}, {%4,%5,%6,%7}, {%8,%9}, {%0,%1,%2,%3};\n"
        : "+f"(d[0]), "+f"(d[1]), "+f"(d[2]), "+f"(d[3])
        : "r"(a[0]), "r"(a[1]), "r"(a[2]), "r"(a[3]), "r"(b[0]), "r"(b[1]));
}

// ---------------- grid barrier ----------------
__device__ __forceinline__ void gsync() {
    __syncthreads();
    if (threadIdx.x == 0) {
        unsigned e;
        asm volatile("ld.acquire.gpu.u32 %0, [%1];" : "=r"(e) : "l"(&g_bar_epoch) : "memory");
        unsigned old;
        asm volatile("atom.add.acq_rel.gpu.u32 %0, [%1], %2;"
                     : "=r"(old) : "l"(&g_bar_count), "r"(1u) : "memory");
        if (old == NB - 1) {
            g_bar_count = 0;
            unsigned dummy;
            asm volatile("atom.add.release.gpu.u32 %0, [%1], %2;"
                         : "=r"(dummy) : "l"(&g_bar_epoch), "r"(1u) : "memory");
        } else {
            unsigned cur;
            do {
                __nanosleep(32);
                asm volatile("ld.acquire.gpu.u32 %0, [%1];" : "=r"(cur) : "l"(&g_bar_epoch) : "memory");
            } while (cur == e);
        }
    }
    __syncthreads();
}

// ---------------- stage loader (cp.async): one A + one B 16B xfer per thread ----------------
template<int AM>
__device__ __forceinline__ void load_stage(uint32_t sb,
    const __half* __restrict__ A0, const __half* __restrict__ A1, const __half* __restrict__ A2,
    const __half* __restrict__ Bt, int bm, int bn, int KB, int kt, int slot)
{
    const int tid = threadIdx.x;
    uint32_t Ab = sb + (uint32_t)slot * STAGE_B;
    uint32_t Bb = Ab + 10240;
    const int gk0 = kt * 32;
    int m = tid >> 2, c4 = tid & 3;
    int gk = gk0 + c4 * 8;
    int rowm = bm + m;
    const __half* ap;
    if (AM == 0)      ap = A0 + (size_t)rowm * 256 + gk;
    else if (AM == 1) ap = (gk < 256) ? (A1 + (size_t)rowm * 256 + gk)
                                      : (A2 + (size_t)rowm * 256 + gk - 256);
    else if (AM == 2) ap = (gk < 256) ? (A0 + (size_t)rowm * 256 + gk)
                    : ((gk < 512) ? (A1 + (size_t)rowm * 256 + gk - 256)
                                  : (A2 + (size_t)rowm * 256 + gk - 512));
    else { const __half* p = (rowm < R_) ? A1 : A2;
           ap = p + (size_t)(rowm & (R_ - 1)) * 256 + gk; }
    CPA(Ab + (uint32_t)(m * 80 + c4 * 16), ap);
    CPA(Bb + (uint32_t)(m * 80 + c4 * 16), Bt + (size_t)(bn + m) * KB + gk);
}

// ---------------- fp16 tensor-core GEMM phase (mbarrier ring, no mainloop syncs) ----------------
template<int AM, int EPI, bool XUPD, bool CIH>
__device__ void gemm_tc(char* smp, uint32_t sb, int& gbase,
    const __half* __restrict__ A0, const __half* __restrict__ A1, const __half* __restrict__ A2,
    const __half* __restrict__ B0, const __half* __restrict__ B1,
    const float* __restrict__ bias, __half* __restrict__ C,
    const void* __restrict__ c_in, float* __restrict__ c_out,
    int Mtiles, int Ntiles, int NOUT, int KB, int nkt, int t,
    const float* __restrict__ input, int boff)
{
    const int tid = threadIdx.x, lane = tid & 31, warp = tid >> 5;
    const int wm = warp >> 2, wn = warp & 3;          // 4 x 4
    const int q = lane & 3, rsel = lane >> 2;
    const int tot = Mtiles * Ntiles;
    float* bias_s = (float*)(smp + BIAS_OFF);
    float* wx_s   = (float*)(smp + WX_OFF);
    const uint32_t sbm = sb + MBAR_OFF;
    const uint32_t offL = (uint32_t)((lane & 15) * 80 + (lane >> 4) * 16);

    for (int tile = (blockIdx.x + boff) % NB; tile < tot; tile += NB) {
        const int bm = (tile % Mtiles) * 128;
        const int bn = (tile / Mtiles) * 128;
        const __half* Bt = (AM == 3 && bm >= R_) ? B1 : B0;

        __syncthreads();   // prior tile epilogue done before bias/wx overwrite
        if (EPI >= 1) for (int i = tid; i < 128; i += NT) bias_s[i] = bias[bn + i];
        if (XUPD)     for (int i = tid; i < 384; i += NT) wx_s[i] = g_Wx[(i >> 7) * 1024 + bn + (i & 127)];

        float acc[2][4][4];
#pragma unroll
        for (int a = 0; a < 2; a++)
#pragma unroll
            for (int b = 0; b < 4; b++)
#pragma unroll
                for (int l = 0; l < 4; l++) acc[a][b][l] = 0.0f;

        // prologue: fill 4 stages (nkt >= 8 always)
#pragma unroll
        for (int s = 0; s < 4; s++) {
            int g = gbase + s;
            if (g >= NSTAGE) MBAR_WAITP(sbm + 128 + (g & 7) * 16, ((g >> 3) - 1) & 1);
            load_stage<AM>(sb, A0, A1, A2, Bt, bm, bn, KB, s, g & 7);
            CP_ARRIVE(sbm + (g & 7) * 16);
        }

        for (int kt = 0; kt < nkt; kt++) {
            if (kt + 4 < nkt) {
                int g = gbase + kt + 4;
                if (g >= NSTAGE) MBAR_WAITP(sbm + 128 + (g & 7) * 16, ((g >> 3) - 1) & 1);
                load_stage<AM>(sb, A0, A1, A2, Bt, bm, bn, KB, kt + 4, g & 7);
                CP_ARRIVE(sbm + (g & 7) * 16);
            }
            const int gc = gbase + kt;
            MBAR_WAITP(sbm + (gc & 7) * 16, (gc >> 3) & 1);

            uint32_t Ab = sb + (uint32_t)(gc & 7) * STAGE_B;
            uint32_t Bb = Ab + 10240;
#pragma unroll
            for (int st = 0; st < 2; st++) {        // two k16 steps per BK=32
                uint32_t a[2][4], b[2][4];
#pragma unroll
                for (int tm = 0; tm < 2; tm++)
                    LDSM4(a[tm][0], a[tm][1], a[tm][2], a[tm][3],
                          Ab + (uint32_t)((wm * 32 + tm * 16) * 80 + st * 32) + offL);
#pragma unroll
                for (int tp = 0; tp < 2; tp++)
                    LDSM4(b[tp][0], b[tp][1], b[tp][2], b[tp][3],
                          Bb + (uint32_t)((wn * 32 + tp * 16) * 80 + st * 32) + offL);
#pragma unroll
                for (int tm = 0; tm < 2; tm++)
#pragma unroll
                    for (int tn = 0; tn < 4; tn++) {
                        uint32_t bb[2] = { b[tn >> 1][tn & 1], b[tn >> 1][(tn & 1) + 2] };
                        mma_f16(acc[tm][tn], a[tm], bb);
                    }
            }
            if (lane == 0) MBAR_ARRIVE(sbm + 128 + (gc & 7) * 16);
        }
        gbase += nkt;

        // ---------------- epilogue ----------------
#pragma unroll
        for (int tm = 0; tm < 2; tm++)
#pragma unroll
            for (int tn = 0; tn < 4; tn++) {
                const int r0  = bm + wm * 32 + tm * 16 + rsel;
                const int cl  = wn * 32 + tn * 8 + 2 * q;     // local col (even)
                const int col = bn + cl;
                if (EPI == 0) {
                    __half2 h01, h23;
                    h01.x = __float2half(acc[tm][tn][0]); h01.y = __float2half(acc[tm][tn][1]);
                    h23.x = __float2half(acc[tm][tn][2]); h23.y = __float2half(acc[tm][tn][3]);
                    *(__half2*)(C + (size_t)r0 * NOUT + col)       = h01;
                    *(__half2*)(C + (size_t)(r0 + 8) * NOUT + col) = h23;
                } else if (EPI == 1) {
                    float b0 = bias_s[cl], b1 = bias_s[cl + 1];
                    __half2 h01, h23;
                    h01.x = __float2half(sigmoidf_(acc[tm][tn][0] + b0));
                    h01.y = __float2half(sigmoidf_(acc[tm][tn][1] + b1));
                    h23.x = __float2half(sigmoidf_(acc[tm][tn][2] + b0));
                    h23.y = __float2half(sigmoidf_(acc[tm][tn][3] + b1));
                    *(__half2*)(C + (size_t)r0 * NOUT + col)       = h01;
                    *(__half2*)(C + (size_t)(r0 + 8) * NOUT + col) = h23;
                } else {
                    float b0 = bias_s[cl], b1 = bias_s[cl + 1];
#pragma unroll
                    for (int half = 0; half < 2; half++) {
                        const int r = r0 + half * 8;
                        float v0 = acc[tm][tn][half * 2 + 0] + b0;
                        float v1 = acc[tm][tn][half * 2 + 1] + b1;
                        if (XUPD) {
                            int bb = r >> 7, s = r & (S_ - 1);
                            const float* xp = input + (((size_t)bb * T_ + t) * S_ + s) * F_;
                            float x0 = xp[0], x1 = xp[1], x2 = xp[2];
                            v0 += x0 * wx_s[cl]     + x1 * wx_s[128 + cl]     + x2 * wx_s[256 + cl];
                            v1 += x0 * wx_s[cl + 1] + x1 * wx_s[128 + cl + 1] + x2 * wx_s[256 + cl + 1];
                        }
                        float p0 = __shfl_xor_sync(0xffffffffu, v0, 1);
                        float p1 = __shfl_xor_sync(0xffffffffu, v1, 1);
                        if (!(q & 1)) {
                            int h = (bn + cl) >> 2;
                            float cprev = CIH ? __half2float(((const __half*)c_in)[(size_t)r * H_ + h])
                                              : ((const float*)c_in)[(size_t)r * H_ + h];
                            float cn = sigmoidf_(v1) * cprev + sigmoidf_(v0) * tanhf(p0);
                            float hn = sigmoidf_(p1) * tanhf(cn);
                            C[(size_t)r * H_ + h] = __float2half(hn);
                            if (c_out) c_out[(size_t)r * H_ + h] = cn;
                        }
                    }
                }
            }
    }
}

// ---------------- attention: one warp per row, all 8 heads at once ----------------
// lane l owns elements [8l, 8l+8) of the 256-wide row (head = l/4).
// Quad reduce (xor 1, xor 2) completes each head's 32-elem dot.
__device__ __forceinline__ void attn_phase() {
    const int w0 = blockIdx.x * WPB + (threadIdx.x >> 5);
    const int lane = threadIdx.x & 31;
    const float scale = 0.17677669529663687f;   // 1/sqrt(32)
    for (int r = w0; r < 2 * R_; r += NB * WPB) {
        int s = r & (S_ - 1);
        const __half* rowq = g_qkv + (size_t)r * 768 + 8 * lane;
        uint4 qraw = *(const uint4*)rowq;
        const __half2* q2 = (const __half2*)&qraw;
        const int offs[4] = {2, 1, -1, -2};
        float d[4];
        bool ok[4];
#pragma unroll
        for (int n = 0; n < 4; n++) {
            int sn = s + offs[n];
            ok[n] = (sn >= 0 && sn < S_);
            float acc = 0.0f;
            if (ok[n]) {
                uint4 kraw = *(const uint4*)(g_qkv + (size_t)(r + offs[n]) * 768 + 256 + 8 * lane);
                const __half2* k2 = (const __half2*)&kraw;
#pragma unroll
                for (int j = 0; j < 4; j++) {
                    float2 qf = __half22float2(q2[j]);
                    float2 kf = __half22float2(k2[j]);
                    acc = fmaf(qf.x, kf.x, acc);
                    acc = fmaf(qf.y, kf.y, acc);
                }
            }
            d[n] = acc;
        }
#pragma unroll
        for (int n = 0; n < 4; n++) {
            d[n] += __shfl_xor_sync(0xffffffffu, d[n], 1);
            d[n] += __shfl_xor_sync(0xffffffffu, d[n], 2);
            d[n] *= scale;
        }
        float mx = fmaxf(fmaxf(d[0], d[1]), fmaxf(d[2], d[3]));
        float e[4], sum = 0.0f;
#pragma unroll
        for (int n = 0; n < 4; n++) { e[n] = __expf(d[n] - mx); sum += e[n]; }
        float inv = 1.0f / sum;
        float cx[8] = {0, 0, 0, 0, 0, 0, 0, 0};
#pragma unroll
        for (int n = 0; n < 4; n++) {
            if (ok[n]) {
                float a = e[n] * inv;
                uint4 vraw = *(const uint4*)(g_qkv + (size_t)(r + offs[n]) * 768 + 512 + 8 * lane);
                const __half2* v2 = (const __half2*)&vraw;
#pragma unroll
                for (int j = 0; j < 4; j++) {
                    float2 vf = __half22float2(v2[j]);
                    cx[2 * j]     = fmaf(a, vf.x, cx[2 * j]);
                    cx[2 * j + 1] = fmaf(a, vf.y, cx[2 * j + 1]);
                }
            }
        }
        uint4 oraw;
        __half2* o2 = (__half2*)&oraw;
#pragma unroll
        for (int j = 0; j < 4; j++) {
            o2[j].x = __float2half(cx[2 * j]);
            o2[j].y = __float2half(cx[2 * j + 1]);
        }
        __half* ctx = (r < R_) ? (g_ctx_e + (size_t)r * H_) : (g_ctx_d + (size_t)(r - R_) * H_);
        *(uint4*)(ctx + 8 * lane) = oraw;
    }
}

// ---------------- output GEMV + assembly ----------------
__device__ __forceinline__ void out_phase(const __half* __restrict__ dh,
                                          const float* __restrict__ W,
                                          const float* __restrict__ bb,
                                          const float* __restrict__ input,
                                          float* __restrict__ dout, int t) {
    const int w0 = blockIdx.x * WPB + (threadIdx.x >> 5);
    const int lane = threadIdx.x & 31;
    for (int r = w0; r < R_; r += NB * WPB) {
        int b = r >> 7, s = r & (S_ - 1);
        float s0 = 0.0f, s1 = 0.0f;
#pragma unroll
        for (int j = 0; j < H_; j += 32) {
            float wv = W[j + lane];
            s0 = fmaf(__half2float(dh[(size_t)r * H_ + j + lane]), wv, s0);
            if (s > 0) s1 = fmaf(__half2float(dh[(size_t)(r - 1) * H_ + j + lane]), wv, s1);
        }
        s0 = warp_sum(s0);
        s1 = warp_sum(s1);
        if (lane == 0) {
            float o  = s0 + bb[0];
            float In = (s > 0) ? (s1 + bb[0])
                               : input[(((size_t)b * T_ + (t + 1)) * S_ + 0) * F_ + 1];
            float num = input[(((size_t)b * T_ + t) * S_ + s) * F_ + 2] + In - o;
            size_t base = (((size_t)b * (T_ - TP_ - 1) + (t - TP_)) * S_ + s) * 3;
            dout[base + 0] = o;
            dout[base + 1] = In;
            dout[base + 2] = num;
        }
    }
}

// ---------------- persistent kernel ----------------
__global__ __launch_bounds__(NT, 1)
void persist_kernel(const float* __restrict__ input, const float* __restrict__ embb,
                    const float* __restrict__ outW, const float* __restrict__ outb,
                    float* __restrict__ dout)
{
    extern __shared__ char smp[];
    uint32_t sb = s2u(smp);
    if (threadIdx.x == 0) {
#pragma unroll
        for (int s = 0; s < NSTAGE; s++) {
            MBAR_INIT(sb + MBAR_OFF + s * 16, NT);          // full: all threads cp-arrive
            MBAR_INIT(sb + MBAR_OFF + 128 + s * 16, WPB);   // empty: one arrive per warp
        }
    }
    __syncthreads();
    int gbase = 0;

    int ce = 0, cd = 0;
    gemm_tc<0, 0, false, false>(smp, sb, gbase, g_eh[0], nullptr, nullptr,
                                g_We_t, nullptr, nullptr, g_qkv, nullptr, nullptr,
                                16, 6, 768, 256, 8, 0, nullptr, 0);
    gsync();
    attn_phase();   // dec half reads stale qkv pre-step-0 but g_ctx_d unused until G4 after refresh
    gsync();

    for (int t = 0; t < T_ - 1; t++) {
        // G1: enc gates + LSTM (K=512 + rank-3 x) -> eh[ce^1], ec
        gemm_tc<1, 2, true, false>(smp, sb, gbase, nullptr, g_eh[ce], g_ctx_e,
                                   g_Wge_t, nullptr, g_bge, g_eh[ce ^ 1], g_ec, g_ec,
                                   16, 8, 256, 512, 16, t, input, 0);
        gsync();
        // G2: QKV dual; emb->code on offset blocks
        gemm_tc<3, 0, false, false>(smp, sb, gbase, nullptr, g_eh[ce ^ 1], g_dh[cd],
                                    g_We_t, g_Wd_t, nullptr, g_qkv, nullptr, nullptr,
                                    32, 6, 768, 256, 8, 0, nullptr, 0);
        gemm_tc<0, 1, false, false>(smp, sb, gbase, g_eh[ce ^ 1], nullptr, nullptr,
                                    g_embT, nullptr, embb, g_code, nullptr, nullptr,
                                    16, 2, 256, 256, 8, 0, nullptr, 44);
        gsync();
        // G3: attention (enc ctx for t+1, dec ctx for t); out(t-1)
        attn_phase();
        if (t - 1 >= TP_) out_phase(g_dh[cd], outW, outb, input, dout, t - 1);
        gsync();
        // G4: dec gates + LSTM (K=768, c_in = dh(t-1) half) -> dh[cd^1]
        gemm_tc<2, 2, false, true>(smp, sb, gbase, g_code, g_dh[cd], g_ctx_d,
                                   g_Wgd_t, nullptr, g_bgd, g_dh[cd ^ 1], g_dh[cd], nullptr,
                                   16, 8, 256, 768, 24, 0, nullptr, 0);
        gsync();
        ce ^= 1; cd ^= 1;
    }
    out_phase(g_dh[cd], outW, outb, input, dout, T_ - 2);
}

// ---------------- single prep kernel ----------------
__global__ void prep_all_kernel(const float* __restrict__ eWq, const float* __restrict__ eWk,
                                const float* __restrict__ eWv, const float* __restrict__ eWg,
                                const float* __restrict__ ebg, const float* __restrict__ dWq,
                                const float* __restrict__ dWk, const float* __restrict__ dWv,
                                const float* __restrict__ dWg, const float* __restrict__ dbg,
                                const float* __restrict__ embW) {
    int idx = blockIdx.x * blockDim.x + threadIdx.x;
    if (idx < R_ * H_) {
        g_eh[0][idx] = __float2half(0.0f);
        g_dh[0][idx] = __float2half(0.0f);
        g_ec[idx] = 0.0f;
    }
    if (idx < 768 * 256) {
        int n = idx >> 8, k = idx & 255;
        const float* se = (n < 256) ? eWq : ((n < 512) ? eWk : eWv);
        const float* sd = (n < 256) ? dWq : ((n < 512) ? dWk : dWv);
        g_We_t[idx] = __float2half(se[(size_t)k * 256 + (n & 255)]);
        g_Wd_t[idx] = __float2half(sd[(size_t)k * 256 + (n & 255)]);
    }
    if (idx < 1024 * 512) {
        int n = idx >> 9, k2 = idx & 511;
        int gcol = (n & 3) * 256 + (n >> 2);
        g_Wge_t[idx] = __float2half(eWg[(size_t)(3 + k2) * 1024 + gcol]);
        if (k2 < 3) g_Wx[k2 * 1024 + n] = eWg[(size_t)k2 * 1024 + gcol];
        if (k2 == 0) g_bge[n] = ebg[gcol];
    }
    if (idx < 1024 * 768) {
        int n = idx / 768, k2 = idx - n * 768;
        int gcol = (n & 3) * 256 + (n >> 2);
        g_Wgd_t[idx] = __float2half(dWg[(size_t)k2 * 1024 + gcol]);
        if (k2 == 0) g_bgd[n] = dbg[gcol];
    }
    if (idx < 256 * 256) {
        int n = idx >> 8, k = idx & 255;
        g_embT[idx] = __float2half(embW[(size_t)k * 256 + n]);
    }
}

// ---------------- host ----------------
extern "C" void kernel_launch(void* const* d_in, const int* in_sizes, int n_in,
                              void* d_out, int out_size) {
    const float* input = (const float*)d_in[0];
    const float* eWq = (const float*)d_in[1];
    const float* eWk = (const float*)d_in[2];
    const float* eWv = (const float*)d_in[3];
    const float* eWg = (const float*)d_in[4];
    const float* ebg = (const float*)d_in[5];
    const float* dWq = (const float*)d_in[6];
    const float* dWk = (const float*)d_in[7];
    const float* dWv = (const float*)d_in[8];
    const float* dWg = (const float*)d_in[9];
    const float* dbg = (const float*)d_in[10];
    const float* embW = (const float*)d_in[11];
    const float* embb = (const float*)d_in[12];
    const float* outW = (const float*)d_in[13];
    const float* outb = (const float*)d_in[14];
    float* dout = (float*)d_out;

    static int s_init = 0;
    if (!s_init) {
        cudaFuncSetAttribute(persist_kernel, cudaFuncAttributeMaxDynamicSharedMemorySize, SMEM_SZ);
        s_init = 1;
    }

    prep_all_kernel<<<(1024 * 768 + 255) / 256, 256>>>(eWq, eWk, eWv, eWg, ebg,
                                                       dWq, dWk, dWv, dWg, dbg, embW);
    persist_kernel<<<NB, NT, SMEM_SZ>>>(input, embb, outW, outb, dout);
}

// round 14
// speedup vs baseline: 3.0625x; 1.0662x over previous
#include <cuda_runtime.h>
#include <cuda_fp16.h>
#include <cstdint>
#include <math.h>

#define B_  16
#define T_  32
#define S_  128
#define F_  3
#define H_  256
#define NH_ 8
#define DK_ 32
#define TP_ 4
#define R_  2048
#define NB  148        // one persistent block per SM
#define NT  512        // threads per block (16 warps)
#define WPB 16

// ---------------- device scratch ----------------
__device__ __half g_eh[2][R_*H_];
__device__ float  g_ec[R_*H_];
__device__ __half g_dh[2][R_*H_];
__device__ __half g_qkv[2*R_*768];     // enc rows [0,2048), dec [2048,4096)
__device__ __half g_ctx_e[R_*H_];
__device__ __half g_ctx_d[R_*H_];
__device__ __half g_code[R_*H_];
__device__ __half g_We_t[768*256];     // [n][k]
__device__ __half g_Wd_t[768*256];
__device__ __half g_Wge_t[1024*512];   // enc gates rows 3..514, cols permuted 4h+g
__device__ __half g_Wgd_t[1024*768];
__device__ __half g_embT[256*256];
__device__ float  g_Wx[3*1024];        // enc gate x-rows (fp32), permuted cols
__device__ float  g_bge[1024];
__device__ float  g_bgd[1024];
__device__ unsigned g_bar_count;
__device__ unsigned g_bar_epoch;

// ---------------- smem layout: 8 cp.async stages + mbarriers + bias/wx ----------------
#define NSTAGE    8
#define STAGE_B   20480
#define MBAR_OFF  (NSTAGE*STAGE_B)         // full[8] @ +s*16, empty[8] @ +128+s*16
#define BIAS_OFF  (MBAR_OFF + 256)
#define WX_OFF    (BIAS_OFF + 512)
#define SMEM_SZ   (WX_OFF + 1536)          // 166144

__device__ __forceinline__ uint32_t s2u(const void* p) {
    uint32_t a;
    asm("{ .reg .u64 t; cvta.to.shared.u64 t, %1; cvt.u32.u64 %0, t; }" : "=r"(a) : "l"(p));
    return a;
}
#define CPA(dst, src) asm volatile("cp.async.cg.shared.global [%0], [%1], 16;" :: "r"(dst), "l"(src) : "memory")
#define CP_ARRIVE(a)  asm volatile("cp.async.mbarrier.arrive.noinc.shared.b64 [%0];" :: "r"(a) : "memory")
#define MBAR_INIT(a, c) asm volatile("mbarrier.init.shared.b64 [%0], %1;" :: "r"(a), "r"(c) : "memory")
#define MBAR_ARRIVE(a)  asm volatile("mbarrier.arrive.shared.b64 _, [%0];" :: "r"(a) : "memory")
#define MBAR_WAITP(a, par) do { \
    uint32_t _m = (a), _p = (par), _d; \
    asm volatile("{ .reg .pred p; mbarrier.try_wait.parity.acquire.cta.shared::cta.b64 p, [%1], %2; selp.b32 %0,1,0,p; }" \
        : "=r"(_d) : "r"(_m), "r"(_p) : "memory"); \
    if (!_d) { \
        asm volatile("{ .reg .pred P1; WL_%=: mbarrier.try_wait.parity.acquire.cta.shared::cta.b64 P1, [%0], %1, 0x989680;" \
            " @P1 bra.uni WD_%=; bra.uni WL_%=; WD_%=: }" :: "r"(_m), "r"(_p) : "memory"); \
    } } while (0)
#define LDSM4(r0, r1, r2, r3, a) \
    asm volatile("ldmatrix.sync.aligned.m8n8.x4.shared.b16 {%0,%1,%2,%3}, [%4];" \
        : "=r"(r0), "=r"(r1), "=r"(r2), "=r"(r3) : "r"(a))

__device__ __forceinline__ float sigmoidf_(float x) { return 1.0f / (1.0f + __expf(-x)); }
__device__ __forceinline__ float warp_sum(float v) {
    v += __shfl_xor_sync(0xffffffffu, v, 16);
    v += __shfl_xor_sync(0xffffffffu, v, 8);
    v += __shfl_xor_sync(0xffffffffu, v, 4);
    v += __shfl_xor_sync(0xffffffffu, v, 2);
    v += __shfl_xor_sync(0xffffffffu, v, 1);
    return v;
}

__device__ __forceinline__ void mma_f16(float* d, const uint32_t* a, const uint32_t* b) {
    asm volatile(
        "mma.sync.aligned.m16n8k16.row.col.f32.f16.f16.f32 "
        "{%0,%1,%2,%3}, {%4,%5,%6,%7}, {%8,%9}, {%0,%1,%2,%3};\n"
        : "+f"(d[0]), "+f"(d[1]), "+f"(d[2]), "+f"(d[3])
        : "r"(a[0]), "r"(a[1]), "r"(a[2]), "r"(a[3]), "r"(b[0]), "r"(b[1]));
}

// ---------------- grid barrier ----------------
__device__ __forceinline__ void gsync() {
    __syncthreads();
    if (threadIdx.x == 0) {
        unsigned e;
        asm volatile("ld.acquire.gpu.u32 %0, [%1];" : "=r"(e) : "l"(&g_bar_epoch) : "memory");
        unsigned old;
        asm volatile("atom.add.acq_rel.gpu.u32 %0, [%1], %2;"
                     : "=r"(old) : "l"(&g_bar_count), "r"(1u) : "memory");
        if (old == NB - 1) {
            g_bar_count = 0;
            unsigned dummy;
            asm volatile("atom.add.release.gpu.u32 %0, [%1], %2;"
                         : "=r"(dummy) : "l"(&g_bar_epoch), "r"(1u) : "memory");
        } else {
            unsigned cur;
            do {
                __nanosleep(32);
                asm volatile("ld.acquire.gpu.u32 %0, [%1];" : "=r"(cur) : "l"(&g_bar_epoch) : "memory");
            } while (cur == e);
        }
    }
    __syncthreads();
}

// ---------------- stage loader (cp.async): one A + one B 16B xfer per thread ----------------
// AM 0: A0 plain [row][256]. AM 1: enc gates [eh|ctx] K=512. AM 2: dec gates [code|dh|ctx] K=768.
template<int AM>
__device__ __forceinline__ void load_stage(uint32_t sb,
    const __half* __restrict__ A0, const __half* __restrict__ A1, const __half* __restrict__ A2,
    const __half* __restrict__ Bt, int bm, int bn, int KB, int kt, int slot)
{
    const int tid = threadIdx.x;
    uint32_t Ab = sb + (uint32_t)slot * STAGE_B;
    uint32_t Bb = Ab + 10240;
    const int gk0 = kt * 32;
    int m = tid >> 2, c4 = tid & 3;
    int gk = gk0 + c4 * 8;
    int rowm = bm + m;
    const __half* ap;
    if (AM == 0)      ap = A0 + (size_t)rowm * 256 + gk;
    else if (AM == 1) ap = (gk < 256) ? (A1 + (size_t)rowm * 256 + gk)
                                      : (A2 + (size_t)rowm * 256 + gk - 256);
    else              ap = (gk < 256) ? (A0 + (size_t)rowm * 256 + gk)
                    : ((gk < 512) ? (A1 + (size_t)rowm * 256 + gk - 256)
                                  : (A2 + (size_t)rowm * 256 + gk - 512));
    CPA(Ab + (uint32_t)(m * 80 + c4 * 16), ap);
    CPA(Bb + (uint32_t)(m * 80 + c4 * 16), Bt + (size_t)(bn + m) * KB + gk);
}

// ---------------- fp16 tensor-core GEMM phase (mbarrier ring) ----------------
template<int AM, int EPI, bool XUPD, bool CIH>
__device__ void gemm_tc(char* smp, uint32_t sb, int& gbase,
    const __half* __restrict__ A0, const __half* __restrict__ A1, const __half* __restrict__ A2,
    const __half* __restrict__ B0,
    const float* __restrict__ bias, __half* __restrict__ C,
    const void* __restrict__ c_in, float* __restrict__ c_out,
    int Mtiles, int Ntiles, int NOUT, int KB, int nkt, int t,
    const float* __restrict__ input, int boff)
{
    const int tid = threadIdx.x, lane = tid & 31, warp = tid >> 5;
    const int wm = warp >> 2, wn = warp & 3;          // 4 x 4
    const int q = lane & 3, rsel = lane >> 2;
    const int tot = Mtiles * Ntiles;
    float* bias_s = (float*)(smp + BIAS_OFF);
    float* wx_s   = (float*)(smp + WX_OFF);
    const uint32_t sbm = sb + MBAR_OFF;
    const uint32_t offL = (uint32_t)((lane & 15) * 80 + (lane >> 4) * 16);

    for (int tile = (blockIdx.x + boff) % NB; tile < tot; tile += NB) {
        const int bm = (tile % Mtiles) * 128;
        const int bn = (tile / Mtiles) * 128;

        __syncthreads();   // prior tile epilogue done before bias/wx overwrite
        if (EPI >= 1) for (int i = tid; i < 128; i += NT) bias_s[i] = bias[bn + i];
        if (XUPD)     for (int i = tid; i < 384; i += NT) wx_s[i] = g_Wx[(i >> 7) * 1024 + bn + (i & 127)];

        float acc[2][4][4];
#pragma unroll
        for (int a = 0; a < 2; a++)
#pragma unroll
            for (int b = 0; b < 4; b++)
#pragma unroll
                for (int l = 0; l < 4; l++) acc[a][b][l] = 0.0f;

        // prologue: fill 4 stages (nkt >= 8 always)
#pragma unroll
        for (int s = 0; s < 4; s++) {
            int g = gbase + s;
            if (g >= NSTAGE) MBAR_WAITP(sbm + 128 + (g & 7) * 16, ((g >> 3) - 1) & 1);
            load_stage<AM>(sb, A0, A1, A2, B0, bm, bn, KB, s, g & 7);
            CP_ARRIVE(sbm + (g & 7) * 16);
        }

        for (int kt = 0; kt < nkt; kt++) {
            if (kt + 4 < nkt) {
                int g = gbase + kt + 4;
                if (g >= NSTAGE) MBAR_WAITP(sbm + 128 + (g & 7) * 16, ((g >> 3) - 1) & 1);
                load_stage<AM>(sb, A0, A1, A2, B0, bm, bn, KB, kt + 4, g & 7);
                CP_ARRIVE(sbm + (g & 7) * 16);
            }
            const int gc = gbase + kt;
            MBAR_WAITP(sbm + (gc & 7) * 16, (gc >> 3) & 1);

            uint32_t Ab = sb + (uint32_t)(gc & 7) * STAGE_B;
            uint32_t Bb = Ab + 10240;
#pragma unroll
            for (int st = 0; st < 2; st++) {        // two k16 steps per BK=32
                uint32_t a[2][4], b[2][4];
#pragma unroll
                for (int tm = 0; tm < 2; tm++)
                    LDSM4(a[tm][0], a[tm][1], a[tm][2], a[tm][3],
                          Ab + (uint32_t)((wm * 32 + tm * 16) * 80 + st * 32) + offL);
#pragma unroll
                for (int tp = 0; tp < 2; tp++)
                    LDSM4(b[tp][0], b[tp][1], b[tp][2], b[tp][3],
                          Bb + (uint32_t)((wn * 32 + tp * 16) * 80 + st * 32) + offL);
#pragma unroll
                for (int tm = 0; tm < 2; tm++)
#pragma unroll
                    for (int tn = 0; tn < 4; tn++) {
                        uint32_t bb[2] = { b[tn >> 1][tn & 1], b[tn >> 1][(tn & 1) + 2] };
                        mma_f16(acc[tm][tn], a[tm], bb);
                    }
            }
            if (lane == 0) MBAR_ARRIVE(sbm + 128 + (gc & 7) * 16);
        }
        gbase += nkt;

        // ---------------- epilogue ----------------
#pragma unroll
        for (int tm = 0; tm < 2; tm++)
#pragma unroll
            for (int tn = 0; tn < 4; tn++) {
                const int r0  = bm + wm * 32 + tm * 16 + rsel;
                const int cl  = wn * 32 + tn * 8 + 2 * q;     // local col (even)
                const int col = bn + cl;
                if (EPI == 0) {
                    __half2 h01, h23;
                    h01.x = __float2half(acc[tm][tn][0]); h01.y = __float2half(acc[tm][tn][1]);
                    h23.x = __float2half(acc[tm][tn][2]); h23.y = __float2half(acc[tm][tn][3]);
                    *(__half2*)(C + (size_t)r0 * NOUT + col)       = h01;
                    *(__half2*)(C + (size_t)(r0 + 8) * NOUT + col) = h23;
                } else if (EPI == 1) {
                    float b0 = bias_s[cl], b1 = bias_s[cl + 1];
                    __half2 h01, h23;
                    h01.x = __float2half(sigmoidf_(acc[tm][tn][0] + b0));
                    h01.y = __float2half(sigmoidf_(acc[tm][tn][1] + b1));
                    h23.x = __float2half(sigmoidf_(acc[tm][tn][2] + b0));
                    h23.y = __float2half(sigmoidf_(acc[tm][tn][3] + b1));
                    *(__half2*)(C + (size_t)r0 * NOUT + col)       = h01;
                    *(__half2*)(C + (size_t)(r0 + 8) * NOUT + col) = h23;
                } else {
                    float b0 = bias_s[cl], b1 = bias_s[cl + 1];
#pragma unroll
                    for (int half = 0; half < 2; half++) {
                        const int r = r0 + half * 8;
                        float v0 = acc[tm][tn][half * 2 + 0] + b0;
                        float v1 = acc[tm][tn][half * 2 + 1] + b1;
                        if (XUPD) {
                            int bb = r >> 7, s = r & (S_ - 1);
                            const float* xp = input + (((size_t)bb * T_ + t) * S_ + s) * F_;
                            float x0 = xp[0], x1 = xp[1], x2 = xp[2];
                            v0 += x0 * wx_s[cl]     + x1 * wx_s[128 + cl]     + x2 * wx_s[256 + cl];
                            v1 += x0 * wx_s[cl + 1] + x1 * wx_s[128 + cl + 1] + x2 * wx_s[256 + cl + 1];
                        }
                        float p0 = __shfl_xor_sync(0xffffffffu, v0, 1);
                        float p1 = __shfl_xor_sync(0xffffffffu, v1, 1);
                        if (!(q & 1)) {
                            int h = (bn + cl) >> 2;
                            float cprev = CIH ? __half2float(((const __half*)c_in)[(size_t)r * H_ + h])
                                              : ((const float*)c_in)[(size_t)r * H_ + h];
                            float cn = sigmoidf_(v1) * cprev + sigmoidf_(v0) * tanhf(p0);
                            float hn = sigmoidf_(p1) * tanhf(cn);
                            C[(size_t)r * H_ + h] = __float2half(hn);
                            if (c_out) c_out[(size_t)r * H_ + h] = cn;
                        }
                    }
                }
            }
    }
}

// ---------------- attention: one warp per row, all 8 heads; block subrange ----------------
// rowbase: 0 (enc -> g_ctx_e) or R_ (dec -> g_ctx_d). Blocks [b0, b0+nbk).
__device__ __forceinline__ void attn_range(int rowbase, int b0, int nbk) {
    const int w0 = (blockIdx.x - b0) * WPB + (threadIdx.x >> 5);
    const int lane = threadIdx.x & 31;
    const float scale = 0.17677669529663687f;   // 1/sqrt(32)
    __half* ctxb = (rowbase == 0) ? g_ctx_e : g_ctx_d;
    for (int ri = w0; ri < R_; ri += nbk * WPB) {
        int r = rowbase + ri;
        int s = ri & (S_ - 1);
        uint4 qraw = *(const uint4*)(g_qkv + (size_t)r * 768 + 8 * lane);
        const __half2* q2 = (const __half2*)&qraw;
        const int offs[4] = {2, 1, -1, -2};
        float d[4];
        bool ok[4];
#pragma unroll
        for (int n = 0; n < 4; n++) {
            int sn = s + offs[n];
            ok[n] = (sn >= 0 && sn < S_);
            float acc = 0.0f;
            if (ok[n]) {
                uint4 kraw = *(const uint4*)(g_qkv + (size_t)(r + offs[n]) * 768 + 256 + 8 * lane);
                const __half2* k2 = (const __half2*)&kraw;
#pragma unroll
                for (int j = 0; j < 4; j++) {
                    float2 qf = __half22float2(q2[j]);
                    float2 kf = __half22float2(k2[j]);
                    acc = fmaf(qf.x, kf.x, acc);
                    acc = fmaf(qf.y, kf.y, acc);
                }
            }
            d[n] = acc;
        }
#pragma unroll
        for (int n = 0; n < 4; n++) {
            d[n] += __shfl_xor_sync(0xffffffffu, d[n], 1);
            d[n] += __shfl_xor_sync(0xffffffffu, d[n], 2);
            d[n] *= scale;
        }
        float mx = fmaxf(fmaxf(d[0], d[1]), fmaxf(d[2], d[3]));
        float e[4], sum = 0.0f;
#pragma unroll
        for (int n = 0; n < 4; n++) { e[n] = __expf(d[n] - mx); sum += e[n]; }
        float inv = 1.0f / sum;
        float cx[8] = {0, 0, 0, 0, 0, 0, 0, 0};
#pragma unroll
        for (int n = 0; n < 4; n++) {
            if (ok[n]) {
                float a = e[n] * inv;
                uint4 vraw = *(const uint4*)(g_qkv + (size_t)(r + offs[n]) * 768 + 512 + 8 * lane);
                const __half2* v2 = (const __half2*)&vraw;
#pragma unroll
                for (int j = 0; j < 4; j++) {
                    float2 vf = __half22float2(v2[j]);
                    cx[2 * j]     = fmaf(a, vf.x, cx[2 * j]);
                    cx[2 * j + 1] = fmaf(a, vf.y, cx[2 * j + 1]);
                }
            }
        }
        uint4 oraw;
        __half2* o2 = (__half2*)&oraw;
#pragma unroll
        for (int j = 0; j < 4; j++) {
            o2[j].x = __float2half(cx[2 * j]);
            o2[j].y = __float2half(cx[2 * j + 1]);
        }
        *(uint4*)(ctxb + (size_t)ri * H_ + 8 * lane) = oraw;
    }
}

// ---------------- output GEMV + assembly; block subrange ----------------
__device__ __forceinline__ void out_range(const __half* __restrict__ dh,
                                          const float* __restrict__ W,
                                          const float* __restrict__ bb,
                                          const float* __restrict__ input,
                                          float* __restrict__ dout, int t,
                                          int b0, int nbk) {
    const int w0 = (blockIdx.x - b0) * WPB + (threadIdx.x >> 5);
    const int lane = threadIdx.x & 31;
    for (int r = w0; r < R_; r += nbk * WPB) {
        int b = r >> 7, s = r & (S_ - 1);
        float s0 = 0.0f, s1 = 0.0f;
#pragma unroll
        for (int j = 0; j < H_; j += 32) {
            float wv = W[j + lane];
            s0 = fmaf(__half2float(dh[(size_t)r * H_ + j + lane]), wv, s0);
            if (s > 0) s1 = fmaf(__half2float(dh[(size_t)(r - 1) * H_ + j + lane]), wv, s1);
        }
        s0 = warp_sum(s0);
        s1 = warp_sum(s1);
        if (lane == 0) {
            float o  = s0 + bb[0];
            float In = (s > 0) ? (s1 + bb[0])
                               : input[(((size_t)b * T_ + (t + 1)) * S_ + 0) * F_ + 1];
            float num = input[(((size_t)b * T_ + t) * S_ + s) * F_ + 2] + In - o;
            size_t base = (((size_t)b * (T_ - TP_ - 1) + (t - TP_)) * S_ + s) * 3;
            dout[base + 0] = o;
            dout[base + 1] = In;
            dout[base + 2] = num;
        }
    }
}

// ---------------- persistent kernel ----------------
// Per step t (4 barriers, every phase one wave):
//  G1: enc gates+LSTM -> eh(t), ec                                   (128 tiles)
//  G2: dec QKV (96 tiles, blk 0-95) + emb->code (32 tiles, blk 96-127)
//  G3: enc QKV(t+1) (96 tiles, blk 0-95); dec attn(t) + out(t-1) on blk 96-147
//  G4: dec gates+LSTM -> dh(t) (128 tiles); enc attn(t+1) on blk 128-147
__global__ __launch_bounds__(NT, 1)
void persist_kernel(const float* __restrict__ input, const float* __restrict__ embb,
                    const float* __restrict__ outW, const float* __restrict__ outb,
                    float* __restrict__ dout)
{
    extern __shared__ char smp[];
    uint32_t sb = s2u(smp);
    if (threadIdx.x == 0) {
#pragma unroll
        for (int s = 0; s < NSTAGE; s++) {
            MBAR_INIT(sb + MBAR_OFF + s * 16, NT);          // full: all threads cp-arrive
            MBAR_INIT(sb + MBAR_OFF + 128 + s * 16, WPB);   // empty: one arrive per warp
        }
    }
    __syncthreads();
    int gbase = 0;

    int ce = 0, cd = 0;
    // pre-loop: enc QKV(0) then enc attention(0)
    gemm_tc<0, 0, false, false>(smp, sb, gbase, g_eh[0], nullptr, nullptr,
                                g_We_t, nullptr, g_qkv, nullptr, nullptr,
                                16, 6, 768, 256, 8, 0, nullptr, 0);
    gsync();
    attn_range(0, 0, NB);
    gsync();

    for (int t = 0; t < T_ - 1; t++) {
        // G1: enc gates + LSTM (K=512 + rank-3 x) -> eh[ce^1], ec
        gemm_tc<1, 2, true, false>(smp, sb, gbase, nullptr, g_eh[ce], g_ctx_e,
                                   g_Wge_t, g_bge, g_eh[ce ^ 1], g_ec, g_ec,
                                   16, 8, 256, 512, 16, t, input, 0);
        gsync();
        // G2: dec QKV (blk 0-95) + emb->code (blk 96-127)
        gemm_tc<0, 0, false, false>(smp, sb, gbase, g_dh[cd], nullptr, nullptr,
                                    g_Wd_t, nullptr, g_qkv + (size_t)R_ * 768, nullptr, nullptr,
                                    16, 6, 768, 256, 8, 0, nullptr, 0);
        gemm_tc<0, 1, false, false>(smp, sb, gbase, g_eh[ce ^ 1], nullptr, nullptr,
                                    g_embT, embb, g_code, nullptr, nullptr,
                                    16, 2, 256, 256, 8, 0, nullptr, 52);
        gsync();
        // G3: enc QKV(t+1) (blk 0-95); dec attn + out(t-1) on blk 96-147
        gemm_tc<0, 0, false, false>(smp, sb, gbase, g_eh[ce ^ 1], nullptr, nullptr,
                                    g_We_t, nullptr, g_qkv, nullptr, nullptr,
                                    16, 6, 768, 256, 8, 0, nullptr, 0);
        if (blockIdx.x >= 96) {
            attn_range(R_, 96, 52);
            if (t - 1 >= TP_) out_range(g_dh[cd], outW, outb, input, dout, t - 1, 96, 52);
        }
        gsync();
        // G4: dec gates + LSTM (K=768) -> dh[cd^1]; enc attn(t+1) on blk 128-147
        gemm_tc<2, 2, false, true>(smp, sb, gbase, g_code, g_dh[cd], g_ctx_d,
                                   g_Wgd_t, g_bgd, g_dh[cd ^ 1], g_dh[cd], nullptr,
                                   16, 8, 256, 768, 24, 0, nullptr, 0);
        if (blockIdx.x >= 128) attn_range(0, 128, 20);
        gsync();
        ce ^= 1; cd ^= 1;
    }
    out_range(g_dh[cd], outW, outb, input, dout, T_ - 2, 0, NB);
}

// ---------------- single prep kernel ----------------
__global__ void prep_all_kernel(const float* __restrict__ eWq, const float* __restrict__ eWk,
                                const float* __restrict__ eWv, const float* __restrict__ eWg,
                                const float* __restrict__ ebg, const float* __restrict__ dWq,
                                const float* __restrict__ dWk, const float* __restrict__ dWv,
                                const float* __restrict__ dWg, const float* __restrict__ dbg,
                                const float* __restrict__ embW) {
    int idx = blockIdx.x * blockDim.x + threadIdx.x;
    if (idx < R_ * H_) {
        g_eh[0][idx] = __float2half(0.0f);
        g_dh[0][idx] = __float2half(0.0f);
        g_ec[idx] = 0.0f;
    }
    if (idx < 768 * 256) {
        int n = idx >> 8, k = idx & 255;
        const float* se = (n < 256) ? eWq : ((n < 512) ? eWk : eWv);
        const float* sd = (n < 256) ? dWq : ((n < 512) ? dWk : dWv);
        g_We_t[idx] = __float2half(se[(size_t)k * 256 + (n & 255)]);
        g_Wd_t[idx] = __float2half(sd[(size_t)k * 256 + (n & 255)]);
    }
    if (idx < 1024 * 512) {
        int n = idx >> 9, k2 = idx & 511;
        int gcol = (n & 3) * 256 + (n >> 2);
        g_Wge_t[idx] = __float2half(eWg[(size_t)(3 + k2) * 1024 + gcol]);
        if (k2 < 3) g_Wx[k2 * 1024 + n] = eWg[(size_t)k2 * 1024 + gcol];
        if (k2 == 0) g_bge[n] = ebg[gcol];
    }
    if (idx < 1024 * 768) {
        int n = idx / 768, k2 = idx - n * 768;
        int gcol = (n & 3) * 256 + (n >> 2);
        g_Wgd_t[idx] = __float2half(dWg[(size_t)k2 * 1024 + gcol]);
        if (k2 == 0) g_bgd[n] = dbg[gcol];
    }
    if (idx < 256 * 256) {
        int n = idx >> 8, k = idx & 255;
        g_embT[idx] = __float2half(embW[(size_t)k * 256 + n]);
    }
}

// ---------------- host ----------------
extern "C" void kernel_launch(void* const* d_in, const int* in_sizes, int n_in,
                              void* d_out, int out_size) {
    const float* input = (const float*)d_in[0];
    const float* eWq = (const float*)d_in[1];
    const float* eWk = (const float*)d_in[2];
    const float* eWv = (const float*)d_in[3];
    const float* eWg = (const float*)d_in[4];
    const float* ebg = (const float*)d_in[5];
    const float* dWq = (const float*)d_in[6];
    const float* dWk = (const float*)d_in[7];
    const float* dWv = (const float*)d_in[8];
    const float* dWg = (const float*)d_in[9];
    const float* dbg = (const float*)d_in[10];
    const float* embW = (const float*)d_in[11];
    const float* embb = (const float*)d_in[12];
    const float* outW = (const float*)d_in[13];
    const float* outb = (const float*)d_in[14];
    float* dout = (float*)d_out;

    static int s_init = 0;
    if (!s_init) {
        cudaFuncSetAttribute(persist_kernel, cudaFuncAttributeMaxDynamicSharedMemorySize, SMEM_SZ);
        s_init = 1;
    }

    prep_all_kernel<<<(1024 * 768 + 255) / 256, 256>>>(eWq, eWk, eWv, eWg, ebg,
                                                       dWq, dWk, dWv, dWg, dbg, embW);
    persist_kernel<<<NB, NT, SMEM_SZ>>>(input, embb, outW, outb, dout);
}

// round 15
// speedup vs baseline: 3.1932x; 1.0427x over previous
#include <cuda_runtime.h>
#include <cuda_fp16.h>
#include <cstdint>
#include <math.h>

#define B_  16
#define T_  32
#define S_  128
#define F_  3
#define H_  256
#define NH_ 8
#define DK_ 32
#define TP_ 4
#define R_  2048
#define NB  148        // one persistent block per SM
#define NT  512        // threads per block (16 warps)
#define WPB 16

// ---------------- device scratch ----------------
__device__ __half g_eh[2][R_*H_];
__device__ float  g_ec[R_*H_];
__device__ __half g_dh[2][R_*H_];
__device__ __half g_qkv[2*R_*768];     // enc rows [0,2048), dec [2048,4096)
__device__ __half g_ctx_e[R_*H_];
__device__ __half g_ctx_d[R_*H_];
__device__ __half g_code[R_*H_];
__device__ __half g_We_t[768*256];     // [n][k]
__device__ __half g_Wd_t[768*256];
__device__ __half g_Wge_t[1024*512];   // enc gates rows 3..514, cols permuted 4h+g
__device__ __half g_Wgd_t[1024*768];
__device__ __half g_embT[256*256];
__device__ float  g_Wx[3*1024];        // enc gate x-rows (fp32), permuted cols
__device__ float  g_bge[1024];
__device__ float  g_bgd[1024];
__device__ unsigned g_bar_count;
__device__ unsigned g_bar_epoch;

// ---------------- smem: 4 stages of BK=64 (A 128x64 + B 128x64, stride 144B) ----------------
#define NSTAGE    4
#define TILE_HB   18432                    // 128 rows * 144B
#define STAGE_B   (2*TILE_HB)              // 36864
#define MBAR_OFF  (NSTAGE*STAGE_B)         // 147456; full[4] @ +s*16, empty[4] @ +64+s*16
#define BIAS_OFF  (MBAR_OFF + 128)
#define WX_OFF    (BIAS_OFF + 512)
#define SMEM_SZ   (WX_OFF + 1536)          // 149632

__device__ __forceinline__ uint32_t s2u(const void* p) {
    uint32_t a;
    asm("{ .reg .u64 t; cvta.to.shared.u64 t, %1; cvt.u32.u64 %0, t; }" : "=r"(a) : "l"(p));
    return a;
}
#define CPA(dst, src) asm volatile("cp.async.cg.shared.global [%0], [%1], 16;" :: "r"(dst), "l"(src) : "memory")
#define CP_ARRIVE(a)  asm volatile("cp.async.mbarrier.arrive.noinc.shared.b64 [%0];" :: "r"(a) : "memory")
#define MBAR_INIT(a, c) asm volatile("mbarrier.init.shared.b64 [%0], %1;" :: "r"(a), "r"(c) : "memory")
#define MBAR_ARRIVE(a)  asm volatile("mbarrier.arrive.shared.b64 _, [%0];" :: "r"(a) : "memory")
#define MBAR_WAITP(a, par) do { \
    uint32_t _m = (a), _p = (par), _d; \
    asm volatile("{ .reg .pred p; mbarrier.try_wait.parity.acquire.cta.shared::cta.b64 p, [%1], %2; selp.b32 %0,1,0,p; }" \
        : "=r"(_d) : "r"(_m), "r"(_p) : "memory"); \
    if (!_d) { \
        asm volatile("{ .reg .pred P1; WL_%=: mbarrier.try_wait.parity.acquire.cta.shared::cta.b64 P1, [%0], %1, 0x989680;" \
            " @P1 bra.uni WD_%=; bra.uni WL_%=; WD_%=: }" :: "r"(_m), "r"(_p) : "memory"); \
    } } while (0)
#define LDSM4(r0, r1, r2, r3, a) \
    asm volatile("ldmatrix.sync.aligned.m8n8.x4.shared.b16 {%0,%1,%2,%3}, [%4];" \
        : "=r"(r0), "=r"(r1), "=r"(r2), "=r"(r3) : "r"(a))

__device__ __forceinline__ float sigmoidf_(float x) { return 1.0f / (1.0f + __expf(-x)); }
__device__ __forceinline__ float warp_sum(float v) {
    v += __shfl_xor_sync(0xffffffffu, v, 16);
    v += __shfl_xor_sync(0xffffffffu, v, 8);
    v += __shfl_xor_sync(0xffffffffu, v, 4);
    v += __shfl_xor_sync(0xffffffffu, v, 2);
    v += __shfl_xor_sync(0xffffffffu, v, 1);
    return v;
}

__device__ __forceinline__ void mma_f16(float* d, const uint32_t* a, const uint32_t* b) {
    asm volatile(
        "mma.sync.aligned.m16n8k16.row.col.f32.f16.f16.f32 "
        "{%0,%1,%2,%3}, {%4,%5,%6,%7}, {%8,%9}, {%0,%1,%2,%3};\n"
        : "+f"(d[0]), "+f"(d[1]), "+f"(d[2]), "+f"(d[3])
        : "r"(a[0]), "r"(a[1]), "r"(a[2]), "r"(a[3]), "r"(b[0]), "r"(b[1]));
}

// ---------------- grid barrier ----------------
__device__ __forceinline__ void gsync() {
    __syncthreads();
    if (threadIdx.x == 0) {
        unsigned e;
        asm volatile("ld.acquire.gpu.u32 %0, [%1];" : "=r"(e) : "l"(&g_bar_epoch) : "memory");
        unsigned old;
        asm volatile("atom.add.acq_rel.gpu.u32 %0, [%1], %2;"
                     : "=r"(old) : "l"(&g_bar_count), "r"(1u) : "memory");
        if (old == NB - 1) {
            g_bar_count = 0;
            unsigned dummy;
            asm volatile("atom.add.release.gpu.u32 %0, [%1], %2;"
                         : "=r"(dummy) : "l"(&g_bar_epoch), "r"(1u) : "memory");
        } else {
            unsigned cur;
            do {
                __nanosleep(32);
                asm volatile("ld.acquire.gpu.u32 %0, [%1];" : "=r"(cur) : "l"(&g_bar_epoch) : "memory");
            } while (cur == e);
        }
    }
    __syncthreads();
}

// ---------------- stage loader (cp.async): 2 A + 2 B 16B xfers per thread, BK=64 ----------------
// AM 0: A0 plain [row][256]. AM 1: enc gates [eh|ctx] K=512. AM 2: dec gates [code|dh|ctx] K=768.
// 64-col chunks never straddle 256-col segment boundaries.
template<int AM>
__device__ __forceinline__ void load_stage(uint32_t sb,
    const __half* __restrict__ A0, const __half* __restrict__ A1, const __half* __restrict__ A2,
    const __half* __restrict__ Bt, int bm, int bn, int KB, int kt, int slot)
{
    const int tid = threadIdx.x;
    uint32_t Ab = sb + (uint32_t)slot * STAGE_B;
    uint32_t Bb = Ab + TILE_HB;
    const int gk0 = kt * 64;
#pragma unroll
    for (int i = 0; i < 2; i++) {
        int idx = tid + i * NT;
        int m = idx >> 3, g8 = idx & 7;
        int gk = gk0 + g8 * 8;
        const __half* ap;
        if (AM == 0)      ap = A0 + (size_t)(bm + m) * 256 + gk;
        else if (AM == 1) ap = (gk < 256) ? (A1 + (size_t)(bm + m) * 256 + gk)
                                          : (A2 + (size_t)(bm + m) * 256 + gk - 256);
        else              ap = (gk < 256) ? (A0 + (size_t)(bm + m) * 256 + gk)
                        : ((gk < 512) ? (A1 + (size_t)(bm + m) * 256 + gk - 256)
                                      : (A2 + (size_t)(bm + m) * 256 + gk - 512));
        CPA(Ab + (uint32_t)(m * 144 + g8 * 16), ap);
        CPA(Bb + (uint32_t)(m * 144 + g8 * 16), Bt + (size_t)(bn + m) * KB + gk);
    }
}

// ---------------- fp16 tensor-core GEMM phase (mbarrier ring, BK=64) ----------------
template<int AM, int EPI, bool XUPD, bool CIH>
__device__ void gemm_tc(char* smp, uint32_t sb, int& gbase,
    const __half* __restrict__ A0, const __half* __restrict__ A1, const __half* __restrict__ A2,
    const __half* __restrict__ B0,
    const float* __restrict__ bias, __half* __restrict__ C,
    const void* __restrict__ c_in, float* __restrict__ c_out,
    int Mtiles, int Ntiles, int NOUT, int KB, int nkt, int t,
    const float* __restrict__ input, int boff)
{
    const int tid = threadIdx.x, lane = tid & 31, warp = tid >> 5;
    const int wm = warp >> 2, wn = warp & 3;          // 4 x 4
    const int q = lane & 3, rsel = lane >> 2;
    const int tot = Mtiles * Ntiles;
    float* bias_s = (float*)(smp + BIAS_OFF);
    float* wx_s   = (float*)(smp + WX_OFF);
    const uint32_t sbm = sb + MBAR_OFF;
    const uint32_t offL = (uint32_t)((lane & 15) * 144 + (lane >> 4) * 16);
    const uint32_t aBase = (uint32_t)((wm * 32) * 144) + offL;
    const uint32_t bBase = (uint32_t)((wn * 32) * 144) + offL;

    for (int tile = (blockIdx.x + boff) % NB; tile < tot; tile += NB) {
        const int bm = (tile % Mtiles) * 128;
        const int bn = (tile / Mtiles) * 128;

        if (EPI >= 1 || XUPD) {
            __syncthreads();   // prior tile epilogue done before bias/wx overwrite
            if (EPI >= 1) for (int i = tid; i < 128; i += NT) bias_s[i] = bias[bn + i];
            if (XUPD)     for (int i = tid; i < 384; i += NT) wx_s[i] = g_Wx[(i >> 7) * 1024 + bn + (i & 127)];
        }

        float acc[2][4][4];
#pragma unroll
        for (int a = 0; a < 2; a++)
#pragma unroll
            for (int b = 0; b < 4; b++)
#pragma unroll
                for (int l = 0; l < 4; l++) acc[a][b][l] = 0.0f;

        // prologue: fill 2 stages (nkt >= 4 always)
#pragma unroll
        for (int s = 0; s < 2; s++) {
            int g = gbase + s;
            if (g >= NSTAGE) MBAR_WAITP(sbm + 64 + (g & 3) * 16, ((g >> 2) - 1) & 1);
            load_stage<AM>(sb, A0, A1, A2, B0, bm, bn, KB, s, g & 3);
            CP_ARRIVE(sbm + (g & 3) * 16);
        }

        for (int kt = 0; kt < nkt; kt++) {
            if (kt + 2 < nkt) {
                int g = gbase + kt + 2;
                if (g >= NSTAGE) MBAR_WAITP(sbm + 64 + (g & 3) * 16, ((g >> 2) - 1) & 1);
                load_stage<AM>(sb, A0, A1, A2, B0, bm, bn, KB, kt + 2, g & 3);
                CP_ARRIVE(sbm + (g & 3) * 16);
            }
            const int gc = gbase + kt;
            MBAR_WAITP(sbm + (gc & 3) * 16, (gc >> 2) & 1);

            uint32_t Ab = sb + (uint32_t)(gc & 3) * STAGE_B;
            uint32_t Bb = Ab + TILE_HB;
#pragma unroll
            for (int st = 0; st < 4; st++) {        // four k16 steps per BK=64
                uint32_t a[2][4], b[2][4];
#pragma unroll
                for (int tm = 0; tm < 2; tm++)
                    LDSM4(a[tm][0], a[tm][1], a[tm][2], a[tm][3],
                          Ab + aBase + (uint32_t)(tm * 16 * 144 + st * 32));
#pragma unroll
                for (int tp = 0; tp < 2; tp++)
                    LDSM4(b[tp][0], b[tp][1], b[tp][2], b[tp][3],
                          Bb + bBase + (uint32_t)(tp * 16 * 144 + st * 32));
#pragma unroll
                for (int tm = 0; tm < 2; tm++)
#pragma unroll
                    for (int tn = 0; tn < 4; tn++) {
                        uint32_t bb[2] = { b[tn >> 1][tn & 1], b[tn >> 1][(tn & 1) + 2] };
                        mma_f16(acc[tm][tn], a[tm], bb);
                    }
            }
            if (lane == 0) MBAR_ARRIVE(sbm + 64 + (gc & 3) * 16);
        }
        gbase += nkt;

        // ---------------- epilogue ----------------
#pragma unroll
        for (int tm = 0; tm < 2; tm++)
#pragma unroll
            for (int tn = 0; tn < 4; tn++) {
                const int r0  = bm + wm * 32 + tm * 16 + rsel;
                const int cl  = wn * 32 + tn * 8 + 2 * q;     // local col (even)
                const int col = bn + cl;
                if (EPI == 0) {
                    __half2 h01, h23;
                    h01.x = __float2half(acc[tm][tn][0]); h01.y = __float2half(acc[tm][tn][1]);
                    h23.x = __float2half(acc[tm][tn][2]); h23.y = __float2half(acc[tm][tn][3]);
                    *(__half2*)(C + (size_t)r0 * NOUT + col)       = h01;
                    *(__half2*)(C + (size_t)(r0 + 8) * NOUT + col) = h23;
                } else if (EPI == 1) {
                    float b0 = bias_s[cl], b1 = bias_s[cl + 1];
                    __half2 h01, h23;
                    h01.x = __float2half(sigmoidf_(acc[tm][tn][0] + b0));
                    h01.y = __float2half(sigmoidf_(acc[tm][tn][1] + b1));
                    h23.x = __float2half(sigmoidf_(acc[tm][tn][2] + b0));
                    h23.y = __float2half(sigmoidf_(acc[tm][tn][3] + b1));
                    *(__half2*)(C + (size_t)r0 * NOUT + col)       = h01;
                    *(__half2*)(C + (size_t)(r0 + 8) * NOUT + col) = h23;
                } else {
                    float b0 = bias_s[cl], b1 = bias_s[cl + 1];
#pragma unroll
                    for (int half = 0; half < 2; half++) {
                        const int r = r0 + half * 8;
                        float v0 = acc[tm][tn][half * 2 + 0] + b0;
                        float v1 = acc[tm][tn][half * 2 + 1] + b1;
                        if (XUPD) {
                            int bb = r >> 7, s = r & (S_ - 1);
                            const float* xp = input + (((size_t)bb * T_ + t) * S_ + s) * F_;
                            float x0 = xp[0], x1 = xp[1], x2 = xp[2];
                            v0 += x0 * wx_s[cl]     + x1 * wx_s[128 + cl]     + x2 * wx_s[256 + cl];
                            v1 += x0 * wx_s[cl + 1] + x1 * wx_s[128 + cl + 1] + x2 * wx_s[256 + cl + 1];
                        }
                        float p0 = __shfl_xor_sync(0xffffffffu, v0, 1);
                        float p1 = __shfl_xor_sync(0xffffffffu, v1, 1);
                        if (!(q & 1)) {
                            int h = (bn + cl) >> 2;
                            float cprev = CIH ? __half2float(((const __half*)c_in)[(size_t)r * H_ + h])
                                              : ((const float*)c_in)[(size_t)r * H_ + h];
                            float cn = sigmoidf_(v1) * cprev + sigmoidf_(v0) * tanhf(p0);
                            float hn = sigmoidf_(p1) * tanhf(cn);
                            C[(size_t)r * H_ + h] = __float2half(hn);
                            if (c_out) c_out[(size_t)r * H_ + h] = cn;
                        }
                    }
                }
            }
    }
}

// ---------------- attention: one warp per row, all 8 heads; block subrange ----------------
__device__ __forceinline__ void attn_range(int rowbase, int b0, int nbk) {
    const int w0 = (blockIdx.x - b0) * WPB + (threadIdx.x >> 5);
    const int lane = threadIdx.x & 31;
    const float scale = 0.17677669529663687f;   // 1/sqrt(32)
    __half* ctxb = (rowbase == 0) ? g_ctx_e : g_ctx_d;
    for (int ri = w0; ri < R_; ri += nbk * WPB) {
        int r = rowbase + ri;
        int s = ri & (S_ - 1);
        uint4 qraw = *(const uint4*)(g_qkv + (size_t)r * 768 + 8 * lane);
        const __half2* q2 = (const __half2*)&qraw;
        const int offs[4] = {2, 1, -1, -2};
        float d[4];
        bool ok[4];
#pragma unroll
        for (int n = 0; n < 4; n++) {
            int sn = s + offs[n];
            ok[n] = (sn >= 0 && sn < S_);
            float acc = 0.0f;
            if (ok[n]) {
                uint4 kraw = *(const uint4*)(g_qkv + (size_t)(r + offs[n]) * 768 + 256 + 8 * lane);
                const __half2* k2 = (const __half2*)&kraw;
#pragma unroll
                for (int j = 0; j < 4; j++) {
                    float2 qf = __half22float2(q2[j]);
                    float2 kf = __half22float2(k2[j]);
                    acc = fmaf(qf.x, kf.x, acc);
                    acc = fmaf(qf.y, kf.y, acc);
                }
            }
            d[n] = acc;
        }
#pragma unroll
        for (int n = 0; n < 4; n++) {
            d[n] += __shfl_xor_sync(0xffffffffu, d[n], 1);
            d[n] += __shfl_xor_sync(0xffffffffu, d[n], 2);
            d[n] *= scale;
        }
        float mx = fmaxf(fmaxf(d[0], d[1]), fmaxf(d[2], d[3]));
        float e[4], sum = 0.0f;
#pragma unroll
        for (int n = 0; n < 4; n++) { e[n] = __expf(d[n] - mx); sum += e[n]; }
        float inv = 1.0f / sum;
        float cx[8] = {0, 0, 0, 0, 0, 0, 0, 0};
#pragma unroll
        for (int n = 0; n < 4; n++) {
            if (ok[n]) {
                float a = e[n] * inv;
                uint4 vraw = *(const uint4*)(g_qkv + (size_t)(r + offs[n]) * 768 + 512 + 8 * lane);
                const __half2* v2 = (const __half2*)&vraw;
#pragma unroll
                for (int j = 0; j < 4; j++) {
                    float2 vf = __half22float2(v2[j]);
                    cx[2 * j]     = fmaf(a, vf.x, cx[2 * j]);
                    cx[2 * j + 1] = fmaf(a, vf.y, cx[2 * j + 1]);
                }
            }
        }
        uint4 oraw;
        __half2* o2 = (__half2*)&oraw;
#pragma unroll
        for (int j = 0; j < 4; j++) {
            o2[j].x = __float2half(cx[2 * j]);
            o2[j].y = __float2half(cx[2 * j + 1]);
        }
        *(uint4*)(ctxb + (size_t)ri * H_ + 8 * lane) = oraw;
    }
}

// ---------------- output GEMV + assembly; block subrange ----------------
__device__ __forceinline__ void out_range(const __half* __restrict__ dh,
                                          const float* __restrict__ W,
                                          const float* __restrict__ bb,
                                          const float* __restrict__ input,
                                          float* __restrict__ dout, int t,
                                          int b0, int nbk) {
    const int w0 = (blockIdx.x - b0) * WPB + (threadIdx.x >> 5);
    const int lane = threadIdx.x & 31;
    for (int r = w0; r < R_; r += nbk * WPB) {
        int b = r >> 7, s = r & (S_ - 1);
        float s0 = 0.0f, s1 = 0.0f;
#pragma unroll
        for (int j = 0; j < H_; j += 32) {
            float wv = W[j + lane];
            s0 = fmaf(__half2float(dh[(size_t)r * H_ + j + lane]), wv, s0);
            if (s > 0) s1 = fmaf(__half2float(dh[(size_t)(r - 1) * H_ + j + lane]), wv, s1);
        }
        s0 = warp_sum(s0);
        s1 = warp_sum(s1);
        if (lane == 0) {
            float o  = s0 + bb[0];
            float In = (s > 0) ? (s1 + bb[0])
                               : input[(((size_t)b * T_ + (t + 1)) * S_ + 0) * F_ + 1];
            float num = input[(((size_t)b * T_ + t) * S_ + s) * F_ + 2] + In - o;
            size_t base = (((size_t)b * (T_ - TP_ - 1) + (t - TP_)) * S_ + s) * 3;
            dout[base + 0] = o;
            dout[base + 1] = In;
            dout[base + 2] = num;
        }
    }
}

// ---------------- persistent kernel ----------------
// Per step t (4 barriers, every phase one wave):
//  G1: enc gates+LSTM -> eh(t), ec                                   (128 tiles)
//  G2: dec QKV (96 tiles, blk 0-95) + emb->code (32 tiles, blk 96-127)
//  G3: enc QKV(t+1) (96 tiles, blk 0-95); dec attn(t) + out(t-1) on blk 96-147
//  G4: dec gates+LSTM -> dh(t) (128 tiles); enc attn(t+1) on blk 128-147
__global__ __launch_bounds__(NT, 1)
void persist_kernel(const float* __restrict__ input, const float* __restrict__ embb,
                    const float* __restrict__ outW, const float* __restrict__ outb,
                    float* __restrict__ dout)
{
    extern __shared__ char smp[];
    uint32_t sb = s2u(smp);
    if (threadIdx.x == 0) {
#pragma unroll
        for (int s = 0; s < NSTAGE; s++) {
            MBAR_INIT(sb + MBAR_OFF + s * 16, NT);         // full: all threads cp-arrive
            MBAR_INIT(sb + MBAR_OFF + 64 + s * 16, WPB);   // empty: one arrive per warp
        }
    }
    __syncthreads();
    int gbase = 0;

    int ce = 0, cd = 0;
    // pre-loop: enc QKV(0) then enc attention(0)
    gemm_tc<0, 0, false, false>(smp, sb, gbase, g_eh[0], nullptr, nullptr,
                                g_We_t, nullptr, g_qkv, nullptr, nullptr,
                                16, 6, 768, 256, 4, 0, nullptr, 0);
    gsync();
    attn_range(0, 0, NB);
    gsync();

    for (int t = 0; t < T_ - 1; t++) {
        // G1: enc gates + LSTM (K=512 + rank-3 x) -> eh[ce^1], ec
        gemm_tc<1, 2, true, false>(smp, sb, gbase, nullptr, g_eh[ce], g_ctx_e,
                                   g_Wge_t, g_bge, g_eh[ce ^ 1], g_ec, g_ec,
                                   16, 8, 256, 512, 8, t, input, 0);
        gsync();
        // G2: dec QKV (blk 0-95) + emb->code (blk 96-127)
        gemm_tc<0, 0, false, false>(smp, sb, gbase, g_dh[cd], nullptr, nullptr,
                                    g_Wd_t, nullptr, g_qkv + (size_t)R_ * 768, nullptr, nullptr,
                                    16, 6, 768, 256, 4, 0, nullptr, 0);
        gemm_tc<0, 1, false, false>(smp, sb, gbase, g_eh[ce ^ 1], nullptr, nullptr,
                                    g_embT, embb, g_code, nullptr, nullptr,
                                    16, 2, 256, 256, 4, 0, nullptr, 52);
        gsync();
        // G3: enc QKV(t+1) (blk 0-95); dec attn + out(t-1) on blk 96-147
        gemm_tc<0, 0, false, false>(smp, sb, gbase, g_eh[ce ^ 1], nullptr, nullptr,
                                    g_We_t, nullptr, g_qkv, nullptr, nullptr,
                                    16, 6, 768, 256, 4, 0, nullptr, 0);
        if (blockIdx.x >= 96) {
            attn_range(R_, 96, 52);
            if (t - 1 >= TP_) out_range(g_dh[cd], outW, outb, input, dout, t - 1, 96, 52);
        }
        gsync();
        // G4: dec gates + LSTM (K=768) -> dh[cd^1]; enc attn(t+1) on blk 128-147
        gemm_tc<2, 2, false, true>(smp, sb, gbase, g_code, g_dh[cd], g_ctx_d,
                                   g_Wgd_t, g_bgd, g_dh[cd ^ 1], g_dh[cd], nullptr,
                                   16, 8, 256, 768, 12, 0, nullptr, 0);
        if (blockIdx.x >= 128) attn_range(0, 128, 20);
        gsync();
        ce ^= 1; cd ^= 1;
    }
    out_range(g_dh[cd], outW, outb, input, dout, T_ - 2, 0, NB);
}

// ---------------- single prep kernel ----------------
__global__ void prep_all_kernel(const float* __restrict__ eWq, const float* __restrict__ eWk,
                                const float* __restrict__ eWv, const float* __restrict__ eWg,
                                const float* __restrict__ ebg, const float* __restrict__ dWq,
                                const float* __restrict__ dWk, const float* __restrict__ dWv,
                                const float* __restrict__ dWg, const float* __restrict__ dbg,
                                const float* __restrict__ embW) {
    int idx = blockIdx.x * blockDim.x + threadIdx.x;
    if (idx < R_ * H_) {
        g_eh[0][idx] = __float2half(0.0f);
        g_dh[0][idx] = __float2half(0.0f);
        g_ec[idx] = 0.0f;
    }
    if (idx < 768 * 256) {
        int n = idx >> 8, k = idx & 255;
        const float* se = (n < 256) ? eWq : ((n < 512) ? eWk : eWv);
        const float* sd = (n < 256) ? dWq : ((n < 512) ? dWk : dWv);
        g_We_t[idx] = __float2half(se[(size_t)k * 256 + (n & 255)]);
        g_Wd_t[idx] = __float2half(sd[(size_t)k * 256 + (n & 255)]);
    }
    if (idx < 1024 * 512) {
        int n = idx >> 9, k2 = idx & 511;
        int gcol = (n & 3) * 256 + (n >> 2);
        g_Wge_t[idx] = __float2half(eWg[(size_t)(3 + k2) * 1024 + gcol]);
        if (k2 < 3) g_Wx[k2 * 1024 + n] = eWg[(size_t)k2 * 1024 + gcol];
        if (k2 == 0) g_bge[n] = ebg[gcol];
    }
    if (idx < 1024 * 768) {
        int n = idx / 768, k2 = idx - n * 768;
        int gcol = (n & 3) * 256 + (n >> 2);
        g_Wgd_t[idx] = __float2half(dWg[(size_t)k2 * 1024 + gcol]);
        if (k2 == 0) g_bgd[n] = dbg[gcol];
    }
    if (idx < 256 * 256) {
        int n = idx >> 8, k = idx & 255;
        g_embT[idx] = __float2half(embW[(size_t)k * 256 + n]);
    }
}

// ---------------- host ----------------
extern "C" void kernel_launch(void* const* d_in, const int* in_sizes, int n_in,
                              void* d_out, int out_size) {
    const float* input = (const float*)d_in[0];
    const float* eWq = (const float*)d_in[1];
    const float* eWk = (const float*)d_in[2];
    const float* eWv = (const float*)d_in[3];
    const float* eWg = (const float*)d_in[4];
    const float* ebg = (const float*)d_in[5];
    const float* dWq = (const float*)d_in[6];
    const float* dWk = (const float*)d_in[7];
    const float* dWv = (const float*)d_in[8];
    const float* dWg = (const float*)d_in[9];
    const float* dbg = (const float*)d_in[10];
    const float* embW = (const float*)d_in[11];
    const float* embb = (const float*)d_in[12];
    const float* outW = (const float*)d_in[13];
    const float* outb = (const float*)d_in[14];
    float* dout = (float*)d_out;

    static int s_init = 0;
    if (!s_init) {
        cudaFuncSetAttribute(persist_kernel, cudaFuncAttributeMaxDynamicSharedMemorySize, SMEM_SZ);
        s_init = 1;
    }

    prep_all_kernel<<<(1024 * 768 + 255) / 256, 256>>>(eWq, eWk, eWv, eWg, ebg,
                                                       dWq, dWk, dWv, dWg, dbg, embW);
    persist_kernel<<<NB, NT, SMEM_SZ>>>(input, embb, outW, outb, dout);
}

// round 17
// speedup vs baseline: 3.2888x; 1.0299x over previous
#include <cuda_runtime.h>
#include <cuda_fp16.h>
#include <cstdint>
#include <math.h>

#define B_  16
#define T_  32
#define S_  128
#define F_  3
#define H_  256
#define NH_ 8
#define DK_ 32
#define TP_ 4
#define R_  2048
#define NB  148        // one persistent block per SM
#define NT  512        // threads per block (16 warps)
#define WPB 16

// ---------------- device scratch ----------------
__device__ __half g_eh[2][R_*H_];
__device__ float  g_ec[R_*H_];
__device__ __half g_dh[2][R_*H_];
__device__ __half g_qkv[2*R_*768];     // enc rows [0,2048), dec [2048,4096)
__device__ __half g_ctx_e[R_*H_];
__device__ __half g_ctx_d[R_*H_];
__device__ __half g_code[R_*H_];
__device__ __half g_We_t[768*256];     // [n][k]
__device__ __half g_Wd_t[768*256];
__device__ __half g_Wge_t[1024*512];   // enc gates rows 3..514, cols permuted 4h+g
__device__ __half g_Wgd_t[1024*768];
__device__ __half g_embT[256*256];
__device__ float  g_Wx[3*1024];        // enc gate x-rows (fp32), permuted cols
__device__ float  g_bge[1024];
__device__ float  g_bgd[1024];
__device__ unsigned g_bar_count;
__device__ unsigned g_bar_epoch;

// ---------------- smem: 4 stages of BK=64 (A 128x64 + B 128x64, stride 144B) ----------------
#define NSTAGE    4
#define TILE_HB   18432                    // 128 rows * 144B
#define STAGE_B   (2*TILE_HB)              // 36864
#define MBAR_OFF  (NSTAGE*STAGE_B)         // 147456; full[4] @ +s*16, empty[4] @ +64+s*16
#define BIAS_OFF  (MBAR_OFF + 128)
#define WX_OFF    (BIAS_OFF + 512)
#define SMEM_SZ   (WX_OFF + 1536)          // 149632

__device__ __forceinline__ uint32_t s2u(const void* p) {
    uint32_t a;
    asm("{ .reg .u64 t; cvta.to.shared.u64 t, %1; cvt.u32.u64 %0, t; }" : "=r"(a) : "l"(p));
    return a;
}
#define CPA(dst, src) asm volatile("cp.async.cg.shared.global [%0], [%1], 16;" :: "r"(dst), "l"(src) : "memory")
#define CP_ARRIVE(a)  asm volatile("cp.async.mbarrier.arrive.noinc.shared.b64 [%0];" :: "r"(a) : "memory")
#define MBAR_INIT(a, c) asm volatile("mbarrier.init.shared.b64 [%0], %1;" :: "r"(a), "r"(c) : "memory")
#define MBAR_ARRIVE(a)  asm volatile("mbarrier.arrive.shared.b64 _, [%0];" :: "r"(a) : "memory")
#define MBAR_WAITP(a, par) do { \
    uint32_t _m = (a), _p = (par), _d; \
    asm volatile("{ .reg .pred p; mbarrier.try_wait.parity.acquire.cta.shared::cta.b64 p, [%1], %2; selp.b32 %0,1,0,p; }" \
        : "=r"(_d) : "r"(_m), "r"(_p) : "memory"); \
    if (!_d) { \
        asm volatile("{ .reg .pred P1; WL_%=: mbarrier.try_wait.parity.acquire.cta.shared::cta.b64 P1, [%0], %1, 0x989680;" \
            " @P1 bra.uni WD_%=; bra.uni WL_%=; WD_%=: }" :: "r"(_m), "r"(_p) : "memory"); \
    } } while (0)
#define LDSM4(r0, r1, r2, r3, a) \
    asm volatile("ldmatrix.sync.aligned.m8n8.x4.shared.b16 {%0,%1,%2,%3}, [%4];" \
        : "=r"(r0), "=r"(r1), "=r"(r2), "=r"(r3) : "r"(a))

__device__ __forceinline__ float sigmoidf_(float x) { return 1.0f / (1.0f + __expf(-x)); }
__device__ __forceinline__ float warp_sum(float v) {
    v += __shfl_xor_sync(0xffffffffu, v, 16);
    v += __shfl_xor_sync(0xffffffffu, v, 8);
    v += __shfl_xor_sync(0xffffffffu, v, 4);
    v += __shfl_xor_sync(0xffffffffu, v, 2);
    v += __shfl_xor_sync(0xffffffffu, v, 1);
    return v;
}

__device__ __forceinline__ void mma_f16(float* d, const uint32_t* a, const uint32_t* b) {
    asm volatile(
        "mma.sync.aligned.m16n8k16.row.col.f32.f16.f16.f32 "
        "{%0,%1,%2,%3}, {%4,%5,%6,%7}, {%8,%9}, {%0,%1,%2,%3};\n"
        : "+f"(d[0]), "+f"(d[1]), "+f"(d[2]), "+f"(d[3])
        : "r"(a[0]), "r"(a[1]), "r"(a[2]), "r"(a[3]), "r"(b[0]), "r"(b[1]));
}

// ---------------- grid barrier ----------------
__device__ __forceinline__ void gsync() {
    __syncthreads();
    if (threadIdx.x == 0) {
        unsigned e;
        asm volatile("ld.acquire.gpu.u32 %0, [%1];" : "=r"(e) : "l"(&g_bar_epoch) : "memory");
        unsigned old;
        asm volatile("atom.add.acq_rel.gpu.u32 %0, [%1], %2;"
                     : "=r"(old) : "l"(&g_bar_count), "r"(1u) : "memory");
        if (old == NB - 1) {
            g_bar_count = 0;
            unsigned dummy;
            asm volatile("atom.add.release.gpu.u32 %0, [%1], %2;"
                         : "=r"(dummy) : "l"(&g_bar_epoch), "r"(1u) : "memory");
        } else {
            unsigned cur;
            do {
                __nanosleep(32);
                asm volatile("ld.acquire.gpu.u32 %0, [%1];" : "=r"(cur) : "l"(&g_bar_epoch) : "memory");
            } while (cur == e);
        }
    }
    __syncthreads();
}

// ---------------- stage loader: kt is COMPILE-TIME after NKT unroll ----------------
// AM 0: A0 plain [row][256]. AM 1: enc gates [eh|ctx] K=512. AM 2: dec gates [code|dh|ctx] K=768.
template<int AM>
__device__ __forceinline__ void load_stage(uint32_t sb,
    const __half* __restrict__ A0, const __half* __restrict__ A1, const __half* __restrict__ A2,
    const __half* __restrict__ Bt, int bm, int bn, int KB, int kt, int slot)
{
    const int tid = threadIdx.x;
    uint32_t Ab = sb + (uint32_t)slot * STAGE_B;
    uint32_t Bb = Ab + TILE_HB;
    const int gk0 = kt * 64;
#pragma unroll
    for (int i = 0; i < 2; i++) {
        int idx = tid + i * NT;
        int m = idx >> 3, g8 = idx & 7;
        int gk = gk0 + g8 * 8;
        const __half* ap;
        if (AM == 0)      ap = A0 + (size_t)(bm + m) * 256 + gk;
        else if (AM == 1) ap = (gk < 256) ? (A1 + (size_t)(bm + m) * 256 + gk)
                                          : (A2 + (size_t)(bm + m) * 256 + gk - 256);
        else              ap = (gk < 256) ? (A0 + (size_t)(bm + m) * 256 + gk)
                        : ((gk < 512) ? (A1 + (size_t)(bm + m) * 256 + gk - 256)
                                      : (A2 + (size_t)(bm + m) * 256 + gk - 512));
        CPA(Ab + (uint32_t)(m * 144 + g8 * 16), ap);
        CPA(Bb + (uint32_t)(m * 144 + g8 * 16), Bt + (size_t)(bn + m) * KB + gk);
    }
}

// ---------------- fp16 tensor-core GEMM phase: single tile per block, NKT unrolled ----------------
template<int AM, int EPI, bool XUPD, bool CIH, int NKT>
__device__ void gemm_tc(char* smp, uint32_t sb, int& gbase,
    const __half* __restrict__ A0, const __half* __restrict__ A1, const __half* __restrict__ A2,
    const __half* __restrict__ B0,
    const float* __restrict__ bias, __half* __restrict__ C,
    const void* __restrict__ c_in, float* __restrict__ c_out,
    int Mtiles, int NOUT, int KB, int t,
    const float* __restrict__ input, int boff, int tot)
{
    const int tid = threadIdx.x, lane = tid & 31, warp = tid >> 5;
    const int wm = warp >> 2, wn = warp & 3;          // 4 x 4
    const int q = lane & 3, rsel = lane >> 2;
    float* bias_s = (float*)(smp + BIAS_OFF);
    float* wx_s   = (float*)(smp + WX_OFF);
    const uint32_t sbm = sb + MBAR_OFF;
    const uint32_t offL = (uint32_t)((lane & 15) * 144 + (lane >> 4) * 16);
    const uint32_t aBase = (uint32_t)((wm * 32) * 144) + offL;
    const uint32_t bBase = (uint32_t)((wn * 32) * 144) + offL;

    const int tile = (blockIdx.x + boff) % NB;
    if (tile >= tot) return;
    const int bm = (tile % Mtiles) * 128;
    const int bn = (tile / Mtiles) * 128;

    if (EPI >= 1 || XUPD) {
        __syncthreads();   // prior phase epilogue done before bias/wx overwrite (post-gsync safe)
        if (EPI >= 1) for (int i = tid; i < 128; i += NT) bias_s[i] = bias[bn + i];
        if (XUPD)     for (int i = tid; i < 384; i += NT) wx_s[i] = g_Wx[(i >> 7) * 1024 + bn + (i & 127)];
    }

    float acc[2][4][4];
#pragma unroll
    for (int a = 0; a < 2; a++)
#pragma unroll
        for (int b = 0; b < 4; b++)
#pragma unroll
            for (int l = 0; l < 4; l++) acc[a][b][l] = 0.0f;

    // prologue: fill 2 stages
#pragma unroll
    for (int s = 0; s < 2; s++) {
        int g = gbase + s;
        if (g >= NSTAGE) MBAR_WAITP(sbm + 64 + (g & 3) * 16, ((g >> 2) - 1) & 1);
        load_stage<AM>(sb, A0, A1, A2, B0, bm, bn, KB, s, g & 3);
        CP_ARRIVE(sbm + (g & 3) * 16);
    }

#pragma unroll
    for (int kt = 0; kt < NKT; kt++) {
        if (kt + 2 < NKT) {
            int g = gbase + kt + 2;
            if (g >= NSTAGE) MBAR_WAITP(sbm + 64 + (g & 3) * 16, ((g >> 2) - 1) & 1);
            load_stage<AM>(sb, A0, A1, A2, B0, bm, bn, KB, kt + 2, g & 3);
            CP_ARRIVE(sbm + (g & 3) * 16);
        }
        const int gc = gbase + kt;
        MBAR_WAITP(sbm + (gc & 3) * 16, (gc >> 2) & 1);

        uint32_t Ab = sb + (uint32_t)(gc & 3) * STAGE_B;
        uint32_t Bb = Ab + TILE_HB;
#pragma unroll
        for (int st = 0; st < 4; st++) {        // four k16 steps per BK=64
            uint32_t a[2][4], b[2][4];
#pragma unroll
            for (int tm = 0; tm < 2; tm++)
                LDSM4(a[tm][0], a[tm][1], a[tm][2], a[tm][3],
                      Ab + aBase + (uint32_t)(tm * 16 * 144 + st * 32));
#pragma unroll
            for (int tp = 0; tp < 2; tp++)
                LDSM4(b[tp][0], b[tp][1], b[tp][2], b[tp][3],
                      Bb + bBase + (uint32_t)(tp * 16 * 144 + st * 32));
#pragma unroll
            for (int tm = 0; tm < 2; tm++)
#pragma unroll
                for (int tn = 0; tn < 4; tn++) {
                    uint32_t bb[2] = { b[tn >> 1][tn & 1], b[tn >> 1][(tn & 1) + 2] };
                    mma_f16(acc[tm][tn], a[tm], bb);
                }
        }
        if (lane == 0) MBAR_ARRIVE(sbm + 64 + (gc & 3) * 16);
    }
    gbase += NKT;

    // ---------------- epilogue ----------------
#pragma unroll
    for (int tm = 0; tm < 2; tm++)
#pragma unroll
        for (int tn = 0; tn < 4; tn++) {
            const int r0  = bm + wm * 32 + tm * 16 + rsel;
            const int cl  = wn * 32 + tn * 8 + 2 * q;     // local col (even)
            const int col = bn + cl;
            if (EPI == 0) {
                __half2 h01, h23;
                h01.x = __float2half(acc[tm][tn][0]); h01.y = __float2half(acc[tm][tn][1]);
                h23.x = __float2half(acc[tm][tn][2]); h23.y = __float2half(acc[tm][tn][3]);
                *(__half2*)(C + (size_t)r0 * NOUT + col)       = h01;
                *(__half2*)(C + (size_t)(r0 + 8) * NOUT + col) = h23;
            } else if (EPI == 1) {
                float b0 = bias_s[cl], b1 = bias_s[cl + 1];
                __half2 h01, h23;
                h01.x = __float2half(sigmoidf_(acc[tm][tn][0] + b0));
                h01.y = __float2half(sigmoidf_(acc[tm][tn][1] + b1));
                h23.x = __float2half(sigmoidf_(acc[tm][tn][2] + b0));
                h23.y = __float2half(sigmoidf_(acc[tm][tn][3] + b1));
                *(__half2*)(C + (size_t)r0 * NOUT + col)       = h01;
                *(__half2*)(C + (size_t)(r0 + 8) * NOUT + col) = h23;
            } else {
                float b0 = bias_s[cl], b1 = bias_s[cl + 1];
#pragma unroll
                for (int half = 0; half < 2; half++) {
                    const int r = r0 + half * 8;
                    float v0 = acc[tm][tn][half * 2 + 0] + b0;
                    float v1 = acc[tm][tn][half * 2 + 1] + b1;
                    if (XUPD) {
                        int bb = r >> 7, s = r & (S_ - 1);
                        const float* xp = input + (((size_t)bb * T_ + t) * S_ + s) * F_;
                        float x0 = xp[0], x1 = xp[1], x2 = xp[2];
                        v0 += x0 * wx_s[cl]     + x1 * wx_s[128 + cl]     + x2 * wx_s[256 + cl];
                        v1 += x0 * wx_s[cl + 1] + x1 * wx_s[128 + cl + 1] + x2 * wx_s[256 + cl + 1];
                    }
                    float p0 = __shfl_xor_sync(0xffffffffu, v0, 1);
                    float p1 = __shfl_xor_sync(0xffffffffu, v1, 1);
                    if (!(q & 1)) {
                        int h = (bn + cl) >> 2;
                        float cprev = CIH ? __half2float(((const __half*)c_in)[(size_t)r * H_ + h])
                                          : ((const float*)c_in)[(size_t)r * H_ + h];
                        float cn = sigmoidf_(v1) * cprev + sigmoidf_(v0) * tanhf(p0);
                        float hn = sigmoidf_(p1) * tanhf(cn);
                        C[(size_t)r * H_ + h] = __float2half(hn);
                        if (c_out) c_out[(size_t)r * H_ + h] = cn;
                    }
                }
            }
        }
}

// ---------------- attention: one warp per row, all 8 heads; block subrange ----------------
__device__ __forceinline__ void attn_range(int rowbase, int b0, int nbk) {
    const int w0 = (blockIdx.x - b0) * WPB + (threadIdx.x >> 5);
    const int lane = threadIdx.x & 31;
    const float scale = 0.17677669529663687f;   // 1/sqrt(32)
    __half* ctxb = (rowbase == 0) ? g_ctx_e : g_ctx_d;
    for (int ri = w0; ri < R_; ri += nbk * WPB) {
        int r = rowbase + ri;
        int s = ri & (S_ - 1);
        uint4 qraw = *(const uint4*)(g_qkv + (size_t)r * 768 + 8 * lane);
        const __half2* q2 = (const __half2*)&qraw;
        const int offs[4] = {2, 1, -1, -2};
        float d[4];
        bool ok[4];
#pragma unroll
        for (int n = 0; n < 4; n++) {
            int sn = s + offs[n];
            ok[n] = (sn >= 0 && sn < S_);
            float acc = 0.0f;
            if (ok[n]) {
                uint4 kraw = *(const uint4*)(g_qkv + (size_t)(r + offs[n]) * 768 + 256 + 8 * lane);
                const __half2* k2 = (const __half2*)&kraw;
#pragma unroll
                for (int j = 0; j < 4; j++) {
                    float2 qf = __half22float2(q2[j]);
                    float2 kf = __half22float2(k2[j]);
                    acc = fmaf(qf.x, kf.x, acc);
                    acc = fmaf(qf.y, kf.y, acc);
                }
            }
            d[n] = acc;
        }
#pragma unroll
        for (int n = 0; n < 4; n++) {
            d[n] += __shfl_xor_sync(0xffffffffu, d[n], 1);
            d[n] += __shfl_xor_sync(0xffffffffu, d[n], 2);
            d[n] *= scale;
        }
        float mx = fmaxf(fmaxf(d[0], d[1]), fmaxf(d[2], d[3]));
        float e[4], sum = 0.0f;
#pragma unroll
        for (int n = 0; n < 4; n++) { e[n] = __expf(d[n] - mx); sum += e[n]; }
        float inv = 1.0f / sum;
        float cx[8] = {0, 0, 0, 0, 0, 0, 0, 0};
#pragma unroll
        for (int n = 0; n < 4; n++) {
            if (ok[n]) {
                float a = e[n] * inv;
                uint4 vraw = *(const uint4*)(g_qkv + (size_t)(r + offs[n]) * 768 + 512 + 8 * lane);
                const __half2* v2 = (const __half2*)&vraw;
#pragma unroll
                for (int j = 0; j < 4; j++) {
                    float2 vf = __half22float2(v2[j]);
                    cx[2 * j]     = fmaf(a, vf.x, cx[2 * j]);
                    cx[2 * j + 1] = fmaf(a, vf.y, cx[2 * j + 1]);
                }
            }
        }
        uint4 oraw;
        __half2* o2 = (__half2*)&oraw;
#pragma unroll
        for (int j = 0; j < 4; j++) {
            o2[j].x = __float2half(cx[2 * j]);
            o2[j].y = __float2half(cx[2 * j + 1]);
        }
        *(uint4*)(ctxb + (size_t)ri * H_ + 8 * lane) = oraw;
    }
}

// ---------------- output GEMV + assembly; block subrange ----------------
__device__ __forceinline__ void out_range(const __half* __restrict__ dh,
                                          const float* __restrict__ W,
                                          const float* __restrict__ bb,
                                          const float* __restrict__ input,
                                          float* __restrict__ dout, int t,
                                          int b0, int nbk) {
    const int w0 = (blockIdx.x - b0) * WPB + (threadIdx.x >> 5);
    const int lane = threadIdx.x & 31;
    for (int r = w0; r < R_; r += nbk * WPB) {
        int b = r >> 7, s = r & (S_ - 1);
        float s0 = 0.0f, s1 = 0.0f;
#pragma unroll
        for (int j = 0; j < H_; j += 32) {
            float wv = W[j + lane];
            s0 = fmaf(__half2float(dh[(size_t)r * H_ + j + lane]), wv, s0);
            if (s > 0) s1 = fmaf(__half2float(dh[(size_t)(r - 1) * H_ + j + lane]), wv, s1);
        }
        s0 = warp_sum(s0);
        s1 = warp_sum(s1);
        if (lane == 0) {
            float o  = s0 + bb[0];
            float In = (s > 0) ? (s1 + bb[0])
                               : input[(((size_t)b * T_ + (t + 1)) * S_ + 0) * F_ + 1];
            float num = input[(((size_t)b * T_ + t) * S_ + s) * F_ + 2] + In - o;
            size_t base = (((size_t)b * (T_ - TP_ - 1) + (t - TP_)) * S_ + s) * 3;
            dout[base + 0] = o;
            dout[base + 1] = In;
            dout[base + 2] = num;
        }
    }
}

// ---------------- persistent kernel ----------------
// Per step t (4 barriers, every phase <= one wave):
//  G1: enc gates+LSTM (128 tiles); out(t-1) on blk 128-147
//  G2: dec QKV (96 tiles, blk 0-95) + emb->code (32 tiles, blk 96-127)
//  G3: enc QKV(t+1) (96 tiles, blk 0-95); dec attn(t) on blk 96-147
//  G4: dec gates+LSTM (128 tiles); enc attn(t+1) on blk 128-147
__global__ __launch_bounds__(NT, 1)
void persist_kernel(const float* __restrict__ input, const float* __restrict__ embb,
                    const float* __restrict__ outW, const float* __restrict__ outb,
                    float* __restrict__ dout)
{
    extern __shared__ char smp[];
    uint32_t sb = s2u(smp);
    if (threadIdx.x == 0) {
#pragma unroll
        for (int s = 0; s < NSTAGE; s++) {
            MBAR_INIT(sb + MBAR_OFF + s * 16, NT);         // full: all threads cp-arrive
            MBAR_INIT(sb + MBAR_OFF + 64 + s * 16, WPB);   // empty: one arrive per warp
        }
    }
    __syncthreads();
    int gbase = 0;

    int ce = 0, cd = 0;
    // pre-loop: enc QKV(0) then enc attention(0)
    gemm_tc<0, 0, false, false, 4>(smp, sb, gbase, g_eh[0], nullptr, nullptr,
                                   g_We_t, nullptr, g_qkv, nullptr, nullptr,
                                   16, 768, 256, 0, nullptr, 0, 96);
    gsync();
    attn_range(0, 0, NB);
    gsync();

    for (int t = 0; t < T_ - 1; t++) {
        // G1: enc gates + LSTM (K=512 + rank-3 x) -> eh[ce^1], ec; out(t-1) on blk 128-147
        gemm_tc<1, 2, true, false, 8>(smp, sb, gbase, nullptr, g_eh[ce], g_ctx_e,
                                      g_Wge_t, g_bge, g_eh[ce ^ 1], g_ec, g_ec,
                                      16, 256, 512, t, input, 0, 128);
        if (blockIdx.x >= 128 && t - 1 >= TP_)
            out_range(g_dh[cd], outW, outb, input, dout, t - 1, 128, 20);
        gsync();
        // G2: dec QKV (blk 0-95) + emb->code (blk 96-127)
        gemm_tc<0, 0, false, false, 4>(smp, sb, gbase, g_dh[cd], nullptr, nullptr,
                                       g_Wd_t, nullptr, g_qkv + (size_t)R_ * 768, nullptr, nullptr,
                                       16, 768, 256, 0, nullptr, 0, 96);
        gemm_tc<0, 1, false, false, 4>(smp, sb, gbase, g_eh[ce ^ 1], nullptr, nullptr,
                                       g_embT, embb, g_code, nullptr, nullptr,
                                       16, 256, 256, 0, nullptr, 52, 32);
        gsync();
        // G3: enc QKV(t+1) (blk 0-95); dec attn on blk 96-147
        gemm_tc<0, 0, false, false, 4>(smp, sb, gbase, g_eh[ce ^ 1], nullptr, nullptr,
                                       g_We_t, nullptr, g_qkv, nullptr, nullptr,
                                       16, 768, 256, 0, nullptr, 0, 96);
        if (blockIdx.x >= 96) attn_range(R_, 96, 52);
        gsync();
        // G4: dec gates + LSTM (K=768) -> dh[cd^1]; enc attn(t+1) on blk 128-147
        gemm_tc<2, 2, false, true, 12>(smp, sb, gbase, g_code, g_dh[cd], g_ctx_d,
                                       g_Wgd_t, g_bgd, g_dh[cd ^ 1], g_dh[cd], nullptr,
                                       16, 256, 768, 0, nullptr, 0, 128);
        if (blockIdx.x >= 128) attn_range(0, 128, 20);
        gsync();
        ce ^= 1; cd ^= 1;
    }
    out_range(g_dh[cd], outW, outb, input, dout, T_ - 2, 0, NB);
}

// ---------------- single prep kernel ----------------
__global__ void prep_all_kernel(const float* __restrict__ eWq, const float* __restrict__ eWk,
                                const float* __restrict__ eWv, const float* __restrict__ eWg,
                                const float* __restrict__ ebg, const float* __restrict__ dWq,
                                const float* __restrict__ dWk, const float* __restrict__ dWv,
                                const float* __restrict__ dWg, const float* __restrict__ dbg,
                                const float* __restrict__ embW) {
    int idx = blockIdx.x * blockDim.x + threadIdx.x;
    if (idx < R_ * H_) {
        g_eh[0][idx] = __float2half(0.0f);
        g_dh[0][idx] = __float2half(0.0f);
        g_ec[idx] = 0.0f;
    }
    if (idx < 768 * 256) {
        int n = idx >> 8, k = idx & 255;
        const float* se = (n < 256) ? eWq : ((n < 512) ? eWk : eWv);
        const float* sd = (n < 256) ? dWq : ((n < 512) ? dWk : dWv);
        g_We_t[idx] = __float2half(se[(size_t)k * 256 + (n & 255)]);
        g_Wd_t[idx] = __float2half(sd[(size_t)k * 256 + (n & 255)]);
    }
    if (idx < 1024 * 512) {
        int n = idx >> 9, k2 = idx & 511;
        int gcol = (n & 3) * 256 + (n >> 2);
        g_Wge_t[idx] = __float2half(eWg[(size_t)(3 + k2) * 1024 + gcol]);
        if (k2 < 3) g_Wx[k2 * 1024 + n] = eWg[(size_t)k2 * 1024 + gcol];
        if (k2 == 0) g_bge[n] = ebg[gcol];
    }
    if (idx < 1024 * 768) {
        int n = idx / 768, k2 = idx - n * 768;
        int gcol = (n & 3) * 256 + (n >> 2);
        g_Wgd_t[idx] = __float2half(dWg[(size_t)k2 * 1024 + gcol]);
        if (k2 == 0) g_bgd[n] = dbg[gcol];
    }
    if (idx < 256 * 256) {
        int n = idx >> 8, k = idx & 255;
        g_embT[idx] = __float2half(embW[(size_t)k * 256 + n]);
    }
}

// ---------------- host ----------------
extern "C" void kernel_launch(void* const* d_in, const int* in_sizes, int n_in,
                              void* d_out, int out_size) {
    const float* input = (const float*)d_in[0];
    const float* eWq = (const float*)d_in[1];
    const float* eWk = (const float*)d_in[2];
    const float* eWv = (const float*)d_in[3];
    const float* eWg = (const float*)d_in[4];
    const float* ebg = (const float*)d_in[5];
    const float* dWq = (const float*)d_in[6];
    const float* dWk = (const float*)d_in[7];
    const float* dWv = (const float*)d_in[8];
    const float* dWg = (const float*)d_in[9];
    const float* dbg = (const float*)d_in[10];
    const float* embW = (const float*)d_in[11];
    const float* embb = (const float*)d_in[12];
    const float* outW = (const float*)d_in[13];
    const float* outb = (const float*)d_in[14];
    float* dout = (float*)d_out;

    static int s_init = 0;
    if (!s_init) {
        cudaFuncSetAttribute(persist_kernel, cudaFuncAttributeMaxDynamicSharedMemorySize, SMEM_SZ);
        s_init = 1;
    }

    prep_all_kernel<<<(1024 * 768 + 255) / 256, 256>>>(eWq, eWk, eWv, eWg, ebg,
                                                       dWq, dWk, dWv, dWg, dbg, embW);
    persist_kernel<<<NB, NT, SMEM_SZ>>>(input, embb, outW, outb, dout);
}